// round 1
// baseline (speedup 1.0000x reference)
#include <cuda_runtime.h>
#include <cstdint>
#include <cstddef>

#define Sq 1024
#define Dm 768
#define Hh 12
#define HDm 64
#define Bb 8
#define Tt 384
#define SCALE_F 0.125f

// ---------------- scratch (device globals; no allocation allowed) ----------
__device__ float g_T[3][Bb][Dm];                 // time q/k/v vectors per batch
__device__ float g_QS[(size_t)Bb * Sq * Dm];     // qs (no time) for QEr
__device__ float g_Qf[(size_t)Bb * Sq * Dm];     // qs + tq
__device__ float g_Kf[(size_t)Bb * Sq * Dm];     // ks + tk
__device__ float g_Vf[(size_t)Bb * Sq * Dm];     // vs + tv
__device__ float g_QEr[(size_t)Bb * Hh * Sq * Sq]; // 402 MB skew scratch

// ---------------- kernel 1: time projections ------------------------------
__global__ void __launch_bounds__(256) time_proj(
    const float* __restrict__ time_emb,
    const float* __restrict__ Wqt, const float* __restrict__ bqt,
    const float* __restrict__ Wkt, const float* __restrict__ bkt,
    const float* __restrict__ Wvt, const float* __restrict__ bvt)
{
    const int b = blockIdx.x;
    __shared__ float te[Tt];
    for (int i = threadIdx.x; i < Tt; i += blockDim.x)
        te[i] = time_emb[b * Tt + i];
    __syncthreads();
    for (int n = threadIdx.x; n < Dm; n += blockDim.x) {
        float aq = 0.f, ak = 0.f, av = 0.f;
        for (int t = 0; t < Tt; t++) {
            float x = te[t];
            aq += x * Wqt[t * Dm + n];
            ak += x * Wkt[t * Dm + n];
            av += x * Wvt[t * Dm + n];
        }
        g_T[0][b][n] = aq + bqt[n];
        g_T[1][b][n] = ak + bkt[n];
        g_T[2][b][n] = av + bvt[n];
    }
}

// ---------------- kernel 2: QKV projections (fused time add) ---------------
__global__ void __launch_bounds__(256) qkv_gemm(
    const float* __restrict__ X,
    const float* __restrict__ Wq, const float* __restrict__ bq,
    const float* __restrict__ Wk, const float* __restrict__ bk,
    const float* __restrict__ Wv, const float* __restrict__ bv)
{
    const int z = blockIdx.z;
    const float* __restrict__ W    = (z == 0) ? Wq : (z == 1 ? Wk : Wv);
    const float* __restrict__ bias = (z == 0) ? bq : (z == 1 ? bk : bv);
    const int n0 = blockIdx.x * 64;
    const int m0 = blockIdx.y * 64;
    __shared__ float As[64][16];
    __shared__ float Bs[16][64];
    const int tid = threadIdx.x;
    const int tx = tid & 15, ty = tid >> 4;
    float acc[4][4] = {};
    for (int kk = 0; kk < Dm; kk += 16) {
        {
            int r = tid >> 2, c = (tid & 3) << 2;
            *(float4*)&As[r][c] = *(const float4*)&X[(size_t)(m0 + r) * Dm + kk + c];
        }
        {
            int r = tid >> 4, c = (tid & 15) << 2;
            *(float4*)&Bs[r][c] = *(const float4*)&W[(size_t)(kk + r) * Dm + n0 + c];
        }
        __syncthreads();
        #pragma unroll
        for (int k = 0; k < 16; k++) {
            float a[4];
            #pragma unroll
            for (int i = 0; i < 4; i++) a[i] = As[ty * 4 + i][k];
            float4 b4 = *(const float4*)&Bs[k][tx * 4];
            float bb[4] = {b4.x, b4.y, b4.z, b4.w};
            #pragma unroll
            for (int i = 0; i < 4; i++)
                #pragma unroll
                for (int j = 0; j < 4; j++)
                    acc[i][j] += a[i] * bb[j];
        }
        __syncthreads();
    }
    const int b = m0 >> 10;  // 64 | 1024 so whole tile is one batch
    const int col = n0 + tx * 4;
    const float4 bias4 = *(const float4*)&bias[col];
    #pragma unroll
    for (int i = 0; i < 4; i++) {
        const int row = m0 + ty * 4 + i;
        const size_t idx = (size_t)row * Dm + col;
        float v0 = acc[i][0] + bias4.x;
        float v1 = acc[i][1] + bias4.y;
        float v2 = acc[i][2] + bias4.z;
        float v3 = acc[i][3] + bias4.w;
        if (z == 0) {
            *(float4*)&g_QS[idx] = make_float4(v0, v1, v2, v3);
            const float4 t4 = *(const float4*)&g_T[0][b][col];
            *(float4*)&g_Qf[idx] = make_float4(v0 + t4.x, v1 + t4.y, v2 + t4.z, v3 + t4.w);
        } else if (z == 1) {
            const float4 t4 = *(const float4*)&g_T[1][b][col];
            *(float4*)&g_Kf[idx] = make_float4(v0 + t4.x, v1 + t4.y, v2 + t4.z, v3 + t4.w);
        } else {
            const float4 t4 = *(const float4*)&g_T[2][b][col];
            *(float4*)&g_Vf[idx] = make_float4(v0 + t4.x, v1 + t4.y, v2 + t4.z, v3 + t4.w);
        }
    }
}

// ---------------- kernel 3: QEr = qs @ Er^T per (b,h) ----------------------
__global__ void __launch_bounds__(256) qer_gemm(const float* __restrict__ Er)
{
    const int bh = blockIdx.z;
    const int b = bh / Hh, h = bh % Hh;
    const int s0 = blockIdx.y * 64, t0 = blockIdx.x * 64;
    __shared__ float As[64][64];
    __shared__ float Es[64][65];
    const int tid = threadIdx.x;
    const int tx = tid & 15, ty = tid >> 4;

    for (int i = tid; i < 64 * 16; i += 256) {
        int r = i >> 4, c = (i & 15) << 2;
        *(float4*)&As[r][c] =
            *(const float4*)&g_QS[(size_t)(b * Sq + s0 + r) * Dm + h * HDm + c];
    }
    for (int i = tid; i < 64 * 16; i += 256) {
        int r = i >> 4, c = (i & 15) << 2;
        float4 v = *(const float4*)&Er[(size_t)(t0 + r) * HDm + c];
        Es[r][c] = v.x; Es[r][c + 1] = v.y; Es[r][c + 2] = v.z; Es[r][c + 3] = v.w;
    }
    __syncthreads();

    float acc[4][4] = {};
    #pragma unroll 16
    for (int d = 0; d < 64; d++) {
        float a[4], e[4];
        #pragma unroll
        for (int i = 0; i < 4; i++) a[i] = As[ty * 4 + i][d];
        #pragma unroll
        for (int j = 0; j < 4; j++) e[j] = Es[tx * 4 + j][d];
        #pragma unroll
        for (int i = 0; i < 4; i++)
            #pragma unroll
            for (int j = 0; j < 4; j++)
                acc[i][j] += a[i] * e[j];
    }
    #pragma unroll
    for (int i = 0; i < 4; i++) {
        size_t base = (size_t)bh * Sq * Sq + (size_t)(s0 + ty * 4 + i) * Sq + t0 + tx * 4;
        *(float4*)&g_QEr[base] = make_float4(acc[i][0], acc[i][1], acc[i][2], acc[i][3]);
    }
}

// ---------------- kernel 4: flash attention with skewed rel bias -----------
// Srel[q,k] = QEr[q, S-1-(q-k)]  if k <= q
//           = 0                  if k == q+1
//           = QEr[q+1, k-q-2]    if k >= q+2
__global__ void __launch_bounds__(256) attn_kernel(float* __restrict__ out)
{
    extern __shared__ float sm[];
    float* Qs = sm;                    // 64*64
    float* Ks = sm + 64 * 64;          // 64*65 (padded)
    float* Vs = Ks + 64 * 65;          // 64*65
    float* Ps = Vs + 64 * 65;          // 64*65

    const int q0 = blockIdx.x * 64;
    const int h = blockIdx.y;
    const int b = blockIdx.z;
    const int tid = threadIdx.x;
    const int warp = tid >> 5, lane = tid & 31;
    const size_t rowbase = (size_t)b * Sq;
    const float* __restrict__ QErbh = g_QEr + (size_t)(b * Hh + h) * Sq * Sq;

    for (int i = tid; i < 64 * 16; i += 256) {
        int r = i >> 4, c = (i & 15) << 2;
        *(float4*)&Qs[r * 64 + c] =
            *(const float4*)&g_Qf[(rowbase + q0 + r) * Dm + h * HDm + c];
    }

    float m_[8], s_[8], o_[8][2];
    #pragma unroll
    for (int i = 0; i < 8; i++) { m_[i] = -1e30f; s_[i] = 0.f; o_[i][0] = 0.f; o_[i][1] = 0.f; }

    for (int kt = 0; kt < Sq / 64; kt++) {
        const int k0 = kt * 64;
        __syncthreads();
        for (int i = tid; i < 64 * 16; i += 256) {
            int r = i >> 4, c = (i & 15) << 2;
            size_t gidx = (rowbase + k0 + r) * Dm + h * HDm + c;
            float4 kv = *(const float4*)&g_Kf[gidx];
            float4 vv = *(const float4*)&g_Vf[gidx];
            float* kp = &Ks[r * 65 + c];
            kp[0] = kv.x; kp[1] = kv.y; kp[2] = kv.z; kp[3] = kv.w;
            float* vp = &Vs[r * 65 + c];
            vp[0] = vv.x; vp[1] = vv.y; vp[2] = vv.z; vp[3] = vv.w;
        }
        __syncthreads();

        #pragma unroll
        for (int g = 0; g < 2; g++) {
            const int qb = warp * 8 + g * 4;
            float sc[4][2] = {};
            #pragma unroll 16
            for (int d = 0; d < 64; d++) {
                float k0v = Ks[lane * 65 + d];
                float k1v = Ks[(lane + 32) * 65 + d];
                #pragma unroll
                for (int i = 0; i < 4; i++) {
                    float a = Qs[(qb + i) * 64 + d];
                    sc[i][0] += a * k0v;
                    sc[i][1] += a * k1v;
                }
            }
            const int kg0 = k0 + lane, kg1 = kg0 + 32;
            #pragma unroll
            for (int i = 0; i < 4; i++) {
                const int qg = q0 + qb + i;
                float r0 = (kg0 <= qg)
                    ? QErbh[(size_t)qg * Sq + (Sq - 1) - qg + kg0]
                    : ((kg0 == qg + 1) ? 0.f
                                       : QErbh[(size_t)(qg + 1) * Sq + kg0 - qg - 2]);
                float r1 = (kg1 <= qg)
                    ? QErbh[(size_t)qg * Sq + (Sq - 1) - qg + kg1]
                    : ((kg1 == qg + 1) ? 0.f
                                       : QErbh[(size_t)(qg + 1) * Sq + kg1 - qg - 2]);
                float s0v = (sc[i][0] + r0) * SCALE_F;
                float s1v = (sc[i][1] + r1) * SCALE_F;

                float mt = fmaxf(s0v, s1v);
                #pragma unroll
                for (int off = 16; off > 0; off >>= 1)
                    mt = fmaxf(mt, __shfl_xor_sync(0xffffffffu, mt, off));
                const int ri = g * 4 + i;
                float mn = fmaxf(m_[ri], mt);
                float p0 = __expf(s0v - mn);
                float p1 = __expf(s1v - mn);
                float pt = p0 + p1;
                #pragma unroll
                for (int off = 16; off > 0; off >>= 1)
                    pt += __shfl_xor_sync(0xffffffffu, pt, off);
                float corr = __expf(m_[ri] - mn);
                m_[ri] = mn;
                s_[ri] = s_[ri] * corr + pt;
                o_[ri][0] *= corr; o_[ri][1] *= corr;
                Ps[(qb + i) * 65 + lane] = p0;
                Ps[(qb + i) * 65 + lane + 32] = p1;
            }
            __syncwarp();
            #pragma unroll 16
            for (int kk = 0; kk < 64; kk++) {
                float v0 = Vs[kk * 65 + lane];
                float v1 = Vs[kk * 65 + lane + 32];
                #pragma unroll
                for (int i = 0; i < 4; i++) {
                    float p = Ps[(qb + i) * 65 + kk];
                    o_[g * 4 + i][0] += p * v0;
                    o_[g * 4 + i][1] += p * v1;
                }
            }
            __syncwarp();
        }
    }

    #pragma unroll
    for (int ri = 0; ri < 8; ri++) {
        const int qg = q0 + warp * 8 + ri;
        const float inv = 1.0f / s_[ri];
        const size_t ob = (rowbase + qg) * Dm + h * HDm;
        out[ob + lane] = o_[ri][0] * inv;
        out[ob + lane + 32] = o_[ri][1] * inv;
    }
}

// ---------------- launch ----------------------------------------------------
extern "C" void kernel_launch(void* const* d_in, const int* in_sizes, int n_in,
                              void* d_out, int out_size)
{
    (void)in_sizes; (void)n_in; (void)out_size;
    const float* patches  = (const float*)d_in[0];
    const float* time_emb = (const float*)d_in[1];
    const float* Wqs = (const float*)d_in[2];
    const float* bqs = (const float*)d_in[3];
    const float* Wks = (const float*)d_in[4];
    const float* bks = (const float*)d_in[5];
    const float* Wvs = (const float*)d_in[6];
    const float* bvs = (const float*)d_in[7];
    const float* Wqt = (const float*)d_in[8];
    const float* bqt = (const float*)d_in[9];
    const float* Wkt = (const float*)d_in[10];
    const float* bkt = (const float*)d_in[11];
    const float* Wvt = (const float*)d_in[12];
    const float* bvt = (const float*)d_in[13];
    const float* Er  = (const float*)d_in[14];
    float* out = (float*)d_out;

    time_proj<<<Bb, 256>>>(time_emb, Wqt, bqt, Wkt, bkt, Wvt, bvt);

    dim3 gq(Dm / 64, (Bb * Sq) / 64, 3);
    qkv_gemm<<<gq, 256>>>(patches, Wqs, bqs, Wks, bks, Wvs, bvs);

    dim3 ge(Sq / 64, Sq / 64, Bb * Hh);
    qer_gemm<<<ge, 256>>>(Er);

    const int attn_smem = (64 * 64 + 3 * 64 * 65) * (int)sizeof(float);  // 66304 B
    cudaFuncSetAttribute(attn_kernel, cudaFuncAttributeMaxDynamicSharedMemorySize, attn_smem);
    dim3 ga(Sq / 64, Hh, Bb);
    attn_kernel<<<ga, 256, attn_smem>>>(out);
}

// round 3
// speedup vs baseline: 1.2924x; 1.2924x over previous
#include <cuda_runtime.h>
#include <cuda_bf16.h>
#include <cstdint>
#include <cstddef>

#define Sq 1024
#define Dm 768
#define Hh 12
#define HDm 64
#define Bb 8
#define Tt 384
#define SCALE_F 0.125f

// ---------------- scratch (device globals; no allocation allowed) ----------
__device__ float g_T[3][Bb][Dm];                     // time q/k/v vectors per batch
__device__ float g_Qf[(size_t)Bb * Sq * Dm];         // qs + tq  (fp32, attention)
__device__ float g_Kf[(size_t)Bb * Sq * Dm];         // ks + tk
__device__ float g_Vf[(size_t)Bb * Sq * Dm];         // vs + tv
__device__ float g_QEr[(size_t)Bb * Hh * Sq * Sq];   // 402 MB skew scratch
__device__ __nv_bfloat16 g_Phi[(size_t)Bb * Sq * Dm];  // patches hi/lo
__device__ __nv_bfloat16 g_Plo[(size_t)Bb * Sq * Dm];
__device__ __nv_bfloat16 g_WThi[3][Dm][Dm];          // W^T hi/lo  [z][n][k]
__device__ __nv_bfloat16 g_WTlo[3][Dm][Dm];
__device__ __nv_bfloat16 g_QShi[(size_t)Bb * Sq * Dm]; // qs (no time) hi/lo
__device__ __nv_bfloat16 g_QSlo[(size_t)Bb * Sq * Dm];
__device__ __nv_bfloat16 g_Erhi[Sq][HDm];
__device__ __nv_bfloat16 g_Erlo[Sq][HDm];

// ---------------- PTX helpers (baseline ISA only: sm_80+) -------------------
__device__ __forceinline__ uint32_t smem_u32(const void* p) {
    uint32_t a;
    asm("{ .reg .u64 t; cvta.to.shared.u64 t, %1; cvt.u32.u64 %0, t; }"
        : "=r"(a) : "l"(p));
    return a;
}
__device__ __forceinline__ void ldmx4(uint32_t* r, uint32_t addr) {
    asm volatile("ldmatrix.sync.aligned.m8n8.x4.shared.b16 {%0,%1,%2,%3}, [%4];"
                 : "=r"(r[0]), "=r"(r[1]), "=r"(r[2]), "=r"(r[3]) : "r"(addr));
}
__device__ __forceinline__ void mma16816(float* c, const uint32_t* a, const uint32_t* b) {
    asm volatile(
        "mma.sync.aligned.m16n8k16.row.col.f32.bf16.bf16.f32 "
        "{%0,%1,%2,%3}, {%4,%5,%6,%7}, {%8,%9}, {%0,%1,%2,%3};"
        : "+f"(c[0]), "+f"(c[1]), "+f"(c[2]), "+f"(c[3])
        : "r"(a[0]), "r"(a[1]), "r"(a[2]), "r"(a[3]), "r"(b[0]), "r"(b[1]));
}
#define CP16(dst, src) asm volatile("cp.async.cg.shared.global [%0], [%1], 16;" :: "r"(dst), "l"(src))
#define CP_COMMIT()    asm volatile("cp.async.commit_group;" ::: "memory")
#define CP_WAIT1()     asm volatile("cp.async.wait_group 1;" ::: "memory")
#define CP_WAIT0()     asm volatile("cp.async.wait_group 0;" ::: "memory")

// smem tile geometry: rows of 64 bf16 (Kc) padded to stride 72 elements (144 B,
// 16B-aligned; row addresses mod 128B are all distinct within an 8-row phase)
#define KC 64
#define RSTR 72
#define TILE_B (128 * RSTR * 2)          // 18432 B per operand tile
#define STAGE_B (4 * TILE_B)             // Ah, Al, Bh, Bl = 73728 B

// ---------------- kernel 1: time projections ------------------------------
__global__ void __launch_bounds__(256) time_proj(
    const float* __restrict__ time_emb,
    const float* __restrict__ Wqt, const float* __restrict__ bqt,
    const float* __restrict__ Wkt, const float* __restrict__ bkt,
    const float* __restrict__ Wvt, const float* __restrict__ bvt)
{
    const int b = blockIdx.x;
    __shared__ float te[Tt];
    for (int i = threadIdx.x; i < Tt; i += blockDim.x)
        te[i] = time_emb[b * Tt + i];
    __syncthreads();
    for (int n = threadIdx.x; n < Dm; n += blockDim.x) {
        float aq = 0.f, ak = 0.f, av = 0.f;
        for (int t = 0; t < Tt; t++) {
            float x = te[t];
            aq += x * Wqt[t * Dm + n];
            ak += x * Wkt[t * Dm + n];
            av += x * Wvt[t * Dm + n];
        }
        g_T[0][b][n] = aq + bqt[n];
        g_T[1][b][n] = ak + bkt[n];
        g_T[2][b][n] = av + bvt[n];
    }
}

// ---------------- prep: fp32 -> bf16 hi/lo splits --------------------------
__device__ __forceinline__ void split4(float4 v,
    __nv_bfloat162& h0, __nv_bfloat162& h1, __nv_bfloat162& l0, __nv_bfloat162& l1)
{
    __nv_bfloat16 a = __float2bfloat16(v.x), b = __float2bfloat16(v.y);
    __nv_bfloat16 c = __float2bfloat16(v.z), d = __float2bfloat16(v.w);
    h0.x = a; h0.y = b; h1.x = c; h1.y = d;
    l0.x = __float2bfloat16(v.x - __bfloat162float(a));
    l0.y = __float2bfloat16(v.y - __bfloat162float(b));
    l1.x = __float2bfloat16(v.z - __bfloat162float(c));
    l1.y = __float2bfloat16(v.w - __bfloat162float(d));
}

__global__ void __launch_bounds__(256) prep_patches(const float* __restrict__ src)
{
    size_t i = (size_t)blockIdx.x * 256 + threadIdx.x;
    float4 v = ((const float4*)src)[i];
    __nv_bfloat162 h0, h1, l0, l1;
    split4(v, h0, h1, l0, l1);
    __nv_bfloat162* H = (__nv_bfloat162*)g_Phi;
    __nv_bfloat162* L = (__nv_bfloat162*)g_Plo;
    H[2 * i] = h0; H[2 * i + 1] = h1;
    L[2 * i] = l0; L[2 * i + 1] = l1;
}

__global__ void __launch_bounds__(256) prep_er(const float* __restrict__ src)
{
    size_t i = (size_t)blockIdx.x * 256 + threadIdx.x;
    float4 v = ((const float4*)src)[i];
    __nv_bfloat162 h0, h1, l0, l1;
    split4(v, h0, h1, l0, l1);
    __nv_bfloat162* H = (__nv_bfloat162*)&g_Erhi[0][0];
    __nv_bfloat162* L = (__nv_bfloat162*)&g_Erlo[0][0];
    H[2 * i] = h0; H[2 * i + 1] = h1;
    L[2 * i] = l0; L[2 * i + 1] = l1;
}

__global__ void __launch_bounds__(256) prep_wt(
    const float* __restrict__ Wq, const float* __restrict__ Wk,
    const float* __restrict__ Wv)
{
    const int z = blockIdx.z;
    const float* __restrict__ W = (z == 0) ? Wq : (z == 1 ? Wk : Wv);
    __shared__ float s[32][33];
    const int n0 = blockIdx.x * 32, k0 = blockIdx.y * 32;
    const int tx = threadIdx.x & 31, ty = threadIdx.x >> 5;  // 32 x 8
    #pragma unroll
    for (int i = 0; i < 4; i++)
        s[ty + 8 * i][tx] = W[(size_t)(k0 + ty + 8 * i) * Dm + n0 + tx];
    __syncthreads();
    #pragma unroll
    for (int i = 0; i < 4; i++) {
        int n = n0 + ty + 8 * i, k = k0 + tx;
        float v = s[tx][ty + 8 * i];
        __nv_bfloat16 h = __float2bfloat16(v);
        g_WThi[z][n][k] = h;
        g_WTlo[z][n][k] = __float2bfloat16(v - __bfloat162float(h));
    }
}

// ---------------- shared microkernel: one Kc=64 chunk of bf16x3 MMA --------
// warp layout: wm = warp&1 (2 x 64 rows), wn = warp>>1 (4 x 32 cols)
// acc: c[4][4][4]  (4 m-tiles of 16, 4 n-tiles of 8)
__device__ __forceinline__ void mma_chunk(uint32_t stage_base, int wm, int wn,
                                          int lane, float c[4][4][4])
{
    const uint32_t aRow = (uint32_t)(wm * 64 + (lane & 15));
    const uint32_t aColBase = (uint32_t)((lane >> 4) * 8);
    const uint32_t bRow = (uint32_t)(wn * 32 + ((lane >> 3) & 1) * 8 + (lane & 7));
    const uint32_t sAh = stage_base;
    const uint32_t sAl = stage_base + TILE_B;
    const uint32_t sBh = stage_base + 2 * TILE_B;
    const uint32_t sBl = stage_base + 3 * TILE_B;

    #pragma unroll
    for (int ks = 0; ks < 4; ks++) {
        const uint32_t kcol = (uint32_t)(ks * 16) + aColBase;
        uint32_t ah[4][4], al[4][4], bh[4][2], bl[4][2];
        #pragma unroll
        for (int mt = 0; mt < 4; mt++) {
            uint32_t off = ((aRow + mt * 16) * RSTR + kcol) * 2;
            ldmx4(ah[mt], sAh + off);
            ldmx4(al[mt], sAl + off);
        }
        #pragma unroll
        for (int nt2 = 0; nt2 < 2; nt2++) {
            uint32_t off = ((bRow + nt2 * 16) * RSTR + kcol) * 2;
            uint32_t t[4];
            ldmx4(t, sBh + off);
            bh[nt2 * 2][0] = t[0]; bh[nt2 * 2][1] = t[2];
            bh[nt2 * 2 + 1][0] = t[1]; bh[nt2 * 2 + 1][1] = t[3];
            ldmx4(t, sBl + off);
            bl[nt2 * 2][0] = t[0]; bl[nt2 * 2][1] = t[2];
            bl[nt2 * 2 + 1][0] = t[1]; bl[nt2 * 2 + 1][1] = t[3];
        }
        #pragma unroll
        for (int mt = 0; mt < 4; mt++)
            #pragma unroll
            for (int nt = 0; nt < 4; nt++) {
                mma16816(c[mt][nt], ah[mt], bh[nt]);
                mma16816(c[mt][nt], ah[mt], bl[nt]);
                mma16816(c[mt][nt], al[mt], bh[nt]);
            }
    }
}

// ---------------- kernel 2: QKV via mma.sync bf16x3 ------------------------
// grid (6, 64, 3), 256 threads, 2*STAGE_B dynamic smem
__global__ void __launch_bounds__(256) qkv_mma(
    const float* __restrict__ bq, const float* __restrict__ bk,
    const float* __restrict__ bv)
{
    extern __shared__ char sm[];
    const uint32_t smb = smem_u32(sm);
    const int z = blockIdx.z;
    const int n0 = blockIdx.x * 128, m0 = blockIdx.y * 128;
    const int tid = threadIdx.x;
    const int warp = tid >> 5, lane = tid & 31;
    const int wm = warp & 1, wn = warp >> 1;

    const __nv_bfloat16* pAhi = g_Phi;
    const __nv_bfloat16* pAlo = g_Plo;
    const __nv_bfloat16* pBhi = &g_WThi[z][0][0];
    const __nv_bfloat16* pBlo = &g_WTlo[z][0][0];

    auto load_stage = [&](int chunk, int s) {
        const uint32_t st = smb + (uint32_t)s * STAGE_B;
        const int k0 = chunk * KC;
        #pragma unroll
        for (int it = 0; it < 4; it++) {
            int i = tid + it * 256;          // 0..1023
            int r = i >> 3, cc = i & 7;
            uint32_t doff = (uint32_t)(r * RSTR + cc * 8) * 2;
            size_t aoff = (size_t)(m0 + r) * Dm + k0 + cc * 8;
            size_t boff = (size_t)(n0 + r) * Dm + k0 + cc * 8;
            CP16(st + doff, pAhi + aoff);
            CP16(st + TILE_B + doff, pAlo + aoff);
            CP16(st + 2 * TILE_B + doff, pBhi + boff);
            CP16(st + 3 * TILE_B + doff, pBlo + boff);
        }
        CP_COMMIT();
    };

    float c[4][4][4] = {};

    load_stage(0, 0);
    load_stage(1, 1);
    for (int ch = 0; ch < 12; ch++) {
        if (ch < 10) CP_WAIT1(); else if (ch == 10) CP_WAIT0();
        __syncthreads();
        mma_chunk(smb + (uint32_t)(ch & 1) * STAGE_B, wm, wn, lane, c);
        __syncthreads();
        if (ch + 2 < 12) load_stage(ch + 2, ch & 1);
    }

    // epilogue: bias + time add, write fp32 Q/K/V (+ bf16 hi/lo QS for z==0)
    const float* bias = (z == 0) ? bq : (z == 1 ? bk : bv);
    const int lrow = lane >> 2, lcol = (lane & 3) * 2;
    #pragma unroll
    for (int mt = 0; mt < 4; mt++) {
        #pragma unroll
        for (int nt = 0; nt < 4; nt++) {
            const int col = n0 + wn * 32 + nt * 8 + lcol;
            const float bx = bias[col], by = bias[col + 1];
            #pragma unroll
            for (int hf = 0; hf < 2; hf++) {
                const int row = m0 + wm * 64 + mt * 16 + lrow + hf * 8;
                const int b = row >> 10;
                const float v0 = c[mt][nt][hf * 2 + 0] + bx;
                const float v1 = c[mt][nt][hf * 2 + 1] + by;
                const float t0 = g_T[z][b][col];
                const float t1 = g_T[z][b][col + 1];
                const size_t o = (size_t)row * Dm + col;
                float2 f = make_float2(v0 + t0, v1 + t1);
                if (z == 0) {
                    *(float2*)&g_Qf[o] = f;
                    __nv_bfloat16 h0 = __float2bfloat16(v0);
                    __nv_bfloat16 h1 = __float2bfloat16(v1);
                    __nv_bfloat162 hh; hh.x = h0; hh.y = h1;
                    __nv_bfloat162 ll;
                    ll.x = __float2bfloat16(v0 - __bfloat162float(h0));
                    ll.y = __float2bfloat16(v1 - __bfloat162float(h1));
                    *(__nv_bfloat162*)&g_QShi[o] = hh;
                    *(__nv_bfloat162*)&g_QSlo[o] = ll;
                } else if (z == 1) {
                    *(float2*)&g_Kf[o] = f;
                } else {
                    *(float2*)&g_Vf[o] = f;
                }
            }
        }
    }
}

// ---------------- kernel 3: QEr via mma.sync bf16x3 ------------------------
// grid (8 [t], 8 [s], 96 [bh]), 256 threads, STAGE_B smem, K=64 single chunk
__global__ void __launch_bounds__(256) qer_mma()
{
    extern __shared__ char sm[];
    const uint32_t smb = smem_u32(sm);
    const int bh = blockIdx.z, b = bh / Hh, h = bh % Hh;
    const int s0 = blockIdx.y * 128, t0 = blockIdx.x * 128;
    const int tid = threadIdx.x;
    const int warp = tid >> 5, lane = tid & 31;
    const int wm = warp & 1, wn = warp >> 1;

    {
        const __nv_bfloat16* pAhi = g_QShi;
        const __nv_bfloat16* pAlo = g_QSlo;
        #pragma unroll
        for (int it = 0; it < 4; it++) {
            int i = tid + it * 256;
            int r = i >> 3, cc = i & 7;
            uint32_t doff = (uint32_t)(r * RSTR + cc * 8) * 2;
            size_t aoff = (size_t)(b * Sq + s0 + r) * Dm + h * HDm + cc * 8;
            CP16(smb + doff, pAhi + aoff);
            CP16(smb + TILE_B + doff, pAlo + aoff);
            CP16(smb + 2 * TILE_B + doff, &g_Erhi[t0 + r][cc * 8]);
            CP16(smb + 3 * TILE_B + doff, &g_Erlo[t0 + r][cc * 8]);
        }
        CP_COMMIT();
    }

    float c[4][4][4] = {};
    CP_WAIT0();
    __syncthreads();
    mma_chunk(smb, wm, wn, lane, c);

    const int lrow = lane >> 2, lcol = (lane & 3) * 2;
    const size_t base = (size_t)bh * Sq * Sq;
    #pragma unroll
    for (int mt = 0; mt < 4; mt++) {
        #pragma unroll
        for (int nt = 0; nt < 4; nt++) {
            const int col = t0 + wn * 32 + nt * 8 + lcol;
            #pragma unroll
            for (int hf = 0; hf < 2; hf++) {
                const int row = s0 + wm * 64 + mt * 16 + lrow + hf * 8;
                *(float2*)&g_QEr[base + (size_t)row * Sq + col] =
                    make_float2(c[mt][nt][hf * 2 + 0], c[mt][nt][hf * 2 + 1]);
            }
        }
    }
}

// ---------------- kernel 4: flash attention with skewed rel bias -----------
__global__ void __launch_bounds__(256) attn_kernel(float* __restrict__ out)
{
    extern __shared__ float smx[];
    float* Qs = smx;                   // 64*64
    float* Ks = smx + 64 * 64;         // 64*65 (padded)
    float* Vs = Ks + 64 * 65;          // 64*65
    float* Ps = Vs + 64 * 65;          // 64*65

    const int q0 = blockIdx.x * 64;
    const int h = blockIdx.y;
    const int b = blockIdx.z;
    const int tid = threadIdx.x;
    const int warp = tid >> 5, lane = tid & 31;
    const size_t rowbase = (size_t)b * Sq;
    const float* __restrict__ QErbh = g_QEr + (size_t)(b * Hh + h) * Sq * Sq;

    for (int i = tid; i < 64 * 16; i += 256) {
        int r = i >> 4, c = (i & 15) << 2;
        *(float4*)&Qs[r * 64 + c] =
            *(const float4*)&g_Qf[(rowbase + q0 + r) * Dm + h * HDm + c];
    }

    float m_[8], s_[8], o_[8][2];
    #pragma unroll
    for (int i = 0; i < 8; i++) { m_[i] = -1e30f; s_[i] = 0.f; o_[i][0] = 0.f; o_[i][1] = 0.f; }

    for (int kt = 0; kt < Sq / 64; kt++) {
        const int k0 = kt * 64;
        __syncthreads();
        for (int i = tid; i < 64 * 16; i += 256) {
            int r = i >> 4, c = (i & 15) << 2;
            size_t gidx = (rowbase + k0 + r) * Dm + h * HDm + c;
            float4 kv = *(const float4*)&g_Kf[gidx];
            float4 vv = *(const float4*)&g_Vf[gidx];
            float* kp = &Ks[r * 65 + c];
            kp[0] = kv.x; kp[1] = kv.y; kp[2] = kv.z; kp[3] = kv.w;
            float* vp = &Vs[r * 65 + c];
            vp[0] = vv.x; vp[1] = vv.y; vp[2] = vv.z; vp[3] = vv.w;
        }
        __syncthreads();

        #pragma unroll
        for (int g = 0; g < 2; g++) {
            const int qb = warp * 8 + g * 4;
            float sc[4][2] = {};
            #pragma unroll 16
            for (int d = 0; d < 64; d++) {
                float k0v = Ks[lane * 65 + d];
                float k1v = Ks[(lane + 32) * 65 + d];
                #pragma unroll
                for (int i = 0; i < 4; i++) {
                    float a = Qs[(qb + i) * 64 + d];
                    sc[i][0] += a * k0v;
                    sc[i][1] += a * k1v;
                }
            }
            const int kg0 = k0 + lane, kg1 = kg0 + 32;
            #pragma unroll
            for (int i = 0; i < 4; i++) {
                const int qg = q0 + qb + i;
                float r0 = (kg0 <= qg)
                    ? QErbh[(size_t)qg * Sq + (Sq - 1) - qg + kg0]
                    : ((kg0 == qg + 1) ? 0.f
                                       : QErbh[(size_t)(qg + 1) * Sq + kg0 - qg - 2]);
                float r1 = (kg1 <= qg)
                    ? QErbh[(size_t)qg * Sq + (Sq - 1) - qg + kg1]
                    : ((kg1 == qg + 1) ? 0.f
                                       : QErbh[(size_t)(qg + 1) * Sq + kg1 - qg - 2]);
                float s0v = (sc[i][0] + r0) * SCALE_F;
                float s1v = (sc[i][1] + r1) * SCALE_F;

                float mt = fmaxf(s0v, s1v);
                #pragma unroll
                for (int off = 16; off > 0; off >>= 1)
                    mt = fmaxf(mt, __shfl_xor_sync(0xffffffffu, mt, off));
                const int ri = g * 4 + i;
                float mn = fmaxf(m_[ri], mt);
                float p0 = __expf(s0v - mn);
                float p1 = __expf(s1v - mn);
                float pt = p0 + p1;
                #pragma unroll
                for (int off = 16; off > 0; off >>= 1)
                    pt += __shfl_xor_sync(0xffffffffu, pt, off);
                float corr = __expf(m_[ri] - mn);
                m_[ri] = mn;
                s_[ri] = s_[ri] * corr + pt;
                o_[ri][0] *= corr; o_[ri][1] *= corr;
                Ps[(qb + i) * 65 + lane] = p0;
                Ps[(qb + i) * 65 + lane + 32] = p1;
            }
            __syncwarp();
            #pragma unroll 16
            for (int kk = 0; kk < 64; kk++) {
                float v0 = Vs[kk * 65 + lane];
                float v1 = Vs[kk * 65 + lane + 32];
                #pragma unroll
                for (int i = 0; i < 4; i++) {
                    float p = Ps[(qb + i) * 65 + kk];
                    o_[g * 4 + i][0] += p * v0;
                    o_[g * 4 + i][1] += p * v1;
                }
            }
            __syncwarp();
        }
    }

    #pragma unroll
    for (int ri = 0; ri < 8; ri++) {
        const int qg = q0 + warp * 8 + ri;
        const float inv = 1.0f / s_[ri];
        const size_t ob = (rowbase + qg) * Dm + h * HDm;
        out[ob + lane] = o_[ri][0] * inv;
        out[ob + lane + 32] = o_[ri][1] * inv;
    }
}

// ---------------- launch ----------------------------------------------------
extern "C" void kernel_launch(void* const* d_in, const int* in_sizes, int n_in,
                              void* d_out, int out_size)
{
    (void)in_sizes; (void)n_in; (void)out_size;
    const float* patches  = (const float*)d_in[0];
    const float* time_emb = (const float*)d_in[1];
    const float* Wqs = (const float*)d_in[2];
    const float* bqs = (const float*)d_in[3];
    const float* Wks = (const float*)d_in[4];
    const float* bks = (const float*)d_in[5];
    const float* Wvs = (const float*)d_in[6];
    const float* bvs = (const float*)d_in[7];
    const float* Wqt = (const float*)d_in[8];
    const float* bqt = (const float*)d_in[9];
    const float* Wkt = (const float*)d_in[10];
    const float* bkt = (const float*)d_in[11];
    const float* Wvt = (const float*)d_in[12];
    const float* bvt = (const float*)d_in[13];
    const float* Er  = (const float*)d_in[14];
    float* out = (float*)d_out;

    time_proj<<<Bb, 256>>>(time_emb, Wqt, bqt, Wkt, bkt, Wvt, bvt);
    prep_patches<<<(Bb * Sq * Dm / 4) / 256, 256>>>(patches);
    prep_er<<<(Sq * HDm / 4) / 256, 256>>>(Er);
    prep_wt<<<dim3(Dm / 32, Dm / 32, 3), 256>>>(Wqs, Wks, Wvs);

    const int qkv_smem = 2 * STAGE_B;  // 147456
    cudaFuncSetAttribute(qkv_mma, cudaFuncAttributeMaxDynamicSharedMemorySize, qkv_smem);
    qkv_mma<<<dim3(Dm / 128, (Bb * Sq) / 128, 3), 256, qkv_smem>>>(bqs, bks, bvs);

    const int qer_smem = STAGE_B;      // 73728
    cudaFuncSetAttribute(qer_mma, cudaFuncAttributeMaxDynamicSharedMemorySize, qer_smem);
    qer_mma<<<dim3(Sq / 128, Sq / 128, Bb * Hh), 256, qer_smem>>>();

    const int attn_smem = (64 * 64 + 3 * 64 * 65) * (int)sizeof(float);  // 66304
    cudaFuncSetAttribute(attn_kernel, cudaFuncAttributeMaxDynamicSharedMemorySize, attn_smem);
    attn_kernel<<<dim3(Sq / 64, Hh, Bb), 256, attn_smem>>>(out);
}

// round 4
// speedup vs baseline: 1.7873x; 1.3830x over previous
#include <cuda_runtime.h>
#include <cuda_bf16.h>
#include <cstdint>
#include <cstddef>

#define Sq 1024
#define Dm 768
#define Hh 12
#define HDm 64
#define Bb 8
#define Tt 384
#define SCALE_F 0.125f

// ---------------- scratch (device globals; no allocation allowed) ----------
__device__ float g_T[3][Bb][Dm];                       // time q/k/v vectors
__device__ __nv_bfloat16 g_Phi[(size_t)Bb * Sq * Dm];  // patches hi/lo
__device__ __nv_bfloat16 g_Plo[(size_t)Bb * Sq * Dm];
__device__ __nv_bfloat16 g_WThi[3][Dm][Dm];            // W^T hi/lo [z][n][k]
__device__ __nv_bfloat16 g_WTlo[3][Dm][Dm];
__device__ __nv_bfloat16 g_QShi[(size_t)Bb * Sq * Dm]; // qs (no time) hi/lo
__device__ __nv_bfloat16 g_QSlo[(size_t)Bb * Sq * Dm];
__device__ __nv_bfloat16 g_Qhi[(size_t)Bb * Sq * Dm];  // qs+tq hi/lo
__device__ __nv_bfloat16 g_Qlo[(size_t)Bb * Sq * Dm];
__device__ __nv_bfloat16 g_Khi[(size_t)Bb * Sq * Dm];  // ks+tk hi/lo
__device__ __nv_bfloat16 g_Klo[(size_t)Bb * Sq * Dm];
__device__ __nv_bfloat16 g_Vhi[(size_t)Bb * Sq * Dm];  // vs+tv hi/lo
__device__ __nv_bfloat16 g_Vlo[(size_t)Bb * Sq * Dm];
__device__ __nv_bfloat16 g_Erhi[Sq][HDm];
__device__ __nv_bfloat16 g_Erlo[Sq][HDm];

// ---------------- PTX helpers (baseline ISA: sm_80+) ------------------------
__device__ __forceinline__ uint32_t smem_u32(const void* p) {
    uint32_t a;
    asm("{ .reg .u64 t; cvta.to.shared.u64 t, %1; cvt.u32.u64 %0, t; }"
        : "=r"(a) : "l"(p));
    return a;
}
__device__ __forceinline__ void ldmx4(uint32_t* r, uint32_t addr) {
    asm volatile("ldmatrix.sync.aligned.m8n8.x4.shared.b16 {%0,%1,%2,%3}, [%4];"
                 : "=r"(r[0]), "=r"(r[1]), "=r"(r[2]), "=r"(r[3]) : "r"(addr));
}
__device__ __forceinline__ void ldmx4t(uint32_t* r, uint32_t addr) {
    asm volatile("ldmatrix.sync.aligned.m8n8.x4.trans.shared.b16 {%0,%1,%2,%3}, [%4];"
                 : "=r"(r[0]), "=r"(r[1]), "=r"(r[2]), "=r"(r[3]) : "r"(addr));
}
__device__ __forceinline__ void mma16816(float* c, const uint32_t* a, const uint32_t* b) {
    asm volatile(
        "mma.sync.aligned.m16n8k16.row.col.f32.bf16.bf16.f32 "
        "{%0,%1,%2,%3}, {%4,%5,%6,%7}, {%8,%9}, {%0,%1,%2,%3};"
        : "+f"(c[0]), "+f"(c[1]), "+f"(c[2]), "+f"(c[3])
        : "r"(a[0]), "r"(a[1]), "r"(a[2]), "r"(a[3]), "r"(b[0]), "r"(b[1]));
}
#define CP16(dst, src) asm volatile("cp.async.cg.shared.global [%0], [%1], 16;" :: "r"(dst), "l"(src))
#define CP_COMMIT()    asm volatile("cp.async.commit_group;" ::: "memory")
#define CP_WAIT1()     asm volatile("cp.async.wait_group 1;" ::: "memory")
#define CP_WAIT0()     asm volatile("cp.async.wait_group 0;" ::: "memory")

#define KC 64
#define RSTR 72
#define TILE_B (128 * RSTR * 2)          // 18432 B per 128-row operand tile
#define STAGE_B (4 * TILE_B)             // 73728 B
#define DSTR 132

__device__ __forceinline__ void split2(float x, float y, uint32_t& hi, uint32_t& lo) {
    __nv_bfloat162 h, l;
    h.x = __float2bfloat16(x); h.y = __float2bfloat16(y);
    l.x = __float2bfloat16(x - __bfloat162float(h.x));
    l.y = __float2bfloat16(y - __bfloat162float(h.y));
    hi = *(uint32_t*)&h; lo = *(uint32_t*)&l;
}

// ---------------- kernel 1: time projections ------------------------------
__global__ void __launch_bounds__(256) time_proj(
    const float* __restrict__ time_emb,
    const float* __restrict__ Wqt, const float* __restrict__ bqt,
    const float* __restrict__ Wkt, const float* __restrict__ bkt,
    const float* __restrict__ Wvt, const float* __restrict__ bvt)
{
    const int b = blockIdx.x;
    __shared__ float te[Tt];
    for (int i = threadIdx.x; i < Tt; i += blockDim.x)
        te[i] = time_emb[b * Tt + i];
    __syncthreads();
    for (int n = threadIdx.x; n < Dm; n += blockDim.x) {
        float aq = 0.f, ak = 0.f, av = 0.f;
        for (int t = 0; t < Tt; t++) {
            float x = te[t];
            aq += x * Wqt[t * Dm + n];
            ak += x * Wkt[t * Dm + n];
            av += x * Wvt[t * Dm + n];
        }
        g_T[0][b][n] = aq + bqt[n];
        g_T[1][b][n] = ak + bkt[n];
        g_T[2][b][n] = av + bvt[n];
    }
}

// ---------------- prep: fp32 -> bf16 hi/lo splits --------------------------
__device__ __forceinline__ void split4(float4 v,
    __nv_bfloat162& h0, __nv_bfloat162& h1, __nv_bfloat162& l0, __nv_bfloat162& l1)
{
    __nv_bfloat16 a = __float2bfloat16(v.x), b = __float2bfloat16(v.y);
    __nv_bfloat16 c = __float2bfloat16(v.z), d = __float2bfloat16(v.w);
    h0.x = a; h0.y = b; h1.x = c; h1.y = d;
    l0.x = __float2bfloat16(v.x - __bfloat162float(a));
    l0.y = __float2bfloat16(v.y - __bfloat162float(b));
    l1.x = __float2bfloat16(v.z - __bfloat162float(c));
    l1.y = __float2bfloat16(v.w - __bfloat162float(d));
}

__global__ void __launch_bounds__(256) prep_patches(const float* __restrict__ src)
{
    size_t i = (size_t)blockIdx.x * 256 + threadIdx.x;
    float4 v = ((const float4*)src)[i];
    __nv_bfloat162 h0, h1, l0, l1;
    split4(v, h0, h1, l0, l1);
    __nv_bfloat162* H = (__nv_bfloat162*)g_Phi;
    __nv_bfloat162* L = (__nv_bfloat162*)g_Plo;
    H[2 * i] = h0; H[2 * i + 1] = h1;
    L[2 * i] = l0; L[2 * i + 1] = l1;
}

__global__ void __launch_bounds__(256) prep_er(const float* __restrict__ src)
{
    size_t i = (size_t)blockIdx.x * 256 + threadIdx.x;
    float4 v = ((const float4*)src)[i];
    __nv_bfloat162 h0, h1, l0, l1;
    split4(v, h0, h1, l0, l1);
    __nv_bfloat162* H = (__nv_bfloat162*)&g_Erhi[0][0];
    __nv_bfloat162* L = (__nv_bfloat162*)&g_Erlo[0][0];
    H[2 * i] = h0; H[2 * i + 1] = h1;
    L[2 * i] = l0; L[2 * i + 1] = l1;
}

__global__ void __launch_bounds__(256) prep_wt(
    const float* __restrict__ Wq, const float* __restrict__ Wk,
    const float* __restrict__ Wv)
{
    const int z = blockIdx.z;
    const float* __restrict__ W = (z == 0) ? Wq : (z == 1 ? Wk : Wv);
    __shared__ float s[32][33];
    const int n0 = blockIdx.x * 32, k0 = blockIdx.y * 32;
    const int tx = threadIdx.x & 31, ty = threadIdx.x >> 5;
    #pragma unroll
    for (int i = 0; i < 4; i++)
        s[ty + 8 * i][tx] = W[(size_t)(k0 + ty + 8 * i) * Dm + n0 + tx];
    __syncthreads();
    #pragma unroll
    for (int i = 0; i < 4; i++) {
        int n = n0 + ty + 8 * i, k = k0 + tx;
        float v = s[tx][ty + 8 * i];
        __nv_bfloat16 h = __float2bfloat16(v);
        g_WThi[z][n][k] = h;
        g_WTlo[z][n][k] = __float2bfloat16(v - __bfloat162float(h));
    }
}

// ---------------- shared microkernel: one Kc=64 chunk of bf16x3 MMA --------
__device__ __forceinline__ void mma_chunk(uint32_t stage_base, int wm, int wn,
                                          int lane, float c[4][4][4])
{
    const uint32_t aRow = (uint32_t)(wm * 64 + (lane & 15));
    const uint32_t aColBase = (uint32_t)((lane >> 4) * 8);
    const uint32_t bRow = (uint32_t)(wn * 32 + ((lane >> 3) & 1) * 8 + (lane & 7));
    const uint32_t sAh = stage_base;
    const uint32_t sAl = stage_base + TILE_B;
    const uint32_t sBh = stage_base + 2 * TILE_B;
    const uint32_t sBl = stage_base + 3 * TILE_B;

    #pragma unroll
    for (int ks = 0; ks < 4; ks++) {
        const uint32_t kcol = (uint32_t)(ks * 16) + aColBase;
        uint32_t ah[4][4], al[4][4], bh[4][2], bl[4][2];
        #pragma unroll
        for (int mt = 0; mt < 4; mt++) {
            uint32_t off = ((aRow + mt * 16) * RSTR + kcol) * 2;
            ldmx4(ah[mt], sAh + off);
            ldmx4(al[mt], sAl + off);
        }
        #pragma unroll
        for (int nt2 = 0; nt2 < 2; nt2++) {
            uint32_t off = ((bRow + nt2 * 16) * RSTR + kcol) * 2;
            uint32_t t[4];
            ldmx4(t, sBh + off);
            bh[nt2 * 2][0] = t[0]; bh[nt2 * 2][1] = t[2];
            bh[nt2 * 2 + 1][0] = t[1]; bh[nt2 * 2 + 1][1] = t[3];
            ldmx4(t, sBl + off);
            bl[nt2 * 2][0] = t[0]; bl[nt2 * 2][1] = t[2];
            bl[nt2 * 2 + 1][0] = t[1]; bl[nt2 * 2 + 1][1] = t[3];
        }
        #pragma unroll
        for (int mt = 0; mt < 4; mt++)
            #pragma unroll
            for (int nt = 0; nt < 4; nt++) {
                mma16816(c[mt][nt], ah[mt], bh[nt]);
                mma16816(c[mt][nt], ah[mt], bl[nt]);
                mma16816(c[mt][nt], al[mt], bh[nt]);
            }
    }
}

// ---------------- kernel 2: QKV via mma.sync bf16x3 ------------------------
__global__ void __launch_bounds__(256) qkv_mma(
    const float* __restrict__ bq, const float* __restrict__ bk,
    const float* __restrict__ bv)
{
    extern __shared__ char sm[];
    const uint32_t smb = smem_u32(sm);
    const int z = blockIdx.z;
    const int n0 = blockIdx.x * 128, m0 = blockIdx.y * 128;
    const int tid = threadIdx.x;
    const int warp = tid >> 5, lane = tid & 31;
    const int wm = warp & 1, wn = warp >> 1;

    const __nv_bfloat16* pAhi = g_Phi;
    const __nv_bfloat16* pAlo = g_Plo;
    const __nv_bfloat16* pBhi = &g_WThi[z][0][0];
    const __nv_bfloat16* pBlo = &g_WTlo[z][0][0];

    auto load_stage = [&](int chunk, int s) {
        const uint32_t st = smb + (uint32_t)s * STAGE_B;
        const int k0 = chunk * KC;
        #pragma unroll
        for (int it = 0; it < 4; it++) {
            int i = tid + it * 256;
            int r = i >> 3, cc = i & 7;
            uint32_t doff = (uint32_t)(r * RSTR + cc * 8) * 2;
            size_t aoff = (size_t)(m0 + r) * Dm + k0 + cc * 8;
            size_t boff = (size_t)(n0 + r) * Dm + k0 + cc * 8;
            CP16(st + doff, pAhi + aoff);
            CP16(st + TILE_B + doff, pAlo + aoff);
            CP16(st + 2 * TILE_B + doff, pBhi + boff);
            CP16(st + 3 * TILE_B + doff, pBlo + boff);
        }
        CP_COMMIT();
    };

    float c[4][4][4] = {};

    load_stage(0, 0);
    load_stage(1, 1);
    for (int ch = 0; ch < 12; ch++) {
        if (ch < 10) CP_WAIT1(); else if (ch == 10) CP_WAIT0();
        __syncthreads();
        mma_chunk(smb + (uint32_t)(ch & 1) * STAGE_B, wm, wn, lane, c);
        __syncthreads();
        if (ch + 2 < 12) load_stage(ch + 2, ch & 1);
    }

    const float* bias = (z == 0) ? bq : (z == 1 ? bk : bv);
    const int lrow = lane >> 2, lcol = (lane & 3) * 2;
    #pragma unroll
    for (int mt = 0; mt < 4; mt++) {
        #pragma unroll
        for (int nt = 0; nt < 4; nt++) {
            const int col = n0 + wn * 32 + nt * 8 + lcol;
            const float bx = bias[col], by = bias[col + 1];
            #pragma unroll
            for (int hf = 0; hf < 2; hf++) {
                const int row = m0 + wm * 64 + mt * 16 + lrow + hf * 8;
                const int b = row >> 10;
                const float v0 = c[mt][nt][hf * 2 + 0] + bx;
                const float v1 = c[mt][nt][hf * 2 + 1] + by;
                const float t0 = g_T[z][b][col];
                const float t1 = g_T[z][b][col + 1];
                const size_t o = (size_t)row * Dm + col;
                uint32_t hi, lo;
                split2(v0 + t0, v1 + t1, hi, lo);
                if (z == 0) {
                    *(uint32_t*)&g_Qhi[o] = hi;
                    *(uint32_t*)&g_Qlo[o] = lo;
                    uint32_t shi, slo;
                    split2(v0, v1, shi, slo);
                    *(uint32_t*)&g_QShi[o] = shi;
                    *(uint32_t*)&g_QSlo[o] = slo;
                } else if (z == 1) {
                    *(uint32_t*)&g_Khi[o] = hi;
                    *(uint32_t*)&g_Klo[o] = lo;
                } else {
                    *(uint32_t*)&g_Vhi[o] = hi;
                    *(uint32_t*)&g_Vlo[o] = lo;
                }
            }
        }
    }
}

// ---------------- kernel 3: fused flash attention + rel-bias ---------------
// grid (16 q-tiles, 12 h, 8 b), 128 threads (4 warps), Bq=64, Bk=64.
// Srel[q,k]: e=k-q; bias = (e==1)?0 : Dwin[q_loc + (e>=2)][e - (d0-64)]
// where Dwin[rq][j] = QS[q0+rq] . Er[t(d0-64+j)],
//       t(e) = (e<=0) ? 1023+e : e-2.
#define oQh  0u
#define oQl  9216u
#define oQSh 18432u
#define oQSl 29952u
#define oKV  41472u           /* + stage*36864 : Kh,Kl,Vh,Vl each 9216 */
#define oErh 115200u
#define oErl 133632u
#define oD   152064u          /* 65 x 132 fp32 = 34320 */
#define ATTN_SMEM 186384

__global__ void __launch_bounds__(128) attn_mma(float* __restrict__ out)
{
    extern __shared__ char sm[];
    const uint32_t smb = smem_u32(sm);
    const int q0 = blockIdx.x * 64;
    const int h = blockIdx.y, b = blockIdx.z;
    const int tid = threadIdx.x, warp = tid >> 5, lane = tid & 31;
    float* Dw = (float*)(sm + oD);

    auto load_kv = [&](int kt, int s) {
        const uint32_t st = smb + oKV + (uint32_t)s * 36864u;
        const size_t krow0 = ((size_t)(b * Sq + kt * 64)) * Dm + h * HDm;
        #pragma unroll
        for (int it = 0; it < 4; it++) {
            int i = tid + it * 128;
            int r = i >> 3, cc = i & 7;
            uint32_t doff = (uint32_t)(r * RSTR + cc * 8) * 2;
            size_t src = krow0 + (size_t)r * Dm + cc * 8;
            CP16(st + doff, g_Khi + src);
            CP16(st + 9216u + doff, g_Klo + src);
            CP16(st + 18432u + doff, g_Vhi + src);
            CP16(st + 27648u + doff, g_Vlo + src);
        }
    };

    // prologue: Q (64 rows), QSext (80 rows clamped), KV(0)
    {
        const size_t qrow0 = ((size_t)(b * Sq + q0)) * Dm + h * HDm;
        #pragma unroll
        for (int it = 0; it < 4; it++) {
            int i = tid + it * 128;
            int r = i >> 3, cc = i & 7;
            uint32_t doff = (uint32_t)(r * RSTR + cc * 8) * 2;
            size_t src = qrow0 + (size_t)r * Dm + cc * 8;
            CP16(smb + oQh + doff, g_Qhi + src);
            CP16(smb + oQl + doff, g_Qlo + src);
        }
        #pragma unroll
        for (int it = 0; it < 5; it++) {
            int i = tid + it * 128;
            int r = i >> 3, cc = i & 7;
            int rr = q0 + r; if (rr > Sq - 1) rr = Sq - 1;
            uint32_t doff = (uint32_t)(r * RSTR + cc * 8) * 2;
            size_t src = ((size_t)(b * Sq + rr)) * Dm + h * HDm + cc * 8;
            CP16(smb + oQSh + doff, g_QShi + src);
            CP16(smb + oQSl + doff, g_QSlo + src);
        }
        load_kv(0, 0);
        CP_COMMIT();
    }

    float m_[2] = {-1e30f, -1e30f}, l_[2] = {0.f, 0.f};
    float co[8][4] = {};

    for (int kt = 0; kt < 16; kt++) {
        const int s = kt & 1;
        const int d0 = kt * 64 - q0;
        __syncthreads();

        // Er window for this iter
        #pragma unroll
        for (int it = 0; it < 8; it++) {
            int i = tid + it * 128;
            int j = i >> 3, cc = i & 7;
            int e = d0 - 64 + j;
            int t = (e <= 0) ? (Sq - 1 + e) : (e - 2);
            if (t < 0) t = 0; if (t > Sq - 1) t = Sq - 1;
            uint32_t doff = (uint32_t)(j * RSTR + cc * 8) * 2;
            CP16(smb + oErh + doff, &g_Erhi[t][cc * 8]);
            CP16(smb + oErl + doff, &g_Erlo[t][cc * 8]);
        }
        CP_COMMIT();
        if (kt + 1 < 16) load_kv(kt + 1, s ^ 1);
        CP_COMMIT();
        CP_WAIT1();                 // Er(kt) + KV(kt) complete; KV(kt+1) flying
        __syncthreads();

        // ---- D MMA: Dwin[0..64][warp cols 32] ----
        {
            uint32_t ebh[4][4][2], ebl[4][4][2];   // [ntl][ks][2]
            #pragma unroll
            for (int pi = 0; pi < 2; pi++) {
                const uint32_t nrow = (uint32_t)((warp * 2 + pi) * 16 +
                                    ((lane >> 3) & 1) * 8 + (lane & 7));
                #pragma unroll
                for (int ks = 0; ks < 4; ks++) {
                    uint32_t kcol = (uint32_t)(ks * 16 + (lane >> 4) * 8);
                    uint32_t addr = smb + oErh + (nrow * RSTR + kcol) * 2;
                    uint32_t t4[4];
                    ldmx4(t4, addr);
                    ebh[pi * 2][ks][0] = t4[0]; ebh[pi * 2][ks][1] = t4[2];
                    ebh[pi * 2 + 1][ks][0] = t4[1]; ebh[pi * 2 + 1][ks][1] = t4[3];
                    ldmx4(t4, addr + (oErl - oErh));
                    ebl[pi * 2][ks][0] = t4[0]; ebl[pi * 2][ks][1] = t4[2];
                    ebl[pi * 2 + 1][ks][0] = t4[1]; ebl[pi * 2 + 1][ks][1] = t4[3];
                }
            }
            #pragma unroll
            for (int mt = 0; mt < 5; mt++) {
                uint32_t sah[4][4], sal[4][4];
                const uint32_t arow = (uint32_t)(mt * 16 + (lane & 15));
                #pragma unroll
                for (int ks = 0; ks < 4; ks++) {
                    uint32_t addr = smb + oQSh +
                        (arow * RSTR + (uint32_t)(ks * 16 + (lane >> 4) * 8)) * 2;
                    ldmx4(sah[ks], addr);
                    ldmx4(sal[ks], addr + (oQSl - oQSh));
                }
                #pragma unroll
                for (int ntl = 0; ntl < 4; ntl++) {
                    float cc4[4] = {};
                    #pragma unroll
                    for (int ks = 0; ks < 4; ks++) {
                        mma16816(cc4, sah[ks], ebh[ntl][ks]);
                        mma16816(cc4, sah[ks], ebl[ntl][ks]);
                        mma16816(cc4, sal[ks], ebh[ntl][ks]);
                    }
                    const int colb = (warp * 4 + ntl) * 8 + (lane & 3) * 2;
                    const int r0 = mt * 16 + (lane >> 2);
                    if (r0 <= 64)
                        *(float2*)&Dw[r0 * DSTR + colb] = make_float2(cc4[0], cc4[1]);
                    if (r0 + 8 <= 64)
                        *(float2*)&Dw[(r0 + 8) * DSTR + colb] = make_float2(cc4[2], cc4[3]);
                }
            }
        }

        // ---- QK^T MMA: warp rows warp*16..+15 x 64 cols ----
        float c[8][4] = {};
        {
            const uint32_t stK = smb + oKV + (uint32_t)s * 36864u;
            uint32_t qah[4][4], qal[4][4];
            const uint32_t arow = (uint32_t)(warp * 16 + (lane & 15));
            #pragma unroll
            for (int ks = 0; ks < 4; ks++) {
                uint32_t addr = smb + oQh +
                    (arow * RSTR + (uint32_t)(ks * 16 + (lane >> 4) * 8)) * 2;
                ldmx4(qah[ks], addr);
                ldmx4(qal[ks], addr + (oQl - oQh));
            }
            #pragma unroll
            for (int ks = 0; ks < 4; ks++) {
                uint32_t bh[8][2], bl[8][2];
                #pragma unroll
                for (int pp = 0; pp < 4; pp++) {
                    uint32_t nrow = (uint32_t)(pp * 16 + ((lane >> 3) & 1) * 8 + (lane & 7));
                    uint32_t addr = stK +
                        (nrow * RSTR + (uint32_t)(ks * 16 + (lane >> 4) * 8)) * 2;
                    uint32_t t4[4];
                    ldmx4(t4, addr);
                    bh[pp * 2][0] = t4[0]; bh[pp * 2][1] = t4[2];
                    bh[pp * 2 + 1][0] = t4[1]; bh[pp * 2 + 1][1] = t4[3];
                    ldmx4(t4, addr + 9216u);
                    bl[pp * 2][0] = t4[0]; bl[pp * 2][1] = t4[2];
                    bl[pp * 2 + 1][0] = t4[1]; bl[pp * 2 + 1][1] = t4[3];
                }
                #pragma unroll
                for (int nt = 0; nt < 8; nt++) {
                    mma16816(c[nt], qah[ks], bh[nt]);
                    mma16816(c[nt], qah[ks], bl[nt]);
                    mma16816(c[nt], qal[ks], bh[nt]);
                }
            }
        }

        __syncthreads();   // Dwin visible to all warps

        // ---- bias gather + online softmax ----
        float mloc[2] = {-1e30f, -1e30f};
        #pragma unroll
        for (int nt = 0; nt < 8; nt++) {
            #pragma unroll
            for (int e2 = 0; e2 < 2; e2++) {
                const int col = nt * 8 + (lane & 3) * 2 + e2;
                #pragma unroll
                for (int hf = 0; hf < 2; hf++) {
                    const int q_loc = warp * 16 + (lane >> 2) + hf * 8;
                    const int e = d0 + col - q_loc;
                    const int j = col - q_loc + 64;
                    float bias = (e == 1) ? 0.f
                               : Dw[(q_loc + (e >= 2 ? 1 : 0)) * DSTR + j];
                    float sv = (c[nt][hf * 2 + e2] + bias) * SCALE_F;
                    c[nt][hf * 2 + e2] = sv;
                    mloc[hf] = fmaxf(mloc[hf], sv);
                }
            }
        }
        #pragma unroll
        for (int hf = 0; hf < 2; hf++) {
            mloc[hf] = fmaxf(mloc[hf], __shfl_xor_sync(0xffffffffu, mloc[hf], 1));
            mloc[hf] = fmaxf(mloc[hf], __shfl_xor_sync(0xffffffffu, mloc[hf], 2));
        }
        float corr[2], psum[2] = {0.f, 0.f};
        #pragma unroll
        for (int hf = 0; hf < 2; hf++) {
            float mn = fmaxf(m_[hf], mloc[hf]);
            corr[hf] = __expf(m_[hf] - mn);
            m_[hf] = mn;
        }
        #pragma unroll
        for (int nt = 0; nt < 8; nt++) {
            #pragma unroll
            for (int k4 = 0; k4 < 4; k4++) {
                const int hf = k4 >> 1;
                float p = __expf(c[nt][k4] - m_[hf]);
                c[nt][k4] = p;
                psum[hf] += p;
            }
        }
        #pragma unroll
        for (int hf = 0; hf < 2; hf++) {
            psum[hf] += __shfl_xor_sync(0xffffffffu, psum[hf], 1);
            psum[hf] += __shfl_xor_sync(0xffffffffu, psum[hf], 2);
            l_[hf] = l_[hf] * corr[hf] + psum[hf];
        }
        #pragma unroll
        for (int nt = 0; nt < 8; nt++) {
            co[nt][0] *= corr[0]; co[nt][1] *= corr[0];
            co[nt][2] *= corr[1]; co[nt][3] *= corr[1];
        }

        // ---- PV MMA ----
        {
            const uint32_t stV = smb + oKV + (uint32_t)s * 36864u + 18432u;
            #pragma unroll
            for (int ktk = 0; ktk < 4; ktk++) {
                uint32_t pha[4], pla[4];
                #pragma unroll
                for (int half2 = 0; half2 < 2; half2++) {
                    #pragma unroll
                    for (int sub = 0; sub < 2; sub++) {
                        float x = c[2 * ktk + sub][half2 * 2];
                        float y = c[2 * ktk + sub][half2 * 2 + 1];
                        uint32_t hi, lo;
                        split2(x, y, hi, lo);
                        pha[half2 + sub * 2] = hi;
                        pla[half2 + sub * 2] = lo;
                    }
                }
                uint32_t vbh[8][2], vbl[8][2];
                #pragma unroll
                for (int pp = 0; pp < 4; pp++) {
                    uint32_t krow = (uint32_t)(ktk * 16 + (lane & 7) + ((lane >> 3) & 1) * 8);
                    uint32_t ncol = (uint32_t)(pp * 16 + (lane >> 4) * 8);
                    uint32_t addr = stV + (krow * RSTR + ncol) * 2;
                    uint32_t t4[4];
                    ldmx4t(t4, addr);
                    vbh[pp * 2][0] = t4[0]; vbh[pp * 2][1] = t4[1];
                    vbh[pp * 2 + 1][0] = t4[2]; vbh[pp * 2 + 1][1] = t4[3];
                    ldmx4t(t4, addr + 9216u);
                    vbl[pp * 2][0] = t4[0]; vbl[pp * 2][1] = t4[1];
                    vbl[pp * 2 + 1][0] = t4[2]; vbl[pp * 2 + 1][1] = t4[3];
                }
                #pragma unroll
                for (int nt = 0; nt < 8; nt++) {
                    mma16816(co[nt], pha, vbh[nt]);
                    mma16816(co[nt], pha, vbl[nt]);
                    mma16816(co[nt], pla, vbh[nt]);
                }
            }
        }
    }

    // epilogue
    #pragma unroll
    for (int hf = 0; hf < 2; hf++) {
        const float inv = 1.0f / l_[hf];
        const int qrow = q0 + warp * 16 + (lane >> 2) + hf * 8;
        const size_t ob = ((size_t)(b * Sq + qrow)) * Dm + h * HDm;
        #pragma unroll
        for (int nt = 0; nt < 8; nt++) {
            const int col = nt * 8 + (lane & 3) * 2;
            *(float2*)&out[ob + col] =
                make_float2(co[nt][hf * 2] * inv, co[nt][hf * 2 + 1] * inv);
        }
    }
}

// ---------------- launch ----------------------------------------------------
extern "C" void kernel_launch(void* const* d_in, const int* in_sizes, int n_in,
                              void* d_out, int out_size)
{
    (void)in_sizes; (void)n_in; (void)out_size;
    const float* patches  = (const float*)d_in[0];
    const float* time_emb = (const float*)d_in[1];
    const float* Wqs = (const float*)d_in[2];
    const float* bqs = (const float*)d_in[3];
    const float* Wks = (const float*)d_in[4];
    const float* bks = (const float*)d_in[5];
    const float* Wvs = (const float*)d_in[6];
    const float* bvs = (const float*)d_in[7];
    const float* Wqt = (const float*)d_in[8];
    const float* bqt = (const float*)d_in[9];
    const float* Wkt = (const float*)d_in[10];
    const float* bkt = (const float*)d_in[11];
    const float* Wvt = (const float*)d_in[12];
    const float* bvt = (const float*)d_in[13];
    const float* Er  = (const float*)d_in[14];
    float* out = (float*)d_out;

    time_proj<<<Bb, 256>>>(time_emb, Wqt, bqt, Wkt, bkt, Wvt, bvt);
    prep_patches<<<(Bb * Sq * Dm / 4) / 256, 256>>>(patches);
    prep_er<<<(Sq * HDm / 4) / 256, 256>>>(Er);
    prep_wt<<<dim3(Dm / 32, Dm / 32, 3), 256>>>(Wqs, Wks, Wvs);

    const int qkv_smem = 2 * STAGE_B;  // 147456
    cudaFuncSetAttribute(qkv_mma, cudaFuncAttributeMaxDynamicSharedMemorySize, qkv_smem);
    qkv_mma<<<dim3(Dm / 128, (Bb * Sq) / 128, 3), 256, qkv_smem>>>(bqs, bks, bvs);

    cudaFuncSetAttribute(attn_mma, cudaFuncAttributeMaxDynamicSharedMemorySize, ATTN_SMEM);
    attn_mma<<<dim3(Sq / 64, Hh, Bb), 128, ATTN_SMEM>>>(out);
}

// round 5
// speedup vs baseline: 2.0975x; 1.1735x over previous
#include <cuda_runtime.h>
#include <cuda_bf16.h>
#include <cstdint>
#include <cstddef>

#define Sq 1024
#define Dm 768
#define Hh 12
#define HDm 64
#define Bb 8
#define Tt 384
#define SCALE_F 0.125f

// ---------------- scratch (device globals; no allocation allowed) ----------
__device__ float g_T[3][Bb][Dm];                       // time q/k/v vectors
__device__ __nv_bfloat16 g_Phi[(size_t)Bb * Sq * Dm];  // patches hi/lo
__device__ __nv_bfloat16 g_Plo[(size_t)Bb * Sq * Dm];
__device__ __nv_bfloat16 g_WThi[3][Dm][Dm];            // W^T hi/lo [z][n][k]
__device__ __nv_bfloat16 g_WTlo[3][Dm][Dm];
__device__ __nv_bfloat16 g_QShi[(size_t)Bb * Sq * Dm]; // qs (no time) hi/lo
__device__ __nv_bfloat16 g_QSlo[(size_t)Bb * Sq * Dm];
__device__ __nv_bfloat16 g_Qhi[(size_t)Bb * Sq * Dm];  // qs+tq hi/lo
__device__ __nv_bfloat16 g_Qlo[(size_t)Bb * Sq * Dm];
__device__ __nv_bfloat16 g_Khi[(size_t)Bb * Sq * Dm];  // ks+tk hi/lo
__device__ __nv_bfloat16 g_Klo[(size_t)Bb * Sq * Dm];
__device__ __nv_bfloat16 g_Vhi[(size_t)Bb * Sq * Dm];  // vs+tv hi/lo
__device__ __nv_bfloat16 g_Vlo[(size_t)Bb * Sq * Dm];
__device__ __nv_bfloat16 g_Erhi[Sq][HDm];
__device__ __nv_bfloat16 g_Erlo[Sq][HDm];

// ---------------- PTX helpers (baseline ISA: sm_80+) ------------------------
__device__ __forceinline__ uint32_t smem_u32(const void* p) {
    uint32_t a;
    asm("{ .reg .u64 t; cvta.to.shared.u64 t, %1; cvt.u32.u64 %0, t; }"
        : "=r"(a) : "l"(p));
    return a;
}
__device__ __forceinline__ void ldmx4(uint32_t* r, uint32_t addr) {
    asm volatile("ldmatrix.sync.aligned.m8n8.x4.shared.b16 {%0,%1,%2,%3}, [%4];"
                 : "=r"(r[0]), "=r"(r[1]), "=r"(r[2]), "=r"(r[3]) : "r"(addr));
}
__device__ __forceinline__ void ldmx4t(uint32_t* r, uint32_t addr) {
    asm volatile("ldmatrix.sync.aligned.m8n8.x4.trans.shared.b16 {%0,%1,%2,%3}, [%4];"
                 : "=r"(r[0]), "=r"(r[1]), "=r"(r[2]), "=r"(r[3]) : "r"(addr));
}
__device__ __forceinline__ void mma16816(float* c, const uint32_t* a, const uint32_t* b) {
    asm volatile(
        "mma.sync.aligned.m16n8k16.row.col.f32.bf16.bf16.f32 "
        "{%0,%1,%2,%3}, {%4,%5,%6,%7}, {%8,%9}, {%0,%1,%2,%3};"
        : "+f"(c[0]), "+f"(c[1]), "+f"(c[2]), "+f"(c[3])
        : "r"(a[0]), "r"(a[1]), "r"(a[2]), "r"(a[3]), "r"(b[0]), "r"(b[1]));
}
#define CP16(dst, src) asm volatile("cp.async.cg.shared.global [%0], [%1], 16;" :: "r"(dst), "l"(src))
#define CP_COMMIT()    asm volatile("cp.async.commit_group;" ::: "memory")
#define CP_WAIT1()     asm volatile("cp.async.wait_group 1;" ::: "memory")
#define CP_WAIT0()     asm volatile("cp.async.wait_group 0;" ::: "memory")

#define KC 64
#define RSTR 72
#define TILE_B (128 * RSTR * 2)          // 18432 B per 128-row operand tile
#define STAGE_B (4 * TILE_B)             // 73728 B
#define DSTR 132

__device__ __forceinline__ void split2(float x, float y, uint32_t& hi, uint32_t& lo) {
    __nv_bfloat162 h, l;
    h.x = __float2bfloat16(x); h.y = __float2bfloat16(y);
    l.x = __float2bfloat16(x - __bfloat162float(h.x));
    l.y = __float2bfloat16(y - __bfloat162float(h.y));
    hi = *(uint32_t*)&h; lo = *(uint32_t*)&l;
}

// ---------------- kernel 1: time projections ------------------------------
__global__ void __launch_bounds__(256) time_proj(
    const float* __restrict__ time_emb,
    const float* __restrict__ Wqt, const float* __restrict__ bqt,
    const float* __restrict__ Wkt, const float* __restrict__ bkt,
    const float* __restrict__ Wvt, const float* __restrict__ bvt)
{
    const int b = blockIdx.x;
    __shared__ float te[Tt];
    for (int i = threadIdx.x; i < Tt; i += blockDim.x)
        te[i] = time_emb[b * Tt + i];
    __syncthreads();
    for (int n = threadIdx.x; n < Dm; n += blockDim.x) {
        float aq = 0.f, ak = 0.f, av = 0.f;
        for (int t = 0; t < Tt; t++) {
            float x = te[t];
            aq += x * Wqt[t * Dm + n];
            ak += x * Wkt[t * Dm + n];
            av += x * Wvt[t * Dm + n];
        }
        g_T[0][b][n] = aq + bqt[n];
        g_T[1][b][n] = ak + bkt[n];
        g_T[2][b][n] = av + bvt[n];
    }
}

// ---------------- prep: fp32 -> bf16 hi/lo splits --------------------------
__device__ __forceinline__ void split4(float4 v,
    __nv_bfloat162& h0, __nv_bfloat162& h1, __nv_bfloat162& l0, __nv_bfloat162& l1)
{
    __nv_bfloat16 a = __float2bfloat16(v.x), b = __float2bfloat16(v.y);
    __nv_bfloat16 c = __float2bfloat16(v.z), d = __float2bfloat16(v.w);
    h0.x = a; h0.y = b; h1.x = c; h1.y = d;
    l0.x = __float2bfloat16(v.x - __bfloat162float(a));
    l0.y = __float2bfloat16(v.y - __bfloat162float(b));
    l1.x = __float2bfloat16(v.z - __bfloat162float(c));
    l1.y = __float2bfloat16(v.w - __bfloat162float(d));
}

__global__ void __launch_bounds__(256) prep_patches(const float* __restrict__ src)
{
    size_t i = (size_t)blockIdx.x * 256 + threadIdx.x;
    float4 v = ((const float4*)src)[i];
    __nv_bfloat162 h0, h1, l0, l1;
    split4(v, h0, h1, l0, l1);
    __nv_bfloat162* H = (__nv_bfloat162*)g_Phi;
    __nv_bfloat162* L = (__nv_bfloat162*)g_Plo;
    H[2 * i] = h0; H[2 * i + 1] = h1;
    L[2 * i] = l0; L[2 * i + 1] = l1;
}

__global__ void __launch_bounds__(256) prep_er(const float* __restrict__ src)
{
    size_t i = (size_t)blockIdx.x * 256 + threadIdx.x;
    float4 v = ((const float4*)src)[i];
    __nv_bfloat162 h0, h1, l0, l1;
    split4(v, h0, h1, l0, l1);
    __nv_bfloat162* H = (__nv_bfloat162*)&g_Erhi[0][0];
    __nv_bfloat162* L = (__nv_bfloat162*)&g_Erlo[0][0];
    H[2 * i] = h0; H[2 * i + 1] = h1;
    L[2 * i] = l0; L[2 * i + 1] = l1;
}

__global__ void __launch_bounds__(256) prep_wt(
    const float* __restrict__ Wq, const float* __restrict__ Wk,
    const float* __restrict__ Wv)
{
    const int z = blockIdx.z;
    const float* __restrict__ W = (z == 0) ? Wq : (z == 1 ? Wk : Wv);
    __shared__ float s[32][33];
    const int n0 = blockIdx.x * 32, k0 = blockIdx.y * 32;
    const int tx = threadIdx.x & 31, ty = threadIdx.x >> 5;
    #pragma unroll
    for (int i = 0; i < 4; i++)
        s[ty + 8 * i][tx] = W[(size_t)(k0 + ty + 8 * i) * Dm + n0 + tx];
    __syncthreads();
    #pragma unroll
    for (int i = 0; i < 4; i++) {
        int n = n0 + ty + 8 * i, k = k0 + tx;
        float v = s[tx][ty + 8 * i];
        __nv_bfloat16 h = __float2bfloat16(v);
        g_WThi[z][n][k] = h;
        g_WTlo[z][n][k] = __float2bfloat16(v - __bfloat162float(h));
    }
}

// ---------------- shared microkernel: one Kc=64 chunk of bf16x3 MMA --------
__device__ __forceinline__ void mma_chunk(uint32_t stage_base, int wm, int wn,
                                          int lane, float c[4][4][4])
{
    const uint32_t aRow = (uint32_t)(wm * 64 + (lane & 15));
    const uint32_t aColBase = (uint32_t)((lane >> 4) * 8);
    const uint32_t bRow = (uint32_t)(wn * 32 + ((lane >> 3) & 1) * 8 + (lane & 7));
    const uint32_t sAh = stage_base;
    const uint32_t sAl = stage_base + TILE_B;
    const uint32_t sBh = stage_base + 2 * TILE_B;
    const uint32_t sBl = stage_base + 3 * TILE_B;

    #pragma unroll
    for (int ks = 0; ks < 4; ks++) {
        const uint32_t kcol = (uint32_t)(ks * 16) + aColBase;
        uint32_t ah[4][4], al[4][4], bh[4][2], bl[4][2];
        #pragma unroll
        for (int mt = 0; mt < 4; mt++) {
            uint32_t off = ((aRow + mt * 16) * RSTR + kcol) * 2;
            ldmx4(ah[mt], sAh + off);
            ldmx4(al[mt], sAl + off);
        }
        #pragma unroll
        for (int nt2 = 0; nt2 < 2; nt2++) {
            uint32_t off = ((bRow + nt2 * 16) * RSTR + kcol) * 2;
            uint32_t t[4];
            ldmx4(t, sBh + off);
            bh[nt2 * 2][0] = t[0]; bh[nt2 * 2][1] = t[2];
            bh[nt2 * 2 + 1][0] = t[1]; bh[nt2 * 2 + 1][1] = t[3];
            ldmx4(t, sBl + off);
            bl[nt2 * 2][0] = t[0]; bl[nt2 * 2][1] = t[2];
            bl[nt2 * 2 + 1][0] = t[1]; bl[nt2 * 2 + 1][1] = t[3];
        }
        #pragma unroll
        for (int mt = 0; mt < 4; mt++)
            #pragma unroll
            for (int nt = 0; nt < 4; nt++) {
                mma16816(c[mt][nt], ah[mt], bh[nt]);
                mma16816(c[mt][nt], ah[mt], bl[nt]);
                mma16816(c[mt][nt], al[mt], bh[nt]);
            }
    }
}

// ---------------- kernel 2: QKV via mma.sync bf16x3 ------------------------
__global__ void __launch_bounds__(256) qkv_mma(
    const float* __restrict__ bq, const float* __restrict__ bk,
    const float* __restrict__ bv)
{
    extern __shared__ char sm[];
    const uint32_t smb = smem_u32(sm);
    const int z = blockIdx.z;
    const int n0 = blockIdx.x * 128, m0 = blockIdx.y * 128;
    const int tid = threadIdx.x;
    const int warp = tid >> 5, lane = tid & 31;
    const int wm = warp & 1, wn = warp >> 1;

    const __nv_bfloat16* pAhi = g_Phi;
    const __nv_bfloat16* pAlo = g_Plo;
    const __nv_bfloat16* pBhi = &g_WThi[z][0][0];
    const __nv_bfloat16* pBlo = &g_WTlo[z][0][0];

    auto load_stage = [&](int chunk, int s) {
        const uint32_t st = smb + (uint32_t)s * STAGE_B;
        const int k0 = chunk * KC;
        #pragma unroll
        for (int it = 0; it < 4; it++) {
            int i = tid + it * 256;
            int r = i >> 3, cc = i & 7;
            uint32_t doff = (uint32_t)(r * RSTR + cc * 8) * 2;
            size_t aoff = (size_t)(m0 + r) * Dm + k0 + cc * 8;
            size_t boff = (size_t)(n0 + r) * Dm + k0 + cc * 8;
            CP16(st + doff, pAhi + aoff);
            CP16(st + TILE_B + doff, pAlo + aoff);
            CP16(st + 2 * TILE_B + doff, pBhi + boff);
            CP16(st + 3 * TILE_B + doff, pBlo + boff);
        }
        CP_COMMIT();
    };

    float c[4][4][4] = {};

    load_stage(0, 0);
    load_stage(1, 1);
    for (int ch = 0; ch < 12; ch++) {
        if (ch < 10) CP_WAIT1(); else if (ch == 10) CP_WAIT0();
        __syncthreads();
        mma_chunk(smb + (uint32_t)(ch & 1) * STAGE_B, wm, wn, lane, c);
        __syncthreads();
        if (ch + 2 < 12) load_stage(ch + 2, ch & 1);
    }

    const float* bias = (z == 0) ? bq : (z == 1 ? bk : bv);
    const int lrow = lane >> 2, lcol = (lane & 3) * 2;
    #pragma unroll
    for (int mt = 0; mt < 4; mt++) {
        #pragma unroll
        for (int nt = 0; nt < 4; nt++) {
            const int col = n0 + wn * 32 + nt * 8 + lcol;
            const float bx = bias[col], by = bias[col + 1];
            #pragma unroll
            for (int hf = 0; hf < 2; hf++) {
                const int row = m0 + wm * 64 + mt * 16 + lrow + hf * 8;
                const int b = row >> 10;
                const float v0 = c[mt][nt][hf * 2 + 0] + bx;
                const float v1 = c[mt][nt][hf * 2 + 1] + by;
                const float t0 = g_T[z][b][col];
                const float t1 = g_T[z][b][col + 1];
                const size_t o = (size_t)row * Dm + col;
                uint32_t hi, lo;
                split2(v0 + t0, v1 + t1, hi, lo);
                if (z == 0) {
                    *(uint32_t*)&g_Qhi[o] = hi;
                    *(uint32_t*)&g_Qlo[o] = lo;
                    uint32_t shi, slo;
                    split2(v0, v1, shi, slo);
                    *(uint32_t*)&g_QShi[o] = shi;
                    *(uint32_t*)&g_QSlo[o] = slo;
                } else if (z == 1) {
                    *(uint32_t*)&g_Khi[o] = hi;
                    *(uint32_t*)&g_Klo[o] = lo;
                } else {
                    *(uint32_t*)&g_Vhi[o] = hi;
                    *(uint32_t*)&g_Vlo[o] = lo;
                }
            }
        }
    }
}

// ---------------- kernel 3: fused flash attention + rel-bias ---------------
// 256 threads (8 warps). Warp = wp (row group, 16 q rows) x wh (k-half, 32 cols).
// Incremental D: Dw is a 128-col ring keyed by (e & 127); each iteration MMAs
// only the new 64-col strip. Er is a 256-row ring keyed by (e & 255).
#define oQh   0u
#define oQl   9216u
#define oQSh  18432u
#define oQSl  29952u
#define oKV   41472u          /* + stage*36864 : Kh,Kl,Vh,Vl each 9216 */
#define oErh  115200u         /* 256 rows x 144 B */
#define oErl  152064u
#define oD    188928u         /* 65 x 132 fp32 = 34320 */
#define oRed  223248u         /* sM 8x16 f32 (512) + sPS 8x16 f32 (512) */
#define ATTN_SMEM 224272
#define OSTR 68

__global__ void __launch_bounds__(256) attn_mma(float* __restrict__ out)
{
    extern __shared__ char sm[];
    const uint32_t smb = smem_u32(sm);
    const int q0 = blockIdx.x * 64;
    const int h = blockIdx.y, b = blockIdx.z;
    const int tid = threadIdx.x, warp = tid >> 5, lane = tid & 31;
    const int wp = warp & 3, wh = warp >> 2;
    float* Dw = (float*)(sm + oD);
    float* sM = (float*)(sm + oRed);
    float* sPS = sM + 128;

    auto load_kv = [&](int kt, int s) {
        const uint32_t st = smb + oKV + (uint32_t)s * 36864u;
        const size_t krow0 = ((size_t)(b * Sq + kt * 64)) * Dm + h * HDm;
        #pragma unroll
        for (int it = 0; it < 2; it++) {
            int i = tid + it * 256;
            int r = i >> 3, cc = i & 7;
            uint32_t doff = (uint32_t)(r * RSTR + cc * 8) * 2;
            size_t src = krow0 + (size_t)r * Dm + cc * 8;
            CP16(st + doff, g_Khi + src);
            CP16(st + 9216u + doff, g_Klo + src);
            CP16(st + 18432u + doff, g_Vhi + src);
            CP16(st + 27648u + doff, g_Vlo + src);
        }
    };
    // strip s covers e in [s*64 - q0, s*64 - q0 + 64)
    auto load_er = [&](int s) {
        const int estart = s * 64 - q0;
        #pragma unroll
        for (int it = 0; it < 2; it++) {
            int i = tid + it * 256;
            int r = i >> 3, cc = i & 7;
            int e = estart + r;
            int t = (e <= 0) ? (Sq - 1 + e) : (e - 2);
            if (t < 0) t = 0; if (t > Sq - 1) t = Sq - 1;
            int rbuf = (estart + r) & 255;
            uint32_t doff = (uint32_t)(rbuf * RSTR + cc * 8) * 2;
            CP16(smb + oErh + doff, &g_Erhi[t][cc * 8]);
            CP16(smb + oErl + doff, &g_Erlo[t][cc * 8]);
        }
    };
    // MMA one 64-col D strip into Dw (8 warps x 8 cols each)
    auto do_dstrip = [&](int s) {
        const int base = s * 64 - q0;
        const uint32_t erow0 = (uint32_t)(base & 255);
        const int dcol0 = base & 127;
        const int par = warp & 1;
        uint32_t ebh[4][2], ebl[4][2];
        const uint32_t nrow = erow0 +
            (uint32_t)((warp & 6) * 8 + ((lane >> 3) & 1) * 8 + (lane & 7));
        #pragma unroll
        for (int ks = 0; ks < 4; ks++) {
            uint32_t addr = smb + oErh +
                (nrow * RSTR + (uint32_t)(ks * 16 + (lane >> 4) * 8)) * 2;
            uint32_t t4[4];
            ldmx4(t4, addr);
            ebh[ks][0] = t4[par]; ebh[ks][1] = t4[2 + par];
            ldmx4(t4, addr + (oErl - oErh));
            ebl[ks][0] = t4[par]; ebl[ks][1] = t4[2 + par];
        }
        #pragma unroll
        for (int mt = 0; mt < 5; mt++) {
            uint32_t sah[4][4], sal[4][4];
            const uint32_t arow = (uint32_t)(mt * 16 + (lane & 15));
            #pragma unroll
            for (int ks = 0; ks < 4; ks++) {
                uint32_t addr = smb + oQSh +
                    (arow * RSTR + (uint32_t)(ks * 16 + (lane >> 4) * 8)) * 2;
                ldmx4(sah[ks], addr);
                ldmx4(sal[ks], addr + (oQSl - oQSh));
            }
            float cc4[4] = {};
            #pragma unroll
            for (int ks = 0; ks < 4; ks++) {
                mma16816(cc4, sah[ks], ebh[ks]);
                mma16816(cc4, sah[ks], ebl[ks]);
                mma16816(cc4, sal[ks], ebh[ks]);
            }
            const int r0 = mt * 16 + (lane >> 2);
            const int colb = dcol0 + warp * 8 + (lane & 3) * 2;
            if (r0 <= 64)
                *(float2*)&Dw[r0 * DSTR + colb] = make_float2(cc4[0], cc4[1]);
            if (r0 + 8 <= 64)
                *(float2*)&Dw[(r0 + 8) * DSTR + colb] = make_float2(cc4[2], cc4[3]);
        }
    };

    // ---- prologue: Q(64), QSext(80), Er strips {-1,0,1}, KV0 | KV1+strip2 --
    {
        const size_t qrow0 = ((size_t)(b * Sq + q0)) * Dm + h * HDm;
        #pragma unroll
        for (int it = 0; it < 2; it++) {
            int i = tid + it * 256;
            int r = i >> 3, cc = i & 7;
            uint32_t doff = (uint32_t)(r * RSTR + cc * 8) * 2;
            size_t src = qrow0 + (size_t)r * Dm + cc * 8;
            CP16(smb + oQh + doff, g_Qhi + src);
            CP16(smb + oQl + doff, g_Qlo + src);
        }
        #pragma unroll
        for (int it = 0; it < 3; it++) {
            int i = tid + it * 256;
            if (i < 640) {
                int r = i >> 3, cc = i & 7;
                int rr = q0 + r; if (rr > Sq - 1) rr = Sq - 1;
                uint32_t doff = (uint32_t)(r * RSTR + cc * 8) * 2;
                size_t src = ((size_t)(b * Sq + rr)) * Dm + h * HDm + cc * 8;
                CP16(smb + oQSh + doff, g_QShi + src);
                CP16(smb + oQSl + doff, g_QSlo + src);
            }
        }
        load_er(-1); load_er(0); load_er(1);
        load_kv(0, 0);
        CP_COMMIT();                 // G0
        load_kv(1, 1);
        load_er(2);
        CP_COMMIT();                 // G1
    }

    float m_[2] = {-1e30f, -1e30f}, l_[2] = {0.f, 0.f};
    float co[8][4] = {};
    const int row16 = (lane >> 2);   // + hf*8

    for (int kt = 0; kt < 16; kt++) {
        const int s = kt & 1;
        const int d0 = kt * 64 - q0;
        CP_WAIT1();
        __syncthreads();

        // ---- D strips (incremental) ----
        if (kt == 0) { do_dstrip(-1); do_dstrip(0); }
        else do_dstrip(kt);

        // ---- QK^T: 16 q rows x 32 k cols per warp ----
        float c[4][4] = {};
        {
            const uint32_t stK = smb + oKV + (uint32_t)s * 36864u;
            uint32_t qah[4][4], qal[4][4];
            const uint32_t arow = (uint32_t)(wp * 16 + (lane & 15));
            #pragma unroll
            for (int ks = 0; ks < 4; ks++) {
                uint32_t addr = smb + oQh +
                    (arow * RSTR + (uint32_t)(ks * 16 + (lane >> 4) * 8)) * 2;
                ldmx4(qah[ks], addr);
                ldmx4(qal[ks], addr + (oQl - oQh));
            }
            #pragma unroll
            for (int ks = 0; ks < 4; ks++) {
                uint32_t bh[4][2], bl[4][2];
                #pragma unroll
                for (int pp = 0; pp < 2; pp++) {
                    uint32_t nrow = (uint32_t)(wh * 32 + pp * 16 +
                                    ((lane >> 3) & 1) * 8 + (lane & 7));
                    uint32_t addr = stK +
                        (nrow * RSTR + (uint32_t)(ks * 16 + (lane >> 4) * 8)) * 2;
                    uint32_t t4[4];
                    ldmx4(t4, addr);
                    bh[pp * 2][0] = t4[0]; bh[pp * 2][1] = t4[2];
                    bh[pp * 2 + 1][0] = t4[1]; bh[pp * 2 + 1][1] = t4[3];
                    ldmx4(t4, addr + 9216u);
                    bl[pp * 2][0] = t4[0]; bl[pp * 2][1] = t4[2];
                    bl[pp * 2 + 1][0] = t4[1]; bl[pp * 2 + 1][1] = t4[3];
                }
                #pragma unroll
                for (int nt = 0; nt < 4; nt++) {
                    mma16816(c[nt], qah[ks], bh[nt]);
                    mma16816(c[nt], qah[ks], bl[nt]);
                    mma16816(c[nt], qal[ks], bh[nt]);
                }
            }
        }

        __syncthreads();   // Dw strip visible

        // ---- bias gather + partial max ----
        float mloc[2] = {-1e30f, -1e30f};
        #pragma unroll
        for (int nt = 0; nt < 4; nt++) {
            #pragma unroll
            for (int e2 = 0; e2 < 2; e2++) {
                const int col = wh * 32 + nt * 8 + (lane & 3) * 2 + e2;
                #pragma unroll
                for (int hf = 0; hf < 2; hf++) {
                    const int q_loc = wp * 16 + row16 + hf * 8;
                    const int e = d0 + col - q_loc;
                    float bias = (e == 1) ? 0.f
                               : Dw[(q_loc + (e >= 2 ? 1 : 0)) * DSTR + (e & 127)];
                    float sv = (c[nt][hf * 2 + e2] + bias) * SCALE_F;
                    c[nt][hf * 2 + e2] = sv;
                    mloc[hf] = fmaxf(mloc[hf], sv);
                }
            }
        }
        #pragma unroll
        for (int hf = 0; hf < 2; hf++) {
            mloc[hf] = fmaxf(mloc[hf], __shfl_xor_sync(0xffffffffu, mloc[hf], 1));
            mloc[hf] = fmaxf(mloc[hf], __shfl_xor_sync(0xffffffffu, mloc[hf], 2));
        }
        if ((lane & 3) == 0) {
            sM[warp * 16 + row16] = mloc[0];
            sM[warp * 16 + row16 + 8] = mloc[1];
        }
        __syncthreads();

        float corr[2], psum[2] = {0.f, 0.f};
        #pragma unroll
        for (int hf = 0; hf < 2; hf++) {
            float mp = sM[(warp ^ 4) * 16 + row16 + hf * 8];
            float mn = fmaxf(m_[hf], fmaxf(mloc[hf], mp));
            corr[hf] = __expf(m_[hf] - mn);
            m_[hf] = mn;
        }
        #pragma unroll
        for (int nt = 0; nt < 4; nt++) {
            #pragma unroll
            for (int k4 = 0; k4 < 4; k4++) {
                const int hf = k4 >> 1;
                float p = __expf(c[nt][k4] - m_[hf]);
                c[nt][k4] = p;
                psum[hf] += p;
            }
        }
        #pragma unroll
        for (int hf = 0; hf < 2; hf++) {
            psum[hf] += __shfl_xor_sync(0xffffffffu, psum[hf], 1);
            psum[hf] += __shfl_xor_sync(0xffffffffu, psum[hf], 2);
        }
        if ((lane & 3) == 0) {
            sPS[warp * 16 + row16] = psum[0];
            sPS[warp * 16 + row16 + 8] = psum[1];
        }
        __syncthreads();
        #pragma unroll
        for (int hf = 0; hf < 2; hf++) {
            float pp2 = sPS[(warp ^ 4) * 16 + row16 + hf * 8];
            l_[hf] = l_[hf] * corr[hf] + psum[hf] + pp2;
        }
        #pragma unroll
        for (int nt = 0; nt < 8; nt++) {
            co[nt][0] *= corr[0]; co[nt][1] *= corr[0];
            co[nt][2] *= corr[1]; co[nt][3] *= corr[1];
        }

        // ---- PV: P(16 x 32) x V(32 x 64) partial ----
        {
            const uint32_t stV = smb + oKV + (uint32_t)s * 36864u + 18432u;
            #pragma unroll
            for (int ktk = 0; ktk < 2; ktk++) {
                uint32_t pha[4], pla[4];
                #pragma unroll
                for (int sub = 0; sub < 2; sub++) {
                    #pragma unroll
                    for (int half2 = 0; half2 < 2; half2++) {
                        float x = c[2 * ktk + sub][half2 * 2];
                        float y = c[2 * ktk + sub][half2 * 2 + 1];
                        uint32_t hi, lo;
                        split2(x, y, hi, lo);
                        pha[half2 + sub * 2] = hi;
                        pla[half2 + sub * 2] = lo;
                    }
                }
                uint32_t vbh[8][2], vbl[8][2];
                #pragma unroll
                for (int pp = 0; pp < 4; pp++) {
                    uint32_t krow = (uint32_t)(wh * 32 + ktk * 16 +
                                   (lane & 7) + ((lane >> 3) & 1) * 8);
                    uint32_t ncol = (uint32_t)(pp * 16 + (lane >> 4) * 8);
                    uint32_t addr = stV + (krow * RSTR + ncol) * 2;
                    uint32_t t4[4];
                    ldmx4t(t4, addr);
                    vbh[pp * 2][0] = t4[0]; vbh[pp * 2][1] = t4[1];
                    vbh[pp * 2 + 1][0] = t4[2]; vbh[pp * 2 + 1][1] = t4[3];
                    ldmx4t(t4, addr + 9216u);
                    vbl[pp * 2][0] = t4[0]; vbl[pp * 2][1] = t4[1];
                    vbl[pp * 2 + 1][0] = t4[2]; vbl[pp * 2 + 1][1] = t4[3];
                }
                #pragma unroll
                for (int nt = 0; nt < 8; nt++) {
                    mma16816(co[nt], pha, vbh[nt]);
                    mma16816(co[nt], pha, vbl[nt]);
                    mma16816(co[nt], pla, vbh[nt]);
                }
            }
        }

        __syncthreads();   // all reads of KV stage s & Er slots done

        if (kt + 2 < 16) load_kv(kt + 2, s);
        if (kt + 3 < 16) load_er(kt + 3);
        CP_COMMIT();
    }

    // ---- combine warp-pair partials & write out ----
    __syncthreads();
    float* sOut = (float*)(sm + oKV);
    if (wh == 1) {
        #pragma unroll
        for (int hf = 0; hf < 2; hf++) {
            const int row = wp * 16 + row16 + hf * 8;
            #pragma unroll
            for (int nt = 0; nt < 8; nt++) {
                const int col = nt * 8 + (lane & 3) * 2;
                *(float2*)&sOut[row * OSTR + col] =
                    make_float2(co[nt][hf * 2], co[nt][hf * 2 + 1]);
            }
        }
    }
    __syncthreads();
    if (wh == 0) {
        #pragma unroll
        for (int hf = 0; hf < 2; hf++) {
            const float inv = 1.0f / l_[hf];
            const int row = wp * 16 + row16 + hf * 8;
            const size_t ob = ((size_t)(b * Sq + q0 + row)) * Dm + h * HDm;
            #pragma unroll
            for (int nt = 0; nt < 8; nt++) {
                const int col = nt * 8 + (lane & 3) * 2;
                float2 pr = *(float2*)&sOut[row * OSTR + col];
                *(float2*)&out[ob + col] =
                    make_float2((co[nt][hf * 2] + pr.x) * inv,
                                (co[nt][hf * 2 + 1] + pr.y) * inv);
            }
        }
    }
}

// ---------------- launch ----------------------------------------------------
extern "C" void kernel_launch(void* const* d_in, const int* in_sizes, int n_in,
                              void* d_out, int out_size)
{
    (void)in_sizes; (void)n_in; (void)out_size;
    const float* patches  = (const float*)d_in[0];
    const float* time_emb = (const float*)d_in[1];
    const float* Wqs = (const float*)d_in[2];
    const float* bqs = (const float*)d_in[3];
    const float* Wks = (const float*)d_in[4];
    const float* bks = (const float*)d_in[5];
    const float* Wvs = (const float*)d_in[6];
    const float* bvs = (const float*)d_in[7];
    const float* Wqt = (const float*)d_in[8];
    const float* bqt = (const float*)d_in[9];
    const float* Wkt = (const float*)d_in[10];
    const float* bkt = (const float*)d_in[11];
    const float* Wvt = (const float*)d_in[12];
    const float* bvt = (const float*)d_in[13];
    const float* Er  = (const float*)d_in[14];
    float* out = (float*)d_out;

    time_proj<<<Bb, 256>>>(time_emb, Wqt, bqt, Wkt, bkt, Wvt, bvt);
    prep_patches<<<(Bb * Sq * Dm / 4) / 256, 256>>>(patches);
    prep_er<<<(Sq * HDm / 4) / 256, 256>>>(Er);
    prep_wt<<<dim3(Dm / 32, Dm / 32, 3), 256>>>(Wqs, Wks, Wvs);

    const int qkv_smem = 2 * STAGE_B;  // 147456
    cudaFuncSetAttribute(qkv_mma, cudaFuncAttributeMaxDynamicSharedMemorySize, qkv_smem);
    qkv_mma<<<dim3(Dm / 128, (Bb * Sq) / 128, 3), 256, qkv_smem>>>(bqs, bks, bvs);

    cudaFuncSetAttribute(attn_mma, cudaFuncAttributeMaxDynamicSharedMemorySize, ATTN_SMEM);
    attn_mma<<<dim3(Sq / 64, Hh, Bb), 256, ATTN_SMEM>>>(out);
}

// round 6
// speedup vs baseline: 2.1178x; 1.0097x over previous
#include <cuda_runtime.h>
#include <cuda_bf16.h>
#include <cstdint>
#include <cstddef>

#define Sq 1024
#define Dm 768
#define Hh 12
#define HDm 64
#define Bb 8
#define Tt 384
#define SCALE_F 0.125f

// ---------------- scratch (device globals; no allocation allowed) ----------
__device__ float g_T[3][Bb][Dm];                       // time q/k/v vectors
__device__ __nv_bfloat16 g_Phi[(size_t)Bb * Sq * Dm];  // patches hi/lo
__device__ __nv_bfloat16 g_Plo[(size_t)Bb * Sq * Dm];
__device__ __nv_bfloat16 g_WThi[3][Dm][Dm];            // W^T hi/lo [z][n][k]
__device__ __nv_bfloat16 g_WTlo[3][Dm][Dm];
__device__ __nv_bfloat16 g_QShi[(size_t)Bb * Sq * Dm]; // qs (no time) hi/lo
__device__ __nv_bfloat16 g_QSlo[(size_t)Bb * Sq * Dm];
__device__ __nv_bfloat16 g_Qhi[(size_t)Bb * Sq * Dm];  // qs+tq hi/lo
__device__ __nv_bfloat16 g_Qlo[(size_t)Bb * Sq * Dm];
__device__ __nv_bfloat16 g_Khi[(size_t)Bb * Sq * Dm];  // ks+tk hi/lo
__device__ __nv_bfloat16 g_Klo[(size_t)Bb * Sq * Dm];
__device__ __nv_bfloat16 g_Vhi[(size_t)Bb * Sq * Dm];  // vs+tv hi/lo
__device__ __nv_bfloat16 g_Vlo[(size_t)Bb * Sq * Dm];
__device__ __nv_bfloat16 g_Erhi[Sq][HDm];
__device__ __nv_bfloat16 g_Erlo[Sq][HDm];

// ---------------- PTX helpers (baseline ISA: sm_80+) ------------------------
__device__ __forceinline__ uint32_t smem_u32(const void* p) {
    uint32_t a;
    asm("{ .reg .u64 t; cvta.to.shared.u64 t, %1; cvt.u32.u64 %0, t; }"
        : "=r"(a) : "l"(p));
    return a;
}
__device__ __forceinline__ void ldmx4(uint32_t* r, uint32_t addr) {
    asm volatile("ldmatrix.sync.aligned.m8n8.x4.shared.b16 {%0,%1,%2,%3}, [%4];"
                 : "=r"(r[0]), "=r"(r[1]), "=r"(r[2]), "=r"(r[3]) : "r"(addr));
}
__device__ __forceinline__ void ldmx4t(uint32_t* r, uint32_t addr) {
    asm volatile("ldmatrix.sync.aligned.m8n8.x4.trans.shared.b16 {%0,%1,%2,%3}, [%4];"
                 : "=r"(r[0]), "=r"(r[1]), "=r"(r[2]), "=r"(r[3]) : "r"(addr));
}
__device__ __forceinline__ void mma16816(float* c, const uint32_t* a, const uint32_t* b) {
    asm volatile(
        "mma.sync.aligned.m16n8k16.row.col.f32.bf16.bf16.f32 "
        "{%0,%1,%2,%3}, {%4,%5,%6,%7}, {%8,%9}, {%0,%1,%2,%3};"
        : "+f"(c[0]), "+f"(c[1]), "+f"(c[2]), "+f"(c[3])
        : "r"(a[0]), "r"(a[1]), "r"(a[2]), "r"(a[3]), "r"(b[0]), "r"(b[1]));
}
#define CP16(dst, src) asm volatile("cp.async.cg.shared.global [%0], [%1], 16;" :: "r"(dst), "l"(src))
#define CP_COMMIT()    asm volatile("cp.async.commit_group;" ::: "memory")
#define CP_WAIT1()     asm volatile("cp.async.wait_group 1;" ::: "memory")
#define CP_WAIT0()     asm volatile("cp.async.wait_group 0;" ::: "memory")

#define KC 64
#define RSTR 72
#define TILE_B (128 * RSTR * 2)          // 18432 B per 128-row operand tile
#define STAGE_B (4 * TILE_B)             // 73728 B
#define DSTR 132

__device__ __forceinline__ void split2(float x, float y, uint32_t& hi, uint32_t& lo) {
    __nv_bfloat162 h, l;
    h.x = __float2bfloat16(x); h.y = __float2bfloat16(y);
    l.x = __float2bfloat16(x - __bfloat162float(h.x));
    l.y = __float2bfloat16(y - __bfloat162float(h.y));
    hi = *(uint32_t*)&h; lo = *(uint32_t*)&l;
}

// ---------------- kernel 1: time projections ------------------------------
__global__ void __launch_bounds__(256) time_proj(
    const float* __restrict__ time_emb,
    const float* __restrict__ Wqt, const float* __restrict__ bqt,
    const float* __restrict__ Wkt, const float* __restrict__ bkt,
    const float* __restrict__ Wvt, const float* __restrict__ bvt)
{
    const int b = blockIdx.x;
    __shared__ float te[Tt];
    for (int i = threadIdx.x; i < Tt; i += blockDim.x)
        te[i] = time_emb[b * Tt + i];
    __syncthreads();
    for (int n = threadIdx.x; n < Dm; n += blockDim.x) {
        float aq = 0.f, ak = 0.f, av = 0.f;
        for (int t = 0; t < Tt; t++) {
            float x = te[t];
            aq += x * Wqt[t * Dm + n];
            ak += x * Wkt[t * Dm + n];
            av += x * Wvt[t * Dm + n];
        }
        g_T[0][b][n] = aq + bqt[n];
        g_T[1][b][n] = ak + bkt[n];
        g_T[2][b][n] = av + bvt[n];
    }
}

// ---------------- prep: fp32 -> bf16 hi/lo splits --------------------------
__device__ __forceinline__ void split4(float4 v,
    __nv_bfloat162& h0, __nv_bfloat162& h1, __nv_bfloat162& l0, __nv_bfloat162& l1)
{
    __nv_bfloat16 a = __float2bfloat16(v.x), b = __float2bfloat16(v.y);
    __nv_bfloat16 c = __float2bfloat16(v.z), d = __float2bfloat16(v.w);
    h0.x = a; h0.y = b; h1.x = c; h1.y = d;
    l0.x = __float2bfloat16(v.x - __bfloat162float(a));
    l0.y = __float2bfloat16(v.y - __bfloat162float(b));
    l1.x = __float2bfloat16(v.z - __bfloat162float(c));
    l1.y = __float2bfloat16(v.w - __bfloat162float(d));
}

__global__ void __launch_bounds__(256) prep_patches(const float* __restrict__ src)
{
    size_t i = (size_t)blockIdx.x * 256 + threadIdx.x;
    float4 v = ((const float4*)src)[i];
    __nv_bfloat162 h0, h1, l0, l1;
    split4(v, h0, h1, l0, l1);
    __nv_bfloat162* H = (__nv_bfloat162*)g_Phi;
    __nv_bfloat162* L = (__nv_bfloat162*)g_Plo;
    H[2 * i] = h0; H[2 * i + 1] = h1;
    L[2 * i] = l0; L[2 * i + 1] = l1;
}

__global__ void __launch_bounds__(256) prep_er(const float* __restrict__ src)
{
    size_t i = (size_t)blockIdx.x * 256 + threadIdx.x;
    float4 v = ((const float4*)src)[i];
    __nv_bfloat162 h0, h1, l0, l1;
    split4(v, h0, h1, l0, l1);
    __nv_bfloat162* H = (__nv_bfloat162*)&g_Erhi[0][0];
    __nv_bfloat162* L = (__nv_bfloat162*)&g_Erlo[0][0];
    H[2 * i] = h0; H[2 * i + 1] = h1;
    L[2 * i] = l0; L[2 * i + 1] = l1;
}

__global__ void __launch_bounds__(256) prep_wt(
    const float* __restrict__ Wq, const float* __restrict__ Wk,
    const float* __restrict__ Wv)
{
    const int z = blockIdx.z;
    const float* __restrict__ W = (z == 0) ? Wq : (z == 1 ? Wk : Wv);
    __shared__ float s[32][33];
    const int n0 = blockIdx.x * 32, k0 = blockIdx.y * 32;
    const int tx = threadIdx.x & 31, ty = threadIdx.x >> 5;
    #pragma unroll
    for (int i = 0; i < 4; i++)
        s[ty + 8 * i][tx] = W[(size_t)(k0 + ty + 8 * i) * Dm + n0 + tx];
    __syncthreads();
    #pragma unroll
    for (int i = 0; i < 4; i++) {
        int n = n0 + ty + 8 * i, k = k0 + tx;
        float v = s[tx][ty + 8 * i];
        __nv_bfloat16 h = __float2bfloat16(v);
        g_WThi[z][n][k] = h;
        g_WTlo[z][n][k] = __float2bfloat16(v - __bfloat162float(h));
    }
}

// ---------------- shared microkernel: one Kc=64 chunk of bf16x3 MMA --------
__device__ __forceinline__ void mma_chunk(uint32_t stage_base, int wm, int wn,
                                          int lane, float c[4][4][4])
{
    const uint32_t aRow = (uint32_t)(wm * 64 + (lane & 15));
    const uint32_t aColBase = (uint32_t)((lane >> 4) * 8);
    const uint32_t bRow = (uint32_t)(wn * 32 + ((lane >> 3) & 1) * 8 + (lane & 7));
    const uint32_t sAh = stage_base;
    const uint32_t sAl = stage_base + TILE_B;
    const uint32_t sBh = stage_base + 2 * TILE_B;
    const uint32_t sBl = stage_base + 3 * TILE_B;

    #pragma unroll
    for (int ks = 0; ks < 4; ks++) {
        const uint32_t kcol = (uint32_t)(ks * 16) + aColBase;
        uint32_t ah[4][4], al[4][4], bh[4][2], bl[4][2];
        #pragma unroll
        for (int mt = 0; mt < 4; mt++) {
            uint32_t off = ((aRow + mt * 16) * RSTR + kcol) * 2;
            ldmx4(ah[mt], sAh + off);
            ldmx4(al[mt], sAl + off);
        }
        #pragma unroll
        for (int nt2 = 0; nt2 < 2; nt2++) {
            uint32_t off = ((bRow + nt2 * 16) * RSTR + kcol) * 2;
            uint32_t t[4];
            ldmx4(t, sBh + off);
            bh[nt2 * 2][0] = t[0]; bh[nt2 * 2][1] = t[2];
            bh[nt2 * 2 + 1][0] = t[1]; bh[nt2 * 2 + 1][1] = t[3];
            ldmx4(t, sBl + off);
            bl[nt2 * 2][0] = t[0]; bl[nt2 * 2][1] = t[2];
            bl[nt2 * 2 + 1][0] = t[1]; bl[nt2 * 2 + 1][1] = t[3];
        }
        #pragma unroll
        for (int mt = 0; mt < 4; mt++)
            #pragma unroll
            for (int nt = 0; nt < 4; nt++) {
                mma16816(c[mt][nt], ah[mt], bh[nt]);
                mma16816(c[mt][nt], ah[mt], bl[nt]);
                mma16816(c[mt][nt], al[mt], bh[nt]);
            }
    }
}

// ---------------- kernel 2: QKV via mma.sync bf16x3 (3-stage pipeline) -----
__global__ void __launch_bounds__(256) qkv_mma(
    const float* __restrict__ bq, const float* __restrict__ bk,
    const float* __restrict__ bv)
{
    extern __shared__ char sm[];
    const uint32_t smb = smem_u32(sm);
    const int z = blockIdx.z;
    const int n0 = blockIdx.x * 128, m0 = blockIdx.y * 128;
    const int tid = threadIdx.x;
    const int warp = tid >> 5, lane = tid & 31;
    const int wm = warp & 1, wn = warp >> 1;

    const __nv_bfloat16* pAhi = g_Phi;
    const __nv_bfloat16* pAlo = g_Plo;
    const __nv_bfloat16* pBhi = &g_WThi[z][0][0];
    const __nv_bfloat16* pBlo = &g_WTlo[z][0][0];

    auto load_stage = [&](int chunk, int s) {
        const uint32_t st = smb + (uint32_t)s * STAGE_B;
        const int k0 = chunk * KC;
        #pragma unroll
        for (int it = 0; it < 4; it++) {
            int i = tid + it * 256;
            int r = i >> 3, cc = i & 7;
            uint32_t doff = (uint32_t)(r * RSTR + cc * 8) * 2;
            size_t aoff = (size_t)(m0 + r) * Dm + k0 + cc * 8;
            size_t boff = (size_t)(n0 + r) * Dm + k0 + cc * 8;
            CP16(st + doff, pAhi + aoff);
            CP16(st + TILE_B + doff, pAlo + aoff);
            CP16(st + 2 * TILE_B + doff, pBhi + boff);
            CP16(st + 3 * TILE_B + doff, pBlo + boff);
        }
        CP_COMMIT();
    };

    float c[4][4][4] = {};

    load_stage(0, 0);
    load_stage(1, 1);
    for (int ch = 0; ch < 12; ch++) {
        if (ch < 10) CP_WAIT1(); else CP_WAIT0();
        __syncthreads();
        if (ch + 2 < 12) load_stage(ch + 2, (ch + 2) % 3);
        mma_chunk(smb + (uint32_t)(ch % 3) * STAGE_B, wm, wn, lane, c);
    }

    const float* bias = (z == 0) ? bq : (z == 1 ? bk : bv);
    const int lrow = lane >> 2, lcol = (lane & 3) * 2;
    #pragma unroll
    for (int mt = 0; mt < 4; mt++) {
        #pragma unroll
        for (int nt = 0; nt < 4; nt++) {
            const int col = n0 + wn * 32 + nt * 8 + lcol;
            const float bx = bias[col], by = bias[col + 1];
            #pragma unroll
            for (int hf = 0; hf < 2; hf++) {
                const int row = m0 + wm * 64 + mt * 16 + lrow + hf * 8;
                const int b = row >> 10;
                const float v0 = c[mt][nt][hf * 2 + 0] + bx;
                const float v1 = c[mt][nt][hf * 2 + 1] + by;
                const float t0 = g_T[z][b][col];
                const float t1 = g_T[z][b][col + 1];
                const size_t o = (size_t)row * Dm + col;
                uint32_t hi, lo;
                split2(v0 + t0, v1 + t1, hi, lo);
                if (z == 0) {
                    *(uint32_t*)&g_Qhi[o] = hi;
                    *(uint32_t*)&g_Qlo[o] = lo;
                    uint32_t shi, slo;
                    split2(v0, v1, shi, slo);
                    *(uint32_t*)&g_QShi[o] = shi;
                    *(uint32_t*)&g_QSlo[o] = slo;
                } else if (z == 1) {
                    *(uint32_t*)&g_Khi[o] = hi;
                    *(uint32_t*)&g_Klo[o] = lo;
                } else {
                    *(uint32_t*)&g_Vhi[o] = hi;
                    *(uint32_t*)&g_Vlo[o] = lo;
                }
            }
        }
    }
}

// ---------------- kernel 3: fused flash attention + rel-bias ---------------
// 256 threads (8 warps). Warp = wp (row group, 16 q rows) x wh (k-half, 32 cols).
// Independent online softmax per k-half; single merge at the end.
#define oQh   0u
#define oQl   9216u
#define oQSh  18432u
#define oQSl  29952u
#define oKV   41472u          /* + stage*36864 : Kh,Kl,Vh,Vl each 9216 */
#define oErh  115200u         /* 256 rows x 144 B */
#define oErl  152064u
#define oD    188928u         /* 65 x 132 fp32 = 34320 */
#define oRed  223248u         /* sM 128 f32 + sL 128 f32 */
#define ATTN_SMEM 224272
#define OSTR 68

__global__ void __launch_bounds__(256) attn_mma(float* __restrict__ out)
{
    extern __shared__ char sm[];
    const uint32_t smb = smem_u32(sm);
    const int q0 = blockIdx.x * 64;
    const int h = blockIdx.y, b = blockIdx.z;
    const int tid = threadIdx.x, warp = tid >> 5, lane = tid & 31;
    const int wp = warp & 3, wh = warp >> 2;
    float* Dw = (float*)(sm + oD);
    float* sM = (float*)(sm + oRed);
    float* sL = sM + 128;

    auto load_kv = [&](int kt, int s) {
        const uint32_t st = smb + oKV + (uint32_t)s * 36864u;
        const size_t krow0 = ((size_t)(b * Sq + kt * 64)) * Dm + h * HDm;
        #pragma unroll
        for (int it = 0; it < 2; it++) {
            int i = tid + it * 256;
            int r = i >> 3, cc = i & 7;
            uint32_t doff = (uint32_t)(r * RSTR + cc * 8) * 2;
            size_t src = krow0 + (size_t)r * Dm + cc * 8;
            CP16(st + doff, g_Khi + src);
            CP16(st + 9216u + doff, g_Klo + src);
            CP16(st + 18432u + doff, g_Vhi + src);
            CP16(st + 27648u + doff, g_Vlo + src);
        }
    };
    auto load_er = [&](int s) {
        const int estart = s * 64 - q0;
        #pragma unroll
        for (int it = 0; it < 2; it++) {
            int i = tid + it * 256;
            int r = i >> 3, cc = i & 7;
            int e = estart + r;
            int t = (e <= 0) ? (Sq - 1 + e) : (e - 2);
            if (t < 0) t = 0; if (t > Sq - 1) t = Sq - 1;
            int rbuf = (estart + r) & 255;
            uint32_t doff = (uint32_t)(rbuf * RSTR + cc * 8) * 2;
            CP16(smb + oErh + doff, &g_Erhi[t][cc * 8]);
            CP16(smb + oErl + doff, &g_Erlo[t][cc * 8]);
        }
    };
    auto do_dstrip = [&](int s) {
        const int base = s * 64 - q0;
        const uint32_t erow0 = (uint32_t)(base & 255);
        const int dcol0 = base & 127;
        const int par = warp & 1;
        uint32_t ebh[4][2], ebl[4][2];
        const uint32_t nrow = erow0 +
            (uint32_t)((warp & 6) * 8 + ((lane >> 3) & 1) * 8 + (lane & 7));
        #pragma unroll
        for (int ks = 0; ks < 4; ks++) {
            uint32_t addr = smb + oErh +
                (nrow * RSTR + (uint32_t)(ks * 16 + (lane >> 4) * 8)) * 2;
            uint32_t t4[4];
            ldmx4(t4, addr);
            ebh[ks][0] = t4[par]; ebh[ks][1] = t4[2 + par];
            ldmx4(t4, addr + (oErl - oErh));
            ebl[ks][0] = t4[par]; ebl[ks][1] = t4[2 + par];
        }
        #pragma unroll
        for (int mt = 0; mt < 5; mt++) {
            uint32_t sah[4][4], sal[4][4];
            const uint32_t arow = (uint32_t)(mt * 16 + (lane & 15));
            #pragma unroll
            for (int ks = 0; ks < 4; ks++) {
                uint32_t addr = smb + oQSh +
                    (arow * RSTR + (uint32_t)(ks * 16 + (lane >> 4) * 8)) * 2;
                ldmx4(sah[ks], addr);
                ldmx4(sal[ks], addr + (oQSl - oQSh));
            }
            float cc4[4] = {};
            #pragma unroll
            for (int ks = 0; ks < 4; ks++) {
                mma16816(cc4, sah[ks], ebh[ks]);
                mma16816(cc4, sah[ks], ebl[ks]);
                mma16816(cc4, sal[ks], ebh[ks]);
            }
            const int r0 = mt * 16 + (lane >> 2);
            const int colb = dcol0 + warp * 8 + (lane & 3) * 2;
            if (r0 <= 64)
                *(float2*)&Dw[r0 * DSTR + colb] = make_float2(cc4[0], cc4[1]);
            if (r0 + 8 <= 64)
                *(float2*)&Dw[(r0 + 8) * DSTR + colb] = make_float2(cc4[2], cc4[3]);
        }
    };

    // ---- prologue loads ----
    {
        const size_t qrow0 = ((size_t)(b * Sq + q0)) * Dm + h * HDm;
        #pragma unroll
        for (int it = 0; it < 2; it++) {
            int i = tid + it * 256;
            int r = i >> 3, cc = i & 7;
            uint32_t doff = (uint32_t)(r * RSTR + cc * 8) * 2;
            size_t src = qrow0 + (size_t)r * Dm + cc * 8;
            CP16(smb + oQh + doff, g_Qhi + src);
            CP16(smb + oQl + doff, g_Qlo + src);
        }
        #pragma unroll
        for (int it = 0; it < 3; it++) {
            int i = tid + it * 256;
            if (i < 640) {
                int r = i >> 3, cc = i & 7;
                int rr = q0 + r; if (rr > Sq - 1) rr = Sq - 1;
                uint32_t doff = (uint32_t)(r * RSTR + cc * 8) * 2;
                size_t src = ((size_t)(b * Sq + rr)) * Dm + h * HDm + cc * 8;
                CP16(smb + oQSh + doff, g_QShi + src);
                CP16(smb + oQSl + doff, g_QSlo + src);
            }
        }
        load_er(-1); load_er(0); load_er(1);
        load_kv(0, 0);
        CP_COMMIT();                 // G0
        load_kv(1, 1);
        load_er(2);
        CP_COMMIT();                 // G1
    }

    CP_WAIT1();
    __syncthreads();                 // G0 visible to all

    // ---- hoist Q fragments (loop-invariant) ----
    uint32_t qah[4][4], qal[4][4];
    {
        const uint32_t arow = (uint32_t)(wp * 16 + (lane & 15));
        #pragma unroll
        for (int ks = 0; ks < 4; ks++) {
            uint32_t addr = smb + oQh +
                (arow * RSTR + (uint32_t)(ks * 16 + (lane >> 4) * 8)) * 2;
            ldmx4(qah[ks], addr);
            ldmx4(qal[ks], addr + (oQl - oQh));
        }
    }

    float m_[2] = {-1e30f, -1e30f}, l_[2] = {0.f, 0.f};
    float co[8][4] = {};
    const int row16 = (lane >> 2);

    for (int kt = 0; kt < 16; kt++) {
        const int s = kt & 1;
        const int d0 = kt * 64 - q0;
        if (kt > 0) { CP_WAIT1(); __syncthreads(); }

        // ---- D strips (incremental) ----
        if (kt == 0) { do_dstrip(-1); do_dstrip(0); }
        else do_dstrip(kt);

        // ---- QK^T: 16 q rows x 32 k cols per warp ----
        float c[4][4] = {};
        {
            const uint32_t stK = smb + oKV + (uint32_t)s * 36864u;
            #pragma unroll
            for (int ks = 0; ks < 4; ks++) {
                uint32_t bh[4][2], bl[4][2];
                #pragma unroll
                for (int pp = 0; pp < 2; pp++) {
                    uint32_t nrow = (uint32_t)(wh * 32 + pp * 16 +
                                    ((lane >> 3) & 1) * 8 + (lane & 7));
                    uint32_t addr = stK +
                        (nrow * RSTR + (uint32_t)(ks * 16 + (lane >> 4) * 8)) * 2;
                    uint32_t t4[4];
                    ldmx4(t4, addr);
                    bh[pp * 2][0] = t4[0]; bh[pp * 2][1] = t4[2];
                    bh[pp * 2 + 1][0] = t4[1]; bh[pp * 2 + 1][1] = t4[3];
                    ldmx4(t4, addr + 9216u);
                    bl[pp * 2][0] = t4[0]; bl[pp * 2][1] = t4[2];
                    bl[pp * 2 + 1][0] = t4[1]; bl[pp * 2 + 1][1] = t4[3];
                }
                #pragma unroll
                for (int nt = 0; nt < 4; nt++) {
                    mma16816(c[nt], qah[ks], bh[nt]);
                    mma16816(c[nt], qah[ks], bl[nt]);
                    mma16816(c[nt], qal[ks], bh[nt]);
                }
            }
        }

        __syncthreads();   // Dw strip visible

        // ---- bias gather + own-half online softmax ----
        float mloc[2] = {-1e30f, -1e30f};
        #pragma unroll
        for (int nt = 0; nt < 4; nt++) {
            #pragma unroll
            for (int e2 = 0; e2 < 2; e2++) {
                const int col = wh * 32 + nt * 8 + (lane & 3) * 2 + e2;
                #pragma unroll
                for (int hf = 0; hf < 2; hf++) {
                    const int q_loc = wp * 16 + row16 + hf * 8;
                    const int e = d0 + col - q_loc;
                    float bias = (e == 1) ? 0.f
                               : Dw[(q_loc + (e >= 2 ? 1 : 0)) * DSTR + (e & 127)];
                    float sv = (c[nt][hf * 2 + e2] + bias) * SCALE_F;
                    c[nt][hf * 2 + e2] = sv;
                    mloc[hf] = fmaxf(mloc[hf], sv);
                }
            }
        }
        float corr[2], psum[2] = {0.f, 0.f};
        #pragma unroll
        for (int hf = 0; hf < 2; hf++) {
            mloc[hf] = fmaxf(mloc[hf], __shfl_xor_sync(0xffffffffu, mloc[hf], 1));
            mloc[hf] = fmaxf(mloc[hf], __shfl_xor_sync(0xffffffffu, mloc[hf], 2));
            float mn = fmaxf(m_[hf], mloc[hf]);
            corr[hf] = __expf(m_[hf] - mn);
            m_[hf] = mn;
        }
        #pragma unroll
        for (int nt = 0; nt < 4; nt++) {
            #pragma unroll
            for (int k4 = 0; k4 < 4; k4++) {
                const int hf = k4 >> 1;
                float p = __expf(c[nt][k4] - m_[hf]);
                c[nt][k4] = p;
                psum[hf] += p;
            }
        }
        #pragma unroll
        for (int hf = 0; hf < 2; hf++) {
            psum[hf] += __shfl_xor_sync(0xffffffffu, psum[hf], 1);
            psum[hf] += __shfl_xor_sync(0xffffffffu, psum[hf], 2);
            l_[hf] = l_[hf] * corr[hf] + psum[hf];
        }
        #pragma unroll
        for (int nt = 0; nt < 8; nt++) {
            co[nt][0] *= corr[0]; co[nt][1] *= corr[0];
            co[nt][2] *= corr[1]; co[nt][3] *= corr[1];
        }

        // ---- PV: P(16 x 32) x V(32 x 64) partial ----
        {
            const uint32_t stV = smb + oKV + (uint32_t)s * 36864u + 18432u;
            #pragma unroll
            for (int ktk = 0; ktk < 2; ktk++) {
                uint32_t pha[4], pla[4];
                #pragma unroll
                for (int sub = 0; sub < 2; sub++) {
                    #pragma unroll
                    for (int half2 = 0; half2 < 2; half2++) {
                        float x = c[2 * ktk + sub][half2 * 2];
                        float y = c[2 * ktk + sub][half2 * 2 + 1];
                        uint32_t hi, lo;
                        split2(x, y, hi, lo);
                        pha[half2 + sub * 2] = hi;
                        pla[half2 + sub * 2] = lo;
                    }
                }
                uint32_t vbh[8][2], vbl[8][2];
                #pragma unroll
                for (int pp = 0; pp < 4; pp++) {
                    uint32_t krow = (uint32_t)(wh * 32 + ktk * 16 +
                                   (lane & 7) + ((lane >> 3) & 1) * 8);
                    uint32_t ncol = (uint32_t)(pp * 16 + (lane >> 4) * 8);
                    uint32_t addr = stV + (krow * RSTR + ncol) * 2;
                    uint32_t t4[4];
                    ldmx4t(t4, addr);
                    vbh[pp * 2][0] = t4[0]; vbh[pp * 2][1] = t4[1];
                    vbh[pp * 2 + 1][0] = t4[2]; vbh[pp * 2 + 1][1] = t4[3];
                    ldmx4t(t4, addr + 9216u);
                    vbl[pp * 2][0] = t4[0]; vbl[pp * 2][1] = t4[1];
                    vbl[pp * 2 + 1][0] = t4[2]; vbl[pp * 2 + 1][1] = t4[3];
                }
                #pragma unroll
                for (int nt = 0; nt < 8; nt++) {
                    mma16816(co[nt], pha, vbh[nt]);
                    mma16816(co[nt], pha, vbl[nt]);
                    mma16816(co[nt], pla, vbh[nt]);
                }
            }
        }

        __syncthreads();   // all reads of KV stage s & Er slots done

        if (kt + 2 < 16) load_kv(kt + 2, s);
        if (kt + 3 < 16) load_er(kt + 3);
        CP_COMMIT();
    }

    // ---- merge the two k-half softmax states, write out ----
    if ((lane & 3) == 0) {
        #pragma unroll
        for (int hf = 0; hf < 2; hf++) {
            sM[wh * 64 + wp * 16 + row16 + hf * 8] = m_[hf];
            sL[wh * 64 + wp * 16 + row16 + hf * 8] = l_[hf];
        }
    }
    __syncthreads();
    float myc[2], inv[2];
    #pragma unroll
    for (int hf = 0; hf < 2; hf++) {
        const int rowi = wp * 16 + row16 + hf * 8;
        float mo = sM[(wh ^ 1) * 64 + rowi];
        float lo2 = sL[(wh ^ 1) * 64 + rowi];
        float mstar = fmaxf(m_[hf], mo);
        myc[hf] = __expf(m_[hf] - mstar);
        float otc = __expf(mo - mstar);
        inv[hf] = 1.0f / (l_[hf] * myc[hf] + lo2 * otc);
    }
    __syncthreads();
    float* sOut = (float*)(sm + oKV);
    if (wh == 1) {
        #pragma unroll
        for (int hf = 0; hf < 2; hf++) {
            const int row = wp * 16 + row16 + hf * 8;
            #pragma unroll
            for (int nt = 0; nt < 8; nt++) {
                const int col = nt * 8 + (lane & 3) * 2;
                *(float2*)&sOut[row * OSTR + col] =
                    make_float2(co[nt][hf * 2] * myc[hf],
                                co[nt][hf * 2 + 1] * myc[hf]);
            }
        }
    }
    __syncthreads();
    if (wh == 0) {
        #pragma unroll
        for (int hf = 0; hf < 2; hf++) {
            const int row = wp * 16 + row16 + hf * 8;
            const size_t ob = ((size_t)(b * Sq + q0 + row)) * Dm + h * HDm;
            #pragma unroll
            for (int nt = 0; nt < 8; nt++) {
                const int col = nt * 8 + (lane & 3) * 2;
                float2 pr = *(float2*)&sOut[row * OSTR + col];
                *(float2*)&out[ob + col] =
                    make_float2((co[nt][hf * 2] * myc[hf] + pr.x) * inv[hf],
                                (co[nt][hf * 2 + 1] * myc[hf] + pr.y) * inv[hf]);
            }
        }
    }
}

// ---------------- launch ----------------------------------------------------
extern "C" void kernel_launch(void* const* d_in, const int* in_sizes, int n_in,
                              void* d_out, int out_size)
{
    (void)in_sizes; (void)n_in; (void)out_size;
    const float* patches  = (const float*)d_in[0];
    const float* time_emb = (const float*)d_in[1];
    const float* Wqs = (const float*)d_in[2];
    const float* bqs = (const float*)d_in[3];
    const float* Wks = (const float*)d_in[4];
    const float* bks = (const float*)d_in[5];
    const float* Wvs = (const float*)d_in[6];
    const float* bvs = (const float*)d_in[7];
    const float* Wqt = (const float*)d_in[8];
    const float* bqt = (const float*)d_in[9];
    const float* Wkt = (const float*)d_in[10];
    const float* bkt = (const float*)d_in[11];
    const float* Wvt = (const float*)d_in[12];
    const float* bvt = (const float*)d_in[13];
    const float* Er  = (const float*)d_in[14];
    float* out = (float*)d_out;

    time_proj<<<Bb, 256>>>(time_emb, Wqt, bqt, Wkt, bkt, Wvt, bvt);
    prep_patches<<<(Bb * Sq * Dm / 4) / 256, 256>>>(patches);
    prep_er<<<(Sq * HDm / 4) / 256, 256>>>(Er);
    prep_wt<<<dim3(Dm / 32, Dm / 32, 3), 256>>>(Wqs, Wks, Wvs);

    const int qkv_smem = 3 * STAGE_B;  // 221184
    cudaFuncSetAttribute(qkv_mma, cudaFuncAttributeMaxDynamicSharedMemorySize, qkv_smem);
    qkv_mma<<<dim3(Dm / 128, (Bb * Sq) / 128, 3), 256, qkv_smem>>>(bqs, bks, bvs);

    cudaFuncSetAttribute(attn_mma, cudaFuncAttributeMaxDynamicSharedMemorySize, ATTN_SMEM);
    attn_mma<<<dim3(Sq / 64, Hh, Bb), 256, ATTN_SMEM>>>(out);
}

// round 7
// speedup vs baseline: 2.7246x; 1.2865x over previous
#include <cuda_runtime.h>
#include <cuda_bf16.h>
#include <cuda_fp16.h>
#include <cstdint>
#include <cstddef>

#define Sq 1024
#define Dm 768
#define Hh 12
#define HDm 64
#define Bb 8
#define Tt 384
#define SCALE_F 0.125f

// ---------------- scratch (device globals; no allocation allowed) ----------
__device__ float g_T[3][Bb][Dm];                       // time q/k/v vectors
__device__ __nv_bfloat16 g_Phi[(size_t)Bb * Sq * Dm];  // patches hi/lo (qkv in)
__device__ __nv_bfloat16 g_Plo[(size_t)Bb * Sq * Dm];
__device__ __nv_bfloat16 g_WThi[3][Dm][Dm];            // W^T hi/lo [z][n][k]
__device__ __nv_bfloat16 g_WTlo[3][Dm][Dm];
__device__ __half g_Q16[(size_t)Bb * Sq * Dm];         // qs+tq  (fp16)
__device__ __half g_K16[(size_t)Bb * Sq * Dm];         // ks+tk  (fp16)
__device__ __half g_QS16[(size_t)Bb * Sq * Dm];        // qs (no time, fp16)
__device__ __half g_Vh16[(size_t)Bb * Sq * Dm];        // vs+tv fp16 hi
__device__ __half g_Vl16[(size_t)Bb * Sq * Dm];        // vs+tv fp16 lo
__device__ __half g_Er16[Sq][HDm];

// ---------------- PTX helpers (baseline ISA: sm_80+) ------------------------
__device__ __forceinline__ uint32_t smem_u32(const void* p) {
    uint32_t a;
    asm("{ .reg .u64 t; cvta.to.shared.u64 t, %1; cvt.u32.u64 %0, t; }"
        : "=r"(a) : "l"(p));
    return a;
}
__device__ __forceinline__ void ldmx4(uint32_t* r, uint32_t addr) {
    asm volatile("ldmatrix.sync.aligned.m8n8.x4.shared.b16 {%0,%1,%2,%3}, [%4];"
                 : "=r"(r[0]), "=r"(r[1]), "=r"(r[2]), "=r"(r[3]) : "r"(addr));
}
__device__ __forceinline__ void ldmx4t(uint32_t* r, uint32_t addr) {
    asm volatile("ldmatrix.sync.aligned.m8n8.x4.trans.shared.b16 {%0,%1,%2,%3}, [%4];"
                 : "=r"(r[0]), "=r"(r[1]), "=r"(r[2]), "=r"(r[3]) : "r"(addr));
}
__device__ __forceinline__ void mma16816(float* c, const uint32_t* a, const uint32_t* b) {
    asm volatile(
        "mma.sync.aligned.m16n8k16.row.col.f32.bf16.bf16.f32 "
        "{%0,%1,%2,%3}, {%4,%5,%6,%7}, {%8,%9}, {%0,%1,%2,%3};"
        : "+f"(c[0]), "+f"(c[1]), "+f"(c[2]), "+f"(c[3])
        : "r"(a[0]), "r"(a[1]), "r"(a[2]), "r"(a[3]), "r"(b[0]), "r"(b[1]));
}
__device__ __forceinline__ void mma16816h(float* c, const uint32_t* a, const uint32_t* b) {
    asm volatile(
        "mma.sync.aligned.m16n8k16.row.col.f32.f16.f16.f32 "
        "{%0,%1,%2,%3}, {%4,%5,%6,%7}, {%8,%9}, {%0,%1,%2,%3};"
        : "+f"(c[0]), "+f"(c[1]), "+f"(c[2]), "+f"(c[3])
        : "r"(a[0]), "r"(a[1]), "r"(a[2]), "r"(a[3]), "r"(b[0]), "r"(b[1]));
}
#define CP16(dst, src) asm volatile("cp.async.cg.shared.global [%0], [%1], 16;" :: "r"(dst), "l"(src))
#define CP_COMMIT()    asm volatile("cp.async.commit_group;" ::: "memory")
#define CP_WAIT1()     asm volatile("cp.async.wait_group 1;" ::: "memory")
#define CP_WAIT0()     asm volatile("cp.async.wait_group 0;" ::: "memory")

#define KC 64
#define RSTR 72
#define TILE_B (128 * RSTR * 2)          // 18432 B per 128-row bf16 tile (qkv)
#define STAGE_B (4 * TILE_B)             // 73728 B
#define DSTR 132

__device__ __forceinline__ uint32_t packh2(float x, float y) {
    __half2 hh = __floats2half2_rn(x, y);
    return *(uint32_t*)&hh;
}

// ---------------- kernel 1: time projections ------------------------------
__global__ void __launch_bounds__(256) time_proj(
    const float* __restrict__ time_emb,
    const float* __restrict__ Wqt, const float* __restrict__ bqt,
    const float* __restrict__ Wkt, const float* __restrict__ bkt,
    const float* __restrict__ Wvt, const float* __restrict__ bvt)
{
    const int b = blockIdx.x;
    __shared__ float te[Tt];
    for (int i = threadIdx.x; i < Tt; i += blockDim.x)
        te[i] = time_emb[b * Tt + i];
    __syncthreads();
    for (int n = threadIdx.x; n < Dm; n += blockDim.x) {
        float aq = 0.f, ak = 0.f, av = 0.f;
        for (int t = 0; t < Tt; t++) {
            float x = te[t];
            aq += x * Wqt[t * Dm + n];
            ak += x * Wkt[t * Dm + n];
            av += x * Wvt[t * Dm + n];
        }
        g_T[0][b][n] = aq + bqt[n];
        g_T[1][b][n] = ak + bkt[n];
        g_T[2][b][n] = av + bvt[n];
    }
}

// ---------------- prep: fp32 -> bf16 hi/lo splits --------------------------
__device__ __forceinline__ void split4(float4 v,
    __nv_bfloat162& h0, __nv_bfloat162& h1, __nv_bfloat162& l0, __nv_bfloat162& l1)
{
    __nv_bfloat16 a = __float2bfloat16(v.x), b = __float2bfloat16(v.y);
    __nv_bfloat16 c = __float2bfloat16(v.z), d = __float2bfloat16(v.w);
    h0.x = a; h0.y = b; h1.x = c; h1.y = d;
    l0.x = __float2bfloat16(v.x - __bfloat162float(a));
    l0.y = __float2bfloat16(v.y - __bfloat162float(b));
    l1.x = __float2bfloat16(v.z - __bfloat162float(c));
    l1.y = __float2bfloat16(v.w - __bfloat162float(d));
}

__global__ void __launch_bounds__(256) prep_patches(const float* __restrict__ src)
{
    size_t i = (size_t)blockIdx.x * 256 + threadIdx.x;
    float4 v = ((const float4*)src)[i];
    __nv_bfloat162 h0, h1, l0, l1;
    split4(v, h0, h1, l0, l1);
    __nv_bfloat162* H = (__nv_bfloat162*)g_Phi;
    __nv_bfloat162* L = (__nv_bfloat162*)g_Plo;
    H[2 * i] = h0; H[2 * i + 1] = h1;
    L[2 * i] = l0; L[2 * i + 1] = l1;
}

__global__ void __launch_bounds__(256) prep_er(const float* __restrict__ src)
{
    size_t i = (size_t)blockIdx.x * 256 + threadIdx.x;   // i < Sq*HDm/4
    float4 v = ((const float4*)src)[i];
    uint32_t* E = (uint32_t*)&g_Er16[0][0];
    E[2 * i] = packh2(v.x, v.y);
    E[2 * i + 1] = packh2(v.z, v.w);
}

__global__ void __launch_bounds__(256) prep_wt(
    const float* __restrict__ Wq, const float* __restrict__ Wk,
    const float* __restrict__ Wv)
{
    const int z = blockIdx.z;
    const float* __restrict__ W = (z == 0) ? Wq : (z == 1 ? Wk : Wv);
    __shared__ float s[32][33];
    const int n0 = blockIdx.x * 32, k0 = blockIdx.y * 32;
    const int tx = threadIdx.x & 31, ty = threadIdx.x >> 5;
    #pragma unroll
    for (int i = 0; i < 4; i++)
        s[ty + 8 * i][tx] = W[(size_t)(k0 + ty + 8 * i) * Dm + n0 + tx];
    __syncthreads();
    #pragma unroll
    for (int i = 0; i < 4; i++) {
        int n = n0 + ty + 8 * i, k = k0 + tx;
        float v = s[tx][ty + 8 * i];
        __nv_bfloat16 h = __float2bfloat16(v);
        g_WThi[z][n][k] = h;
        g_WTlo[z][n][k] = __float2bfloat16(v - __bfloat162float(h));
    }
}

// ---------------- shared microkernel: one Kc=64 chunk of bf16x3 MMA --------
__device__ __forceinline__ void mma_chunk(uint32_t stage_base, int wm, int wn,
                                          int lane, float c[4][4][4])
{
    const uint32_t aRow = (uint32_t)(wm * 64 + (lane & 15));
    const uint32_t aColBase = (uint32_t)((lane >> 4) * 8);
    const uint32_t bRow = (uint32_t)(wn * 32 + ((lane >> 3) & 1) * 8 + (lane & 7));
    const uint32_t sAh = stage_base;
    const uint32_t sAl = stage_base + TILE_B;
    const uint32_t sBh = stage_base + 2 * TILE_B;
    const uint32_t sBl = stage_base + 3 * TILE_B;

    #pragma unroll
    for (int ks = 0; ks < 4; ks++) {
        const uint32_t kcol = (uint32_t)(ks * 16) + aColBase;
        uint32_t ah[4][4], al[4][4], bh[4][2], bl[4][2];
        #pragma unroll
        for (int mt = 0; mt < 4; mt++) {
            uint32_t off = ((aRow + mt * 16) * RSTR + kcol) * 2;
            ldmx4(ah[mt], sAh + off);
            ldmx4(al[mt], sAl + off);
        }
        #pragma unroll
        for (int nt2 = 0; nt2 < 2; nt2++) {
            uint32_t off = ((bRow + nt2 * 16) * RSTR + kcol) * 2;
            uint32_t t[4];
            ldmx4(t, sBh + off);
            bh[nt2 * 2][0] = t[0]; bh[nt2 * 2][1] = t[2];
            bh[nt2 * 2 + 1][0] = t[1]; bh[nt2 * 2 + 1][1] = t[3];
            ldmx4(t, sBl + off);
            bl[nt2 * 2][0] = t[0]; bl[nt2 * 2][1] = t[2];
            bl[nt2 * 2 + 1][0] = t[1]; bl[nt2 * 2 + 1][1] = t[3];
        }
        #pragma unroll
        for (int mt = 0; mt < 4; mt++)
            #pragma unroll
            for (int nt = 0; nt < 4; nt++) {
                mma16816(c[mt][nt], ah[mt], bh[nt]);
                mma16816(c[mt][nt], ah[mt], bl[nt]);
                mma16816(c[mt][nt], al[mt], bh[nt]);
            }
    }
}

// ---------------- kernel 2: QKV via mma.sync bf16x3 (3-stage pipeline) -----
__global__ void __launch_bounds__(256) qkv_mma(
    const float* __restrict__ bq, const float* __restrict__ bk,
    const float* __restrict__ bv)
{
    extern __shared__ char sm[];
    const uint32_t smb = smem_u32(sm);
    const int z = blockIdx.z;
    const int n0 = blockIdx.x * 128, m0 = blockIdx.y * 128;
    const int tid = threadIdx.x;
    const int warp = tid >> 5, lane = tid & 31;
    const int wm = warp & 1, wn = warp >> 1;

    const __nv_bfloat16* pAhi = g_Phi;
    const __nv_bfloat16* pAlo = g_Plo;
    const __nv_bfloat16* pBhi = &g_WThi[z][0][0];
    const __nv_bfloat16* pBlo = &g_WTlo[z][0][0];

    auto load_stage = [&](int chunk, int s) {
        const uint32_t st = smb + (uint32_t)s * STAGE_B;
        const int k0 = chunk * KC;
        #pragma unroll
        for (int it = 0; it < 4; it++) {
            int i = tid + it * 256;
            int r = i >> 3, cc = i & 7;
            uint32_t doff = (uint32_t)(r * RSTR + cc * 8) * 2;
            size_t aoff = (size_t)(m0 + r) * Dm + k0 + cc * 8;
            size_t boff = (size_t)(n0 + r) * Dm + k0 + cc * 8;
            CP16(st + doff, pAhi + aoff);
            CP16(st + TILE_B + doff, pAlo + aoff);
            CP16(st + 2 * TILE_B + doff, pBhi + boff);
            CP16(st + 3 * TILE_B + doff, pBlo + boff);
        }
        CP_COMMIT();
    };

    float c[4][4][4] = {};

    load_stage(0, 0);
    load_stage(1, 1);
    for (int ch = 0; ch < 12; ch++) {
        if (ch < 10) CP_WAIT1(); else CP_WAIT0();
        __syncthreads();
        if (ch + 2 < 12) load_stage(ch + 2, (ch + 2) % 3);
        mma_chunk(smb + (uint32_t)(ch % 3) * STAGE_B, wm, wn, lane, c);
    }

    const float* bias = (z == 0) ? bq : (z == 1 ? bk : bv);
    const int lrow = lane >> 2, lcol = (lane & 3) * 2;
    #pragma unroll
    for (int mt = 0; mt < 4; mt++) {
        #pragma unroll
        for (int nt = 0; nt < 4; nt++) {
            const int col = n0 + wn * 32 + nt * 8 + lcol;
            const float bx = bias[col], by = bias[col + 1];
            #pragma unroll
            for (int hf = 0; hf < 2; hf++) {
                const int row = m0 + wm * 64 + mt * 16 + lrow + hf * 8;
                const int b = row >> 10;
                const float v0 = c[mt][nt][hf * 2 + 0] + bx;
                const float v1 = c[mt][nt][hf * 2 + 1] + by;
                const float t0 = g_T[z][b][col];
                const float t1 = g_T[z][b][col + 1];
                const size_t o = (size_t)row * Dm + col;
                if (z == 0) {
                    *(uint32_t*)&g_Q16[o] = packh2(v0 + t0, v1 + t1);
                    *(uint32_t*)&g_QS16[o] = packh2(v0, v1);
                } else if (z == 1) {
                    *(uint32_t*)&g_K16[o] = packh2(v0 + t0, v1 + t1);
                } else {
                    const float f0 = v0 + t0, f1 = v1 + t1;
                    __half h0 = __float2half_rn(f0), h1 = __float2half_rn(f1);
                    __half2 hh; hh.x = h0; hh.y = h1;
                    __half2 ll;
                    ll.x = __float2half_rn(f0 - __half2float(h0));
                    ll.y = __float2half_rn(f1 - __half2float(h1));
                    *(__half2*)&g_Vh16[o] = hh;
                    *(__half2*)&g_Vl16[o] = ll;
                }
            }
        }
    }
}

// ---------------- kernel 3: fused flash attention + rel-bias (fp16) --------
// 256 threads (8 warps). Warp = wp (16 q rows) x wh (32-col k-half).
// Scores + D in 1-pass fp16 (exact products); PV = Ph*(Vh + Vl) 2-pass.
#define aQ    0u            /* 64x72 fp16 = 9216 */
#define aQS   9216u         /* 80x72 fp16 = 11520 */
#define aKV   20736u        /* stage: K16 | Vh | Vl each 9216 = 27648; x2 */
#define aEr   76032u        /* 256x72 fp16 = 36864 */
#define aD    112896u       /* 65x132 f32 = 34320 */
#define aRed  147216u       /* sM 128 f32 + sL 128 f32 */
#define ATTN_SMEM 148240
#define OSTR 68

__global__ void __launch_bounds__(256) attn_mma(float* __restrict__ out)
{
    extern __shared__ char sm[];
    const uint32_t smb = smem_u32(sm);
    const int q0 = blockIdx.x * 64;
    const int h = blockIdx.y, b = blockIdx.z;
    const int tid = threadIdx.x, warp = tid >> 5, lane = tid & 31;
    const int wp = warp & 3, wh = warp >> 2;
    float* Dw = (float*)(sm + aD);
    float* sM = (float*)(sm + aRed);
    float* sL = sM + 128;

    auto load_kv = [&](int kt, int s) {
        const uint32_t st = smb + aKV + (uint32_t)s * 27648u;
        const size_t krow0 = ((size_t)(b * Sq + kt * 64)) * Dm + h * HDm;
        #pragma unroll
        for (int it = 0; it < 2; it++) {
            int i = tid + it * 256;
            int r = i >> 3, cc = i & 7;
            uint32_t doff = (uint32_t)(r * RSTR + cc * 8) * 2;
            size_t src = krow0 + (size_t)r * Dm + cc * 8;
            CP16(st + doff, g_K16 + src);
            CP16(st + 9216u + doff, g_Vh16 + src);
            CP16(st + 18432u + doff, g_Vl16 + src);
        }
    };
    auto load_er = [&](int s) {
        const int estart = s * 64 - q0;
        #pragma unroll
        for (int it = 0; it < 2; it++) {
            int i = tid + it * 256;
            int r = i >> 3, cc = i & 7;
            int e = estart + r;
            int t = (e <= 0) ? (Sq - 1 + e) : (e - 2);
            if (t < 0) t = 0; if (t > Sq - 1) t = Sq - 1;
            int rbuf = (estart + r) & 255;
            uint32_t doff = (uint32_t)(rbuf * RSTR + cc * 8) * 2;
            CP16(smb + aEr + doff, &g_Er16[t][cc * 8]);
        }
    };
    auto do_dstrip = [&](int s) {
        const int base = s * 64 - q0;
        const uint32_t erow0 = (uint32_t)(base & 255);
        const int dcol0 = base & 127;
        const int par = warp & 1;
        uint32_t eb[4][2];
        const uint32_t nrow = erow0 +
            (uint32_t)((warp & 6) * 8 + ((lane >> 3) & 1) * 8 + (lane & 7));
        #pragma unroll
        for (int ks = 0; ks < 4; ks++) {
            uint32_t addr = smb + aEr +
                (nrow * RSTR + (uint32_t)(ks * 16 + (lane >> 4) * 8)) * 2;
            uint32_t t4[4];
            ldmx4(t4, addr);
            eb[ks][0] = t4[par]; eb[ks][1] = t4[2 + par];
        }
        #pragma unroll
        for (int mt = 0; mt < 5; mt++) {
            uint32_t sa[4][4];
            const uint32_t arow = (uint32_t)(mt * 16 + (lane & 15));
            #pragma unroll
            for (int ks = 0; ks < 4; ks++) {
                uint32_t addr = smb + aQS +
                    (arow * RSTR + (uint32_t)(ks * 16 + (lane >> 4) * 8)) * 2;
                ldmx4(sa[ks], addr);
            }
            float cc4[4] = {};
            #pragma unroll
            for (int ks = 0; ks < 4; ks++)
                mma16816h(cc4, sa[ks], eb[ks]);
            const int r0 = mt * 16 + (lane >> 2);
            const int colb = dcol0 + warp * 8 + (lane & 3) * 2;
            if (r0 <= 64)
                *(float2*)&Dw[r0 * DSTR + colb] = make_float2(cc4[0], cc4[1]);
            if (r0 + 8 <= 64)
                *(float2*)&Dw[(r0 + 8) * DSTR + colb] = make_float2(cc4[2], cc4[3]);
        }
    };

    // ---- prologue loads ----
    {
        const size_t qrow0 = ((size_t)(b * Sq + q0)) * Dm + h * HDm;
        #pragma unroll
        for (int it = 0; it < 2; it++) {
            int i = tid + it * 256;
            int r = i >> 3, cc = i & 7;
            uint32_t doff = (uint32_t)(r * RSTR + cc * 8) * 2;
            CP16(smb + aQ + doff, g_Q16 + qrow0 + (size_t)r * Dm + cc * 8);
        }
        #pragma unroll
        for (int it = 0; it < 3; it++) {
            int i = tid + it * 256;
            if (i < 640) {
                int r = i >> 3, cc = i & 7;
                int rr = q0 + r; if (rr > Sq - 1) rr = Sq - 1;
                uint32_t doff = (uint32_t)(r * RSTR + cc * 8) * 2;
                CP16(smb + aQS + doff,
                     g_QS16 + ((size_t)(b * Sq + rr)) * Dm + h * HDm + cc * 8);
            }
        }
        load_er(-1); load_er(0); load_er(1);
        load_kv(0, 0);
        CP_COMMIT();                 // G0
        load_kv(1, 1);
        load_er(2);
        CP_COMMIT();                 // G1
    }

    CP_WAIT1();
    __syncthreads();                 // G0 visible

    // ---- hoist Q fragments (loop-invariant) ----
    uint32_t qa[4][4];
    {
        const uint32_t arow = (uint32_t)(wp * 16 + (lane & 15));
        #pragma unroll
        for (int ks = 0; ks < 4; ks++) {
            uint32_t addr = smb + aQ +
                (arow * RSTR + (uint32_t)(ks * 16 + (lane >> 4) * 8)) * 2;
            ldmx4(qa[ks], addr);
        }
    }

    float m_[2] = {-1e30f, -1e30f}, l_[2] = {0.f, 0.f};
    float co[8][4] = {};
    const int row16 = (lane >> 2);

    for (int kt = 0; kt < 16; kt++) {
        const int s = kt & 1;
        const int d0 = kt * 64 - q0;
        if (kt > 0) { CP_WAIT1(); __syncthreads(); }

        // ---- D strips (incremental, fp16 1-pass) ----
        if (kt == 0) { do_dstrip(-1); do_dstrip(0); }
        else do_dstrip(kt);

        // ---- QK^T: fp16 1-pass, 16 q rows x 32 k cols per warp ----
        float c[4][4] = {};
        {
            const uint32_t stK = smb + aKV + (uint32_t)s * 27648u;
            #pragma unroll
            for (int ks = 0; ks < 4; ks++) {
                uint32_t bh[4][2];
                #pragma unroll
                for (int pp = 0; pp < 2; pp++) {
                    uint32_t nrow = (uint32_t)(wh * 32 + pp * 16 +
                                    ((lane >> 3) & 1) * 8 + (lane & 7));
                    uint32_t addr = stK +
                        (nrow * RSTR + (uint32_t)(ks * 16 + (lane >> 4) * 8)) * 2;
                    uint32_t t4[4];
                    ldmx4(t4, addr);
                    bh[pp * 2][0] = t4[0]; bh[pp * 2][1] = t4[2];
                    bh[pp * 2 + 1][0] = t4[1]; bh[pp * 2 + 1][1] = t4[3];
                }
                #pragma unroll
                for (int nt = 0; nt < 4; nt++)
                    mma16816h(c[nt], qa[ks], bh[nt]);
            }
        }

        __syncthreads();   // Dw strip visible

        // ---- bias gather + own-half online softmax ----
        float mloc[2] = {-1e30f, -1e30f};
        #pragma unroll
        for (int nt = 0; nt < 4; nt++) {
            #pragma unroll
            for (int e2 = 0; e2 < 2; e2++) {
                const int col = wh * 32 + nt * 8 + (lane & 3) * 2 + e2;
                #pragma unroll
                for (int hf = 0; hf < 2; hf++) {
                    const int q_loc = wp * 16 + row16 + hf * 8;
                    const int e = d0 + col - q_loc;
                    float bias = (e == 1) ? 0.f
                               : Dw[(q_loc + (e >= 2 ? 1 : 0)) * DSTR + (e & 127)];
                    float sv = (c[nt][hf * 2 + e2] + bias) * SCALE_F;
                    c[nt][hf * 2 + e2] = sv;
                    mloc[hf] = fmaxf(mloc[hf], sv);
                }
            }
        }
        float corr[2], psum[2] = {0.f, 0.f};
        #pragma unroll
        for (int hf = 0; hf < 2; hf++) {
            mloc[hf] = fmaxf(mloc[hf], __shfl_xor_sync(0xffffffffu, mloc[hf], 1));
            mloc[hf] = fmaxf(mloc[hf], __shfl_xor_sync(0xffffffffu, mloc[hf], 2));
            float mn = fmaxf(m_[hf], mloc[hf]);
            corr[hf] = __expf(m_[hf] - mn);
            m_[hf] = mn;
        }
        #pragma unroll
        for (int nt = 0; nt < 4; nt++) {
            #pragma unroll
            for (int k4 = 0; k4 < 4; k4++) {
                const int hf = k4 >> 1;
                float p = __expf(c[nt][k4] - m_[hf]);
                c[nt][k4] = p;
                psum[hf] += p;
            }
        }
        #pragma unroll
        for (int hf = 0; hf < 2; hf++) {
            psum[hf] += __shfl_xor_sync(0xffffffffu, psum[hf], 1);
            psum[hf] += __shfl_xor_sync(0xffffffffu, psum[hf], 2);
            l_[hf] = l_[hf] * corr[hf] + psum[hf];
        }
        #pragma unroll
        for (int nt = 0; nt < 8; nt++) {
            co[nt][0] *= corr[0]; co[nt][1] *= corr[0];
            co[nt][2] *= corr[1]; co[nt][3] *= corr[1];
        }

        // ---- PV: Ph(fp16) x (Vh + Vl) ----
        {
            const uint32_t stV = smb + aKV + (uint32_t)s * 27648u + 9216u;
            #pragma unroll
            for (int ktk = 0; ktk < 2; ktk++) {
                uint32_t pha[4];
                #pragma unroll
                for (int sub = 0; sub < 2; sub++)
                    #pragma unroll
                    for (int h2 = 0; h2 < 2; h2++)
                        pha[h2 + sub * 2] = packh2(c[2 * ktk + sub][h2 * 2],
                                                   c[2 * ktk + sub][h2 * 2 + 1]);
                uint32_t vbh[8][2], vbl[8][2];
                #pragma unroll
                for (int pp = 0; pp < 4; pp++) {
                    uint32_t krow = (uint32_t)(wh * 32 + ktk * 16 +
                                   (lane & 7) + ((lane >> 3) & 1) * 8);
                    uint32_t ncol = (uint32_t)(pp * 16 + (lane >> 4) * 8);
                    uint32_t addr = stV + (krow * RSTR + ncol) * 2;
                    uint32_t t4[4];
                    ldmx4t(t4, addr);
                    vbh[pp * 2][0] = t4[0]; vbh[pp * 2][1] = t4[1];
                    vbh[pp * 2 + 1][0] = t4[2]; vbh[pp * 2 + 1][1] = t4[3];
                    ldmx4t(t4, addr + 9216u);
                    vbl[pp * 2][0] = t4[0]; vbl[pp * 2][1] = t4[1];
                    vbl[pp * 2 + 1][0] = t4[2]; vbl[pp * 2 + 1][1] = t4[3];
                }
                #pragma unroll
                for (int nt = 0; nt < 8; nt++) {
                    mma16816h(co[nt], pha, vbh[nt]);
                    mma16816h(co[nt], pha, vbl[nt]);
                }
            }
        }

        __syncthreads();   // all reads of KV stage s & Er slots done

        if (kt + 2 < 16) load_kv(kt + 2, s);
        if (kt + 3 < 16) load_er(kt + 3);
        CP_COMMIT();
    }

    // ---- merge the two k-half softmax states, write out ----
    if ((lane & 3) == 0) {
        #pragma unroll
        for (int hf = 0; hf < 2; hf++) {
            sM[wh * 64 + wp * 16 + row16 + hf * 8] = m_[hf];
            sL[wh * 64 + wp * 16 + row16 + hf * 8] = l_[hf];
        }
    }
    __syncthreads();
    float myc[2], inv[2];
    #pragma unroll
    for (int hf = 0; hf < 2; hf++) {
        const int rowi = wp * 16 + row16 + hf * 8;
        float mo = sM[(wh ^ 1) * 64 + rowi];
        float lo2 = sL[(wh ^ 1) * 64 + rowi];
        float mstar = fmaxf(m_[hf], mo);
        myc[hf] = __expf(m_[hf] - mstar);
        float otc = __expf(mo - mstar);
        inv[hf] = 1.0f / (l_[hf] * myc[hf] + lo2 * otc);
    }
    __syncthreads();
    float* sOut = (float*)(sm + aKV);
    if (wh == 1) {
        #pragma unroll
        for (int hf = 0; hf < 2; hf++) {
            const int row = wp * 16 + row16 + hf * 8;
            #pragma unroll
            for (int nt = 0; nt < 8; nt++) {
                const int col = nt * 8 + (lane & 3) * 2;
                *(float2*)&sOut[row * OSTR + col] =
                    make_float2(co[nt][hf * 2] * myc[hf],
                                co[nt][hf * 2 + 1] * myc[hf]);
            }
        }
    }
    __syncthreads();
    if (wh == 0) {
        #pragma unroll
        for (int hf = 0; hf < 2; hf++) {
            const int row = wp * 16 + row16 + hf * 8;
            const size_t ob = ((size_t)(b * Sq + q0 + row)) * Dm + h * HDm;
            #pragma unroll
            for (int nt = 0; nt < 8; nt++) {
                const int col = nt * 8 + (lane & 3) * 2;
                float2 pr = *(float2*)&sOut[row * OSTR + col];
                *(float2*)&out[ob + col] =
                    make_float2((co[nt][hf * 2] * myc[hf] + pr.x) * inv[hf],
                                (co[nt][hf * 2 + 1] * myc[hf] + pr.y) * inv[hf]);
            }
        }
    }
}

// ---------------- launch ----------------------------------------------------
extern "C" void kernel_launch(void* const* d_in, const int* in_sizes, int n_in,
                              void* d_out, int out_size)
{
    (void)in_sizes; (void)n_in; (void)out_size;
    const float* patches  = (const float*)d_in[0];
    const float* time_emb = (const float*)d_in[1];
    const float* Wqs = (const float*)d_in[2];
    const float* bqs = (const float*)d_in[3];
    const float* Wks = (const float*)d_in[4];
    const float* bks = (const float*)d_in[5];
    const float* Wvs = (const float*)d_in[6];
    const float* bvs = (const float*)d_in[7];
    const float* Wqt = (const float*)d_in[8];
    const float* bqt = (const float*)d_in[9];
    const float* Wkt = (const float*)d_in[10];
    const float* bkt = (const float*)d_in[11];
    const float* Wvt = (const float*)d_in[12];
    const float* bvt = (const float*)d_in[13];
    const float* Er  = (const float*)d_in[14];
    float* out = (float*)d_out;

    time_proj<<<Bb, 256>>>(time_emb, Wqt, bqt, Wkt, bkt, Wvt, bvt);
    prep_patches<<<(Bb * Sq * Dm / 4) / 256, 256>>>(patches);
    prep_er<<<(Sq * HDm / 4) / 256, 256>>>(Er);
    prep_wt<<<dim3(Dm / 32, Dm / 32, 3), 256>>>(Wqs, Wks, Wvs);

    const int qkv_smem = 3 * STAGE_B;  // 221184
    cudaFuncSetAttribute(qkv_mma, cudaFuncAttributeMaxDynamicSharedMemorySize, qkv_smem);
    qkv_mma<<<dim3(Dm / 128, (Bb * Sq) / 128, 3), 256, qkv_smem>>>(bqs, bks, bvs);

    cudaFuncSetAttribute(attn_mma, cudaFuncAttributeMaxDynamicSharedMemorySize, ATTN_SMEM);
    attn_mma<<<dim3(Sq / 64, Hh, Bb), 256, ATTN_SMEM>>>(out);
}

// round 8
// speedup vs baseline: 3.0958x; 1.1363x over previous
#include <cuda_runtime.h>
#include <cuda_bf16.h>
#include <cuda_fp16.h>
#include <cstdint>
#include <cstddef>

#define Sq 1024
#define Dm 768
#define Hh 12
#define HDm 64
#define Bb 8
#define Tt 384
#define SCALE_F 0.125f

// ---------------- scratch (device globals; no allocation allowed) ----------
__device__ float g_T[3][Bb][Dm];                    // time q/k/v vectors
__device__ __half g_Ph16[(size_t)Bb * Sq * Dm];     // patches fp16 hi
__device__ __half g_Pl16[(size_t)Bb * Sq * Dm];     // patches fp16 lo
__device__ __half g_WT16[3][Dm][Dm];                // W^T fp16 [z][n][k]
__device__ __half g_Q16[(size_t)Bb * Sq * Dm];      // qs+tq  (fp16)
__device__ __half g_K16[(size_t)Bb * Sq * Dm];      // ks+tk  (fp16)
__device__ __half g_QS16[(size_t)Bb * Sq * Dm];     // qs (no time, fp16)
__device__ __half g_V16[(size_t)Bb * Sq * Dm];      // vs+tv  (fp16)
__device__ __half g_Er16[Sq][HDm];

// ---------------- PTX helpers (baseline ISA: sm_80+) ------------------------
__device__ __forceinline__ uint32_t smem_u32(const void* p) {
    uint32_t a;
    asm("{ .reg .u64 t; cvta.to.shared.u64 t, %1; cvt.u32.u64 %0, t; }"
        : "=r"(a) : "l"(p));
    return a;
}
__device__ __forceinline__ void ldmx4(uint32_t* r, uint32_t addr) {
    asm volatile("ldmatrix.sync.aligned.m8n8.x4.shared.b16 {%0,%1,%2,%3}, [%4];"
                 : "=r"(r[0]), "=r"(r[1]), "=r"(r[2]), "=r"(r[3]) : "r"(addr));
}
__device__ __forceinline__ void ldmx4t(uint32_t* r, uint32_t addr) {
    asm volatile("ldmatrix.sync.aligned.m8n8.x4.trans.shared.b16 {%0,%1,%2,%3}, [%4];"
                 : "=r"(r[0]), "=r"(r[1]), "=r"(r[2]), "=r"(r[3]) : "r"(addr));
}
__device__ __forceinline__ void mma16816h(float* c, const uint32_t* a, const uint32_t* b) {
    asm volatile(
        "mma.sync.aligned.m16n8k16.row.col.f32.f16.f16.f32 "
        "{%0,%1,%2,%3}, {%4,%5,%6,%7}, {%8,%9}, {%0,%1,%2,%3};"
        : "+f"(c[0]), "+f"(c[1]), "+f"(c[2]), "+f"(c[3])
        : "r"(a[0]), "r"(a[1]), "r"(a[2]), "r"(a[3]), "r"(b[0]), "r"(b[1]));
}
#define CP16(dst, src) asm volatile("cp.async.cg.shared.global [%0], [%1], 16;" :: "r"(dst), "l"(src))
#define CP_COMMIT()    asm volatile("cp.async.commit_group;" ::: "memory")
#define CP_WAIT1()     asm volatile("cp.async.wait_group 1;" ::: "memory")
#define CP_WAIT0()     asm volatile("cp.async.wait_group 0;" ::: "memory")

#define KC 64
#define RSTR 72
#define TILE_B (128 * RSTR * 2)          // 18432 B per 128-row fp16 tile
#define STAGE_B (3 * TILE_B)             // Ah, Al, B = 55296 B (qkv)
#define DSTR 132

__device__ __forceinline__ uint32_t packh2(float x, float y) {
    __half2 hh = __floats2half2_rn(x, y);
    return *(uint32_t*)&hh;
}

// ---------------- kernel 1: time projections ------------------------------
__global__ void __launch_bounds__(256) time_proj(
    const float* __restrict__ time_emb,
    const float* __restrict__ Wqt, const float* __restrict__ bqt,
    const float* __restrict__ Wkt, const float* __restrict__ bkt,
    const float* __restrict__ Wvt, const float* __restrict__ bvt)
{
    const int b = blockIdx.x;
    __shared__ float te[Tt];
    for (int i = threadIdx.x; i < Tt; i += blockDim.x)
        te[i] = time_emb[b * Tt + i];
    __syncthreads();
    for (int n = threadIdx.x; n < Dm; n += blockDim.x) {
        float aq = 0.f, ak = 0.f, av = 0.f;
        for (int t = 0; t < Tt; t++) {
            float x = te[t];
            aq += x * Wqt[t * Dm + n];
            ak += x * Wkt[t * Dm + n];
            av += x * Wvt[t * Dm + n];
        }
        g_T[0][b][n] = aq + bqt[n];
        g_T[1][b][n] = ak + bkt[n];
        g_T[2][b][n] = av + bvt[n];
    }
}

// ---------------- preps --------------------------------------------------
__global__ void __launch_bounds__(256) prep_patches(const float* __restrict__ src)
{
    size_t i = (size_t)blockIdx.x * 256 + threadIdx.x;
    float4 v = ((const float4*)src)[i];
    __half hx = __float2half_rn(v.x), hy = __float2half_rn(v.y);
    __half hz = __float2half_rn(v.z), hw = __float2half_rn(v.w);
    uint32_t* H = (uint32_t*)g_Ph16;
    uint32_t* L = (uint32_t*)g_Pl16;
    __half2 h0; h0.x = hx; h0.y = hy;
    __half2 h1; h1.x = hz; h1.y = hw;
    H[2 * i] = *(uint32_t*)&h0;
    H[2 * i + 1] = *(uint32_t*)&h1;
    L[2 * i] = packh2(v.x - __half2float(hx), v.y - __half2float(hy));
    L[2 * i + 1] = packh2(v.z - __half2float(hz), v.w - __half2float(hw));
}

__global__ void __launch_bounds__(256) prep_er(const float* __restrict__ src)
{
    size_t i = (size_t)blockIdx.x * 256 + threadIdx.x;   // i < Sq*HDm/4
    float4 v = ((const float4*)src)[i];
    uint32_t* E = (uint32_t*)&g_Er16[0][0];
    E[2 * i] = packh2(v.x, v.y);
    E[2 * i + 1] = packh2(v.z, v.w);
}

__global__ void __launch_bounds__(256) prep_wt(
    const float* __restrict__ Wq, const float* __restrict__ Wk,
    const float* __restrict__ Wv)
{
    const int z = blockIdx.z;
    const float* __restrict__ W = (z == 0) ? Wq : (z == 1 ? Wk : Wv);
    __shared__ float s[32][33];
    const int n0 = blockIdx.x * 32, k0 = blockIdx.y * 32;
    const int tx = threadIdx.x & 31, ty = threadIdx.x >> 5;
    #pragma unroll
    for (int i = 0; i < 4; i++)
        s[ty + 8 * i][tx] = W[(size_t)(k0 + ty + 8 * i) * Dm + n0 + tx];
    __syncthreads();
    #pragma unroll
    for (int i = 0; i < 4; i++) {
        int n = n0 + ty + 8 * i, k = k0 + tx;
        g_WT16[z][n][k] = __float2half_rn(s[tx][ty + 8 * i]);
    }
}

// ---------------- shared microkernel: one Kc=64 chunk of fp16x2 MMA --------
__device__ __forceinline__ void mma_chunk(uint32_t stage_base, int wm, int wn,
                                          int lane, float c[4][4][4])
{
    const uint32_t aRow = (uint32_t)(wm * 64 + (lane & 15));
    const uint32_t aColBase = (uint32_t)((lane >> 4) * 8);
    const uint32_t bRow = (uint32_t)(wn * 32 + ((lane >> 3) & 1) * 8 + (lane & 7));
    const uint32_t sAh = stage_base;
    const uint32_t sAl = stage_base + TILE_B;
    const uint32_t sB  = stage_base + 2 * TILE_B;

    #pragma unroll
    for (int ks = 0; ks < 4; ks++) {
        const uint32_t kcol = (uint32_t)(ks * 16) + aColBase;
        uint32_t ah[4][4], al[4][4], bb[4][2];
        #pragma unroll
        for (int mt = 0; mt < 4; mt++) {
            uint32_t off = ((aRow + mt * 16) * RSTR + kcol) * 2;
            ldmx4(ah[mt], sAh + off);
            ldmx4(al[mt], sAl + off);
        }
        #pragma unroll
        for (int nt2 = 0; nt2 < 2; nt2++) {
            uint32_t off = ((bRow + nt2 * 16) * RSTR + kcol) * 2;
            uint32_t t[4];
            ldmx4(t, sB + off);
            bb[nt2 * 2][0] = t[0]; bb[nt2 * 2][1] = t[2];
            bb[nt2 * 2 + 1][0] = t[1]; bb[nt2 * 2 + 1][1] = t[3];
        }
        #pragma unroll
        for (int mt = 0; mt < 4; mt++)
            #pragma unroll
            for (int nt = 0; nt < 4; nt++) {
                mma16816h(c[mt][nt], ah[mt], bb[nt]);
                mma16816h(c[mt][nt], al[mt], bb[nt]);
            }
    }
}

// ---------------- kernel 2: QKV via mma.sync fp16x2 (3-stage pipeline) -----
__global__ void __launch_bounds__(256) qkv_mma(
    const float* __restrict__ bq, const float* __restrict__ bk,
    const float* __restrict__ bv)
{
    extern __shared__ char sm[];
    const uint32_t smb = smem_u32(sm);
    const int z = blockIdx.z;
    const int n0 = blockIdx.x * 128, m0 = blockIdx.y * 128;
    const int tid = threadIdx.x;
    const int warp = tid >> 5, lane = tid & 31;
    const int wm = warp & 1, wn = warp >> 1;

    auto load_stage = [&](int chunk, int s) {
        const uint32_t st = smb + (uint32_t)s * STAGE_B;
        const int k0 = chunk * KC;
        #pragma unroll
        for (int it = 0; it < 4; it++) {
            int i = tid + it * 256;
            int r = i >> 3, cc = i & 7;
            uint32_t doff = (uint32_t)(r * RSTR + cc * 8) * 2;
            size_t aoff = (size_t)(m0 + r) * Dm + k0 + cc * 8;
            CP16(st + doff, g_Ph16 + aoff);
            CP16(st + TILE_B + doff, g_Pl16 + aoff);
            CP16(st + 2 * TILE_B + doff, &g_WT16[z][n0 + r][k0 + cc * 8]);
        }
        CP_COMMIT();
    };

    float c[4][4][4] = {};

    load_stage(0, 0);
    load_stage(1, 1);
    for (int ch = 0; ch < 12; ch++) {
        if (ch < 10) CP_WAIT1(); else CP_WAIT0();
        __syncthreads();
        if (ch + 2 < 12) load_stage(ch + 2, (ch + 2) % 3);
        mma_chunk(smb + (uint32_t)(ch % 3) * STAGE_B, wm, wn, lane, c);
    }

    const float* bias = (z == 0) ? bq : (z == 1 ? bk : bv);
    const int lrow = lane >> 2, lcol = (lane & 3) * 2;
    #pragma unroll
    for (int mt = 0; mt < 4; mt++) {
        #pragma unroll
        for (int nt = 0; nt < 4; nt++) {
            const int col = n0 + wn * 32 + nt * 8 + lcol;
            const float bx = bias[col], by = bias[col + 1];
            #pragma unroll
            for (int hf = 0; hf < 2; hf++) {
                const int row = m0 + wm * 64 + mt * 16 + lrow + hf * 8;
                const int b = row >> 10;
                const float v0 = c[mt][nt][hf * 2 + 0] + bx;
                const float v1 = c[mt][nt][hf * 2 + 1] + by;
                const float t0 = g_T[z][b][col];
                const float t1 = g_T[z][b][col + 1];
                const size_t o = (size_t)row * Dm + col;
                if (z == 0) {
                    *(uint32_t*)&g_Q16[o] = packh2(v0 + t0, v1 + t1);
                    *(uint32_t*)&g_QS16[o] = packh2(v0, v1);
                } else if (z == 1) {
                    *(uint32_t*)&g_K16[o] = packh2(v0 + t0, v1 + t1);
                } else {
                    *(uint32_t*)&g_V16[o] = packh2(v0 + t0, v1 + t1);
                }
            }
        }
    }
}

// ---------------- kernel 3: fused flash attention + rel-bias (fp16) --------
// 256 threads (8 warps). Warp = wp (16 q rows) x wh (32-col k-half).
// Scores + D in 1-pass fp16; PV 1-pass fp16.
#define aQ    0u            /* 64x72 fp16 = 9216 */
#define aQS   9216u         /* 80x72 fp16 = 11520 */
#define aKV   20736u        /* stage: K16 | V16 each 9216 = 18432; x2 */
#define aEr   57600u        /* 256x72 fp16 = 36864 */
#define aD    94464u        /* 65x132 f32 = 34320 */
#define aRed  128784u       /* sM 128 f32 + sL 128 f32 */
#define ATTN_SMEM 129808
#define OSTR 68

__global__ void __launch_bounds__(256) attn_mma(float* __restrict__ out)
{
    extern __shared__ char sm[];
    const uint32_t smb = smem_u32(sm);
    const int q0 = blockIdx.x * 64;
    const int h = blockIdx.y, b = blockIdx.z;
    const int tid = threadIdx.x, warp = tid >> 5, lane = tid & 31;
    const int wp = warp & 3, wh = warp >> 2;
    float* Dw = (float*)(sm + aD);
    float* sM = (float*)(sm + aRed);
    float* sL = sM + 128;

    auto load_kv = [&](int kt, int s) {
        const uint32_t st = smb + aKV + (uint32_t)s * 18432u;
        const size_t krow0 = ((size_t)(b * Sq + kt * 64)) * Dm + h * HDm;
        #pragma unroll
        for (int it = 0; it < 2; it++) {
            int i = tid + it * 256;
            int r = i >> 3, cc = i & 7;
            uint32_t doff = (uint32_t)(r * RSTR + cc * 8) * 2;
            size_t src = krow0 + (size_t)r * Dm + cc * 8;
            CP16(st + doff, g_K16 + src);
            CP16(st + 9216u + doff, g_V16 + src);
        }
    };
    auto load_er = [&](int s) {
        const int estart = s * 64 - q0;
        #pragma unroll
        for (int it = 0; it < 2; it++) {
            int i = tid + it * 256;
            int r = i >> 3, cc = i & 7;
            int e = estart + r;
            int t = (e <= 0) ? (Sq - 1 + e) : (e - 2);
            if (t < 0) t = 0; if (t > Sq - 1) t = Sq - 1;
            int rbuf = (estart + r) & 255;
            uint32_t doff = (uint32_t)(rbuf * RSTR + cc * 8) * 2;
            CP16(smb + aEr + doff, &g_Er16[t][cc * 8]);
        }
    };
    auto do_dstrip = [&](int s) {
        const int base = s * 64 - q0;
        const uint32_t erow0 = (uint32_t)(base & 255);
        const int dcol0 = base & 127;
        const int par = warp & 1;
        uint32_t eb[4][2];
        const uint32_t nrow = erow0 +
            (uint32_t)((warp & 6) * 8 + ((lane >> 3) & 1) * 8 + (lane & 7));
        #pragma unroll
        for (int ks = 0; ks < 4; ks++) {
            uint32_t addr = smb + aEr +
                (nrow * RSTR + (uint32_t)(ks * 16 + (lane >> 4) * 8)) * 2;
            uint32_t t4[4];
            ldmx4(t4, addr);
            eb[ks][0] = t4[par]; eb[ks][1] = t4[2 + par];
        }
        #pragma unroll
        for (int mt = 0; mt < 5; mt++) {
            uint32_t sa[4][4];
            const uint32_t arow = (uint32_t)(mt * 16 + (lane & 15));
            #pragma unroll
            for (int ks = 0; ks < 4; ks++) {
                uint32_t addr = smb + aQS +
                    (arow * RSTR + (uint32_t)(ks * 16 + (lane >> 4) * 8)) * 2;
                ldmx4(sa[ks], addr);
            }
            float cc4[4] = {};
            #pragma unroll
            for (int ks = 0; ks < 4; ks++)
                mma16816h(cc4, sa[ks], eb[ks]);
            const int r0 = mt * 16 + (lane >> 2);
            const int colb = dcol0 + warp * 8 + (lane & 3) * 2;
            if (r0 <= 64)
                *(float2*)&Dw[r0 * DSTR + colb] = make_float2(cc4[0], cc4[1]);
            if (r0 + 8 <= 64)
                *(float2*)&Dw[(r0 + 8) * DSTR + colb] = make_float2(cc4[2], cc4[3]);
        }
    };

    // ---- prologue loads ----
    {
        const size_t qrow0 = ((size_t)(b * Sq + q0)) * Dm + h * HDm;
        #pragma unroll
        for (int it = 0; it < 2; it++) {
            int i = tid + it * 256;
            int r = i >> 3, cc = i & 7;
            uint32_t doff = (uint32_t)(r * RSTR + cc * 8) * 2;
            CP16(smb + aQ + doff, g_Q16 + qrow0 + (size_t)r * Dm + cc * 8);
        }
        #pragma unroll
        for (int it = 0; it < 3; it++) {
            int i = tid + it * 256;
            if (i < 640) {
                int r = i >> 3, cc = i & 7;
                int rr = q0 + r; if (rr > Sq - 1) rr = Sq - 1;
                uint32_t doff = (uint32_t)(r * RSTR + cc * 8) * 2;
                CP16(smb + aQS + doff,
                     g_QS16 + ((size_t)(b * Sq + rr)) * Dm + h * HDm + cc * 8);
            }
        }
        load_er(-1); load_er(0); load_er(1);
        load_kv(0, 0);
        CP_COMMIT();                 // G0
        load_kv(1, 1);
        load_er(2);
        CP_COMMIT();                 // G1
    }

    CP_WAIT1();
    __syncthreads();                 // G0 visible

    // ---- hoist Q fragments (loop-invariant) ----
    uint32_t qa[4][4];
    {
        const uint32_t arow = (uint32_t)(wp * 16 + (lane & 15));
        #pragma unroll
        for (int ks = 0; ks < 4; ks++) {
            uint32_t addr = smb + aQ +
                (arow * RSTR + (uint32_t)(ks * 16 + (lane >> 4) * 8)) * 2;
            ldmx4(qa[ks], addr);
        }
    }

    float m_[2] = {-1e30f, -1e30f}, l_[2] = {0.f, 0.f};
    float co[8][4] = {};
    const int row16 = (lane >> 2);

    for (int kt = 0; kt < 16; kt++) {
        const int s = kt & 1;
        const int d0 = kt * 64 - q0;
        if (kt > 0) { CP_WAIT1(); __syncthreads(); }

        // ---- D strips (incremental, fp16 1-pass) ----
        if (kt == 0) { do_dstrip(-1); do_dstrip(0); }
        else do_dstrip(kt);

        // ---- QK^T: fp16 1-pass, 16 q rows x 32 k cols per warp ----
        float c[4][4] = {};
        {
            const uint32_t stK = smb + aKV + (uint32_t)s * 18432u;
            #pragma unroll
            for (int ks = 0; ks < 4; ks++) {
                uint32_t bh[4][2];
                #pragma unroll
                for (int pp = 0; pp < 2; pp++) {
                    uint32_t nrow = (uint32_t)(wh * 32 + pp * 16 +
                                    ((lane >> 3) & 1) * 8 + (lane & 7));
                    uint32_t addr = stK +
                        (nrow * RSTR + (uint32_t)(ks * 16 + (lane >> 4) * 8)) * 2;
                    uint32_t t4[4];
                    ldmx4(t4, addr);
                    bh[pp * 2][0] = t4[0]; bh[pp * 2][1] = t4[2];
                    bh[pp * 2 + 1][0] = t4[1]; bh[pp * 2 + 1][1] = t4[3];
                }
                #pragma unroll
                for (int nt = 0; nt < 4; nt++)
                    mma16816h(c[nt], qa[ks], bh[nt]);
            }
        }

        __syncthreads();   // Dw strip visible

        // ---- bias gather + own-half online softmax ----
        float mloc[2] = {-1e30f, -1e30f};
        #pragma unroll
        for (int nt = 0; nt < 4; nt++) {
            #pragma unroll
            for (int e2 = 0; e2 < 2; e2++) {
                const int col = wh * 32 + nt * 8 + (lane & 3) * 2 + e2;
                #pragma unroll
                for (int hf = 0; hf < 2; hf++) {
                    const int q_loc = wp * 16 + row16 + hf * 8;
                    const int e = d0 + col - q_loc;
                    float bias = (e == 1) ? 0.f
                               : Dw[(q_loc + (e >= 2 ? 1 : 0)) * DSTR + (e & 127)];
                    float sv = (c[nt][hf * 2 + e2] + bias) * SCALE_F;
                    c[nt][hf * 2 + e2] = sv;
                    mloc[hf] = fmaxf(mloc[hf], sv);
                }
            }
        }
        float corr[2], psum[2] = {0.f, 0.f};
        #pragma unroll
        for (int hf = 0; hf < 2; hf++) {
            mloc[hf] = fmaxf(mloc[hf], __shfl_xor_sync(0xffffffffu, mloc[hf], 1));
            mloc[hf] = fmaxf(mloc[hf], __shfl_xor_sync(0xffffffffu, mloc[hf], 2));
            float mn = fmaxf(m_[hf], mloc[hf]);
            corr[hf] = __expf(m_[hf] - mn);
            m_[hf] = mn;
        }
        #pragma unroll
        for (int nt = 0; nt < 4; nt++) {
            #pragma unroll
            for (int k4 = 0; k4 < 4; k4++) {
                const int hf = k4 >> 1;
                float p = __expf(c[nt][k4] - m_[hf]);
                c[nt][k4] = p;
                psum[hf] += p;
            }
        }
        #pragma unroll
        for (int hf = 0; hf < 2; hf++) {
            psum[hf] += __shfl_xor_sync(0xffffffffu, psum[hf], 1);
            psum[hf] += __shfl_xor_sync(0xffffffffu, psum[hf], 2);
            l_[hf] = l_[hf] * corr[hf] + psum[hf];
        }
        #pragma unroll
        for (int nt = 0; nt < 8; nt++) {
            co[nt][0] *= corr[0]; co[nt][1] *= corr[0];
            co[nt][2] *= corr[1]; co[nt][3] *= corr[1];
        }

        // ---- PV: Ph(fp16) x V(fp16), 1 pass ----
        {
            const uint32_t stV = smb + aKV + (uint32_t)s * 18432u + 9216u;
            #pragma unroll
            for (int ktk = 0; ktk < 2; ktk++) {
                uint32_t pha[4];
                #pragma unroll
                for (int sub = 0; sub < 2; sub++)
                    #pragma unroll
                    for (int h2 = 0; h2 < 2; h2++)
                        pha[h2 + sub * 2] = packh2(c[2 * ktk + sub][h2 * 2],
                                                   c[2 * ktk + sub][h2 * 2 + 1]);
                uint32_t vb[8][2];
                #pragma unroll
                for (int pp = 0; pp < 4; pp++) {
                    uint32_t krow = (uint32_t)(wh * 32 + ktk * 16 +
                                   (lane & 7) + ((lane >> 3) & 1) * 8);
                    uint32_t ncol = (uint32_t)(pp * 16 + (lane >> 4) * 8);
                    uint32_t addr = stV + (krow * RSTR + ncol) * 2;
                    uint32_t t4[4];
                    ldmx4t(t4, addr);
                    vb[pp * 2][0] = t4[0]; vb[pp * 2][1] = t4[1];
                    vb[pp * 2 + 1][0] = t4[2]; vb[pp * 2 + 1][1] = t4[3];
                }
                #pragma unroll
                for (int nt = 0; nt < 8; nt++)
                    mma16816h(co[nt], pha, vb[nt]);
            }
        }

        __syncthreads();   // all reads of KV stage s & Er slots done

        if (kt + 2 < 16) load_kv(kt + 2, s);
        if (kt + 3 < 16) load_er(kt + 3);
        CP_COMMIT();
    }

    // ---- merge the two k-half softmax states, write out ----
    if ((lane & 3) == 0) {
        #pragma unroll
        for (int hf = 0; hf < 2; hf++) {
            sM[wh * 64 + wp * 16 + row16 + hf * 8] = m_[hf];
            sL[wh * 64 + wp * 16 + row16 + hf * 8] = l_[hf];
        }
    }
    __syncthreads();
    float myc[2], inv[2];
    #pragma unroll
    for (int hf = 0; hf < 2; hf++) {
        const int rowi = wp * 16 + row16 + hf * 8;
        float mo = sM[(wh ^ 1) * 64 + rowi];
        float lo2 = sL[(wh ^ 1) * 64 + rowi];
        float mstar = fmaxf(m_[hf], mo);
        myc[hf] = __expf(m_[hf] - mstar);
        float otc = __expf(mo - mstar);
        inv[hf] = 1.0f / (l_[hf] * myc[hf] + lo2 * otc);
    }
    __syncthreads();
    float* sOut = (float*)(sm + aKV);
    if (wh == 1) {
        #pragma unroll
        for (int hf = 0; hf < 2; hf++) {
            const int row = wp * 16 + row16 + hf * 8;
            #pragma unroll
            for (int nt = 0; nt < 8; nt++) {
                const int col = nt * 8 + (lane & 3) * 2;
                *(float2*)&sOut[row * OSTR + col] =
                    make_float2(co[nt][hf * 2] * myc[hf],
                                co[nt][hf * 2 + 1] * myc[hf]);
            }
        }
    }
    __syncthreads();
    if (wh == 0) {
        #pragma unroll
        for (int hf = 0; hf < 2; hf++) {
            const int row = wp * 16 + row16 + hf * 8;
            const size_t ob = ((size_t)(b * Sq + q0 + row)) * Dm + h * HDm;
            #pragma unroll
            for (int nt = 0; nt < 8; nt++) {
                const int col = nt * 8 + (lane & 3) * 2;
                float2 pr = *(float2*)&sOut[row * OSTR + col];
                *(float2*)&out[ob + col] =
                    make_float2((co[nt][hf * 2] * myc[hf] + pr.x) * inv[hf],
                                (co[nt][hf * 2 + 1] * myc[hf] + pr.y) * inv[hf]);
            }
        }
    }
}

// ---------------- launch ----------------------------------------------------
extern "C" void kernel_launch(void* const* d_in, const int* in_sizes, int n_in,
                              void* d_out, int out_size)
{
    (void)in_sizes; (void)n_in; (void)out_size;
    const float* patches  = (const float*)d_in[0];
    const float* time_emb = (const float*)d_in[1];
    const float* Wqs = (const float*)d_in[2];
    const float* bqs = (const float*)d_in[3];
    const float* Wks = (const float*)d_in[4];
    const float* bks = (const float*)d_in[5];
    const float* Wvs = (const float*)d_in[6];
    const float* bvs = (const float*)d_in[7];
    const float* Wqt = (const float*)d_in[8];
    const float* bqt = (const float*)d_in[9];
    const float* Wkt = (const float*)d_in[10];
    const float* bkt = (const float*)d_in[11];
    const float* Wvt = (const float*)d_in[12];
    const float* bvt = (const float*)d_in[13];
    const float* Er  = (const float*)d_in[14];
    float* out = (float*)d_out;

    time_proj<<<Bb, 256>>>(time_emb, Wqt, bqt, Wkt, bkt, Wvt, bvt);
    prep_patches<<<(Bb * Sq * Dm / 4) / 256, 256>>>(patches);
    prep_er<<<(Sq * HDm / 4) / 256, 256>>>(Er);
    prep_wt<<<dim3(Dm / 32, Dm / 32, 3), 256>>>(Wqs, Wks, Wvs);

    const int qkv_smem = 3 * STAGE_B;  // 165888
    cudaFuncSetAttribute(qkv_mma, cudaFuncAttributeMaxDynamicSharedMemorySize, qkv_smem);
    qkv_mma<<<dim3(Dm / 128, (Bb * Sq) / 128, 3), 256, qkv_smem>>>(bqs, bks, bvs);

    cudaFuncSetAttribute(attn_mma, cudaFuncAttributeMaxDynamicSharedMemorySize, ATTN_SMEM);
    attn_mma<<<dim3(Sq / 64, Hh, Bb), 256, ATTN_SMEM>>>(out);
}

// round 9
// speedup vs baseline: 3.3515x; 1.0826x over previous
#include <cuda_runtime.h>
#include <cuda_bf16.h>
#include <cuda_fp16.h>
#include <cstdint>
#include <cstddef>

#define Sq 1024
#define Dm 768
#define Hh 12
#define HDm 64
#define Bb 8
#define Tt 384
#define SCALE_F 0.125f

// ---------------- scratch (device globals; no allocation allowed) ----------
__device__ float g_T[3][Bb][Dm];                    // time q/k/v vectors
__device__ __half g_Ph16[(size_t)Bb * Sq * Dm];     // patches fp16 hi
__device__ __half g_Pl16[(size_t)Bb * Sq * Dm];     // patches fp16 lo
__device__ __half g_WT16[3][Dm][Dm];                // W^T fp16 [z][n][k]
__device__ __half g_Q16[(size_t)Bb * Sq * Dm];      // qs+tq  (fp16)
__device__ __half g_K16[(size_t)Bb * Sq * Dm];      // ks+tk  (fp16)
__device__ __half g_QS16[(size_t)Bb * Sq * Dm];     // qs (no time, fp16)
__device__ __half g_V16[(size_t)Bb * Sq * Dm];      // vs+tv  (fp16)
__device__ __half g_Er16[Sq][HDm];

// ---------------- PTX helpers (baseline ISA: sm_80+) ------------------------
__device__ __forceinline__ uint32_t smem_u32(const void* p) {
    uint32_t a;
    asm("{ .reg .u64 t; cvta.to.shared.u64 t, %1; cvt.u32.u64 %0, t; }"
        : "=r"(a) : "l"(p));
    return a;
}
__device__ __forceinline__ void ldmx4(uint32_t* r, uint32_t addr) {
    asm volatile("ldmatrix.sync.aligned.m8n8.x4.shared.b16 {%0,%1,%2,%3}, [%4];"
                 : "=r"(r[0]), "=r"(r[1]), "=r"(r[2]), "=r"(r[3]) : "r"(addr));
}
__device__ __forceinline__ void ldmx4t(uint32_t* r, uint32_t addr) {
    asm volatile("ldmatrix.sync.aligned.m8n8.x4.trans.shared.b16 {%0,%1,%2,%3}, [%4];"
                 : "=r"(r[0]), "=r"(r[1]), "=r"(r[2]), "=r"(r[3]) : "r"(addr));
}
__device__ __forceinline__ void mma16816h(float* c, const uint32_t* a, const uint32_t* b) {
    asm volatile(
        "mma.sync.aligned.m16n8k16.row.col.f32.f16.f16.f32 "
        "{%0,%1,%2,%3}, {%4,%5,%6,%7}, {%8,%9}, {%0,%1,%2,%3};"
        : "+f"(c[0]), "+f"(c[1]), "+f"(c[2]), "+f"(c[3])
        : "r"(a[0]), "r"(a[1]), "r"(a[2]), "r"(a[3]), "r"(b[0]), "r"(b[1]));
}
#define CP16(dst, src) asm volatile("cp.async.cg.shared.global [%0], [%1], 16;" :: "r"(dst), "l"(src))
#define CP_COMMIT()    asm volatile("cp.async.commit_group;" ::: "memory")
#define CP_WAIT1()     asm volatile("cp.async.wait_group 1;" ::: "memory")
#define CP_WAIT0()     asm volatile("cp.async.wait_group 0;" ::: "memory")

#define KC 64
#define RSTR 72
#define TILE_B (128 * RSTR * 2)          // 18432 B per 128-row fp16 tile
#define STAGE_B (3 * TILE_B)             // Ah, Al, B = 55296 B (qkv)
#define DSTR 132

__device__ __forceinline__ uint32_t packh2(float x, float y) {
    __half2 hh = __floats2half2_rn(x, y);
    return *(uint32_t*)&hh;
}

// ---------------- kernel 1: time projections ------------------------------
__global__ void __launch_bounds__(256) time_proj(
    const float* __restrict__ time_emb,
    const float* __restrict__ Wqt, const float* __restrict__ bqt,
    const float* __restrict__ Wkt, const float* __restrict__ bkt,
    const float* __restrict__ Wvt, const float* __restrict__ bvt)
{
    const int b = blockIdx.x;
    __shared__ float te[Tt];
    for (int i = threadIdx.x; i < Tt; i += blockDim.x)
        te[i] = time_emb[b * Tt + i];
    __syncthreads();
    for (int n = threadIdx.x; n < Dm; n += blockDim.x) {
        float aq = 0.f, ak = 0.f, av = 0.f;
        for (int t = 0; t < Tt; t++) {
            float x = te[t];
            aq += x * Wqt[t * Dm + n];
            ak += x * Wkt[t * Dm + n];
            av += x * Wvt[t * Dm + n];
        }
        g_T[0][b][n] = aq + bqt[n];
        g_T[1][b][n] = ak + bkt[n];
        g_T[2][b][n] = av + bvt[n];
    }
}

// ---------------- preps --------------------------------------------------
__global__ void __launch_bounds__(256) prep_patches(const float* __restrict__ src)
{
    size_t i = (size_t)blockIdx.x * 256 + threadIdx.x;
    float4 v = ((const float4*)src)[i];
    __half hx = __float2half_rn(v.x), hy = __float2half_rn(v.y);
    __half hz = __float2half_rn(v.z), hw = __float2half_rn(v.w);
    uint32_t* H = (uint32_t*)g_Ph16;
    uint32_t* L = (uint32_t*)g_Pl16;
    __half2 h0; h0.x = hx; h0.y = hy;
    __half2 h1; h1.x = hz; h1.y = hw;
    H[2 * i] = *(uint32_t*)&h0;
    H[2 * i + 1] = *(uint32_t*)&h1;
    L[2 * i] = packh2(v.x - __half2float(hx), v.y - __half2float(hy));
    L[2 * i + 1] = packh2(v.z - __half2float(hz), v.w - __half2float(hw));
}

__global__ void __launch_bounds__(256) prep_er(const float* __restrict__ src)
{
    size_t i = (size_t)blockIdx.x * 256 + threadIdx.x;   // i < Sq*HDm/4
    float4 v = ((const float4*)src)[i];
    uint32_t* E = (uint32_t*)&g_Er16[0][0];
    E[2 * i] = packh2(v.x, v.y);
    E[2 * i + 1] = packh2(v.z, v.w);
}

__global__ void __launch_bounds__(256) prep_wt(
    const float* __restrict__ Wq, const float* __restrict__ Wk,
    const float* __restrict__ Wv)
{
    const int z = blockIdx.z;
    const float* __restrict__ W = (z == 0) ? Wq : (z == 1 ? Wk : Wv);
    __shared__ float s[32][33];
    const int n0 = blockIdx.x * 32, k0 = blockIdx.y * 32;
    const int tx = threadIdx.x & 31, ty = threadIdx.x >> 5;
    #pragma unroll
    for (int i = 0; i < 4; i++)
        s[ty + 8 * i][tx] = W[(size_t)(k0 + ty + 8 * i) * Dm + n0 + tx];
    __syncthreads();
    #pragma unroll
    for (int i = 0; i < 4; i++) {
        int n = n0 + ty + 8 * i, k = k0 + tx;
        g_WT16[z][n][k] = __float2half_rn(s[tx][ty + 8 * i]);
    }
}

// ---------------- shared microkernel: one Kc=64 chunk of fp16x2 MMA --------
__device__ __forceinline__ void mma_chunk(uint32_t stage_base, int wm, int wn,
                                          int lane, float c[4][4][4])
{
    const uint32_t aRow = (uint32_t)(wm * 64 + (lane & 15));
    const uint32_t aColBase = (uint32_t)((lane >> 4) * 8);
    const uint32_t bRow = (uint32_t)(wn * 32 + ((lane >> 3) & 1) * 8 + (lane & 7));
    const uint32_t sAh = stage_base;
    const uint32_t sAl = stage_base + TILE_B;
    const uint32_t sB  = stage_base + 2 * TILE_B;

    #pragma unroll
    for (int ks = 0; ks < 4; ks++) {
        const uint32_t kcol = (uint32_t)(ks * 16) + aColBase;
        uint32_t ah[4][4], al[4][4], bb[4][2];
        #pragma unroll
        for (int mt = 0; mt < 4; mt++) {
            uint32_t off = ((aRow + mt * 16) * RSTR + kcol) * 2;
            ldmx4(ah[mt], sAh + off);
            ldmx4(al[mt], sAl + off);
        }
        #pragma unroll
        for (int nt2 = 0; nt2 < 2; nt2++) {
            uint32_t off = ((bRow + nt2 * 16) * RSTR + kcol) * 2;
            uint32_t t[4];
            ldmx4(t, sB + off);
            bb[nt2 * 2][0] = t[0]; bb[nt2 * 2][1] = t[2];
            bb[nt2 * 2 + 1][0] = t[1]; bb[nt2 * 2 + 1][1] = t[3];
        }
        #pragma unroll
        for (int mt = 0; mt < 4; mt++)
            #pragma unroll
            for (int nt = 0; nt < 4; nt++) {
                mma16816h(c[mt][nt], ah[mt], bb[nt]);
                mma16816h(c[mt][nt], al[mt], bb[nt]);
            }
    }
}

// ---------------- kernel 2: QKV via mma.sync fp16x2 (2-stage, 2 CTA/SM) ----
__global__ void __launch_bounds__(256, 2) qkv_mma(
    const float* __restrict__ bq, const float* __restrict__ bk,
    const float* __restrict__ bv)
{
    extern __shared__ char sm[];
    const uint32_t smb = smem_u32(sm);
    const int z = blockIdx.z;
    const int n0 = blockIdx.x * 128, m0 = blockIdx.y * 128;
    const int tid = threadIdx.x;
    const int warp = tid >> 5, lane = tid & 31;
    const int wm = warp & 1, wn = warp >> 1;

    auto load_stage = [&](int chunk, int s) {
        const uint32_t st = smb + (uint32_t)s * STAGE_B;
        const int k0 = chunk * KC;
        #pragma unroll
        for (int it = 0; it < 4; it++) {
            int i = tid + it * 256;
            int r = i >> 3, cc = i & 7;
            uint32_t doff = (uint32_t)(r * RSTR + cc * 8) * 2;
            size_t aoff = (size_t)(m0 + r) * Dm + k0 + cc * 8;
            CP16(st + doff, g_Ph16 + aoff);
            CP16(st + TILE_B + doff, g_Pl16 + aoff);
            CP16(st + 2 * TILE_B + doff, &g_WT16[z][n0 + r][k0 + cc * 8]);
        }
        CP_COMMIT();
    };

    float c[4][4][4] = {};

    load_stage(0, 0);
    load_stage(1, 1);
    for (int ch = 0; ch < 12; ch++) {
        if (ch < 11) CP_WAIT1(); else CP_WAIT0();
        __syncthreads();
        mma_chunk(smb + (uint32_t)(ch & 1) * STAGE_B, wm, wn, lane, c);
        __syncthreads();
        if (ch + 2 < 12) load_stage(ch + 2, ch & 1);
    }

    const float* bias = (z == 0) ? bq : (z == 1 ? bk : bv);
    const int lrow = lane >> 2, lcol = (lane & 3) * 2;
    #pragma unroll
    for (int mt = 0; mt < 4; mt++) {
        #pragma unroll
        for (int nt = 0; nt < 4; nt++) {
            const int col = n0 + wn * 32 + nt * 8 + lcol;
            const float bx = bias[col], by = bias[col + 1];
            #pragma unroll
            for (int hf = 0; hf < 2; hf++) {
                const int row = m0 + wm * 64 + mt * 16 + lrow + hf * 8;
                const int b = row >> 10;
                const float v0 = c[mt][nt][hf * 2 + 0] + bx;
                const float v1 = c[mt][nt][hf * 2 + 1] + by;
                const float t0 = g_T[z][b][col];
                const float t1 = g_T[z][b][col + 1];
                const size_t o = (size_t)row * Dm + col;
                if (z == 0) {
                    *(uint32_t*)&g_Q16[o] = packh2(v0 + t0, v1 + t1);
                    *(uint32_t*)&g_QS16[o] = packh2(v0, v1);
                } else if (z == 1) {
                    *(uint32_t*)&g_K16[o] = packh2(v0 + t0, v1 + t1);
                } else {
                    *(uint32_t*)&g_V16[o] = packh2(v0 + t0, v1 + t1);
                }
            }
        }
    }
}

// ---------------- kernel 3: fused flash attention + rel-bias (fp16) --------
// 256 threads (8 warps), 2 CTAs/SM. Warp = wp (16 q rows) x wh (32-col k-half).
// Er ring: 3 strips of 64 rows (slot = (s+3)%3). Dw stored fp16.
#define aQ    0u            /* 64x72 fp16 = 9216 */
#define aQS   9216u         /* 80x72 fp16 = 11520 */
#define aKV   20736u        /* stage: K16 | V16 each 9216 = 18432; x2 */
#define aEr   57600u        /* 192x72 fp16 = 27648 */
#define aD    85248u        /* 65x132 fp16 = 17160 */
#define aRed  102408u       /* sM 128 f32 + sL 128 f32 */
#define ATTN_SMEM 103432
#define OSTR 68

__global__ void __launch_bounds__(256, 2) attn_mma(float* __restrict__ out)
{
    extern __shared__ char sm[];
    const uint32_t smb = smem_u32(sm);
    const int q0 = blockIdx.x * 64;
    const int h = blockIdx.y, b = blockIdx.z;
    const int tid = threadIdx.x, warp = tid >> 5, lane = tid & 31;
    const int wp = warp & 3, wh = warp >> 2;
    __half* Dw = (__half*)(sm + aD);
    float* sM = (float*)(sm + aRed);
    float* sL = sM + 128;

    auto load_kv = [&](int kt, int s) {
        const uint32_t st = smb + aKV + (uint32_t)s * 18432u;
        const size_t krow0 = ((size_t)(b * Sq + kt * 64)) * Dm + h * HDm;
        #pragma unroll
        for (int it = 0; it < 2; it++) {
            int i = tid + it * 256;
            int r = i >> 3, cc = i & 7;
            uint32_t doff = (uint32_t)(r * RSTR + cc * 8) * 2;
            size_t src = krow0 + (size_t)r * Dm + cc * 8;
            CP16(st + doff, g_K16 + src);
            CP16(st + 9216u + doff, g_V16 + src);
        }
    };
    auto load_er = [&](int s) {
        const int estart = s * 64 - q0;
        const int slot = ((s + 3) % 3) * 64;
        #pragma unroll
        for (int it = 0; it < 2; it++) {
            int i = tid + it * 256;
            int r = i >> 3, cc = i & 7;
            int e = estart + r;
            int t = (e <= 0) ? (Sq - 1 + e) : (e - 2);
            if (t < 0) t = 0; if (t > Sq - 1) t = Sq - 1;
            uint32_t doff = (uint32_t)((slot + r) * RSTR + cc * 8) * 2;
            CP16(smb + aEr + doff, &g_Er16[t][cc * 8]);
        }
    };
    auto do_dstrip = [&](int s) {
        const int base = s * 64 - q0;
        const uint32_t erow0 = (uint32_t)(((s + 3) % 3) * 64);
        const int dcol0 = base & 127;
        const int par = warp & 1;
        uint32_t eb[4][2];
        const uint32_t nrow = erow0 +
            (uint32_t)((warp & 6) * 8 + ((lane >> 3) & 1) * 8 + (lane & 7));
        #pragma unroll
        for (int ks = 0; ks < 4; ks++) {
            uint32_t addr = smb + aEr +
                (nrow * RSTR + (uint32_t)(ks * 16 + (lane >> 4) * 8)) * 2;
            uint32_t t4[4];
            ldmx4(t4, addr);
            eb[ks][0] = t4[par]; eb[ks][1] = t4[2 + par];
        }
        #pragma unroll
        for (int mt = 0; mt < 5; mt++) {
            uint32_t sa[4][4];
            const uint32_t arow = (uint32_t)(mt * 16 + (lane & 15));
            #pragma unroll
            for (int ks = 0; ks < 4; ks++) {
                uint32_t addr = smb + aQS +
                    (arow * RSTR + (uint32_t)(ks * 16 + (lane >> 4) * 8)) * 2;
                ldmx4(sa[ks], addr);
            }
            float cc4[4] = {};
            #pragma unroll
            for (int ks = 0; ks < 4; ks++)
                mma16816h(cc4, sa[ks], eb[ks]);
            const int r0 = mt * 16 + (lane >> 2);
            const int colb = dcol0 + warp * 8 + (lane & 3) * 2;
            if (r0 <= 64)
                *(uint32_t*)&Dw[r0 * DSTR + colb] = packh2(cc4[0], cc4[1]);
            if (r0 + 8 <= 64)
                *(uint32_t*)&Dw[(r0 + 8) * DSTR + colb] = packh2(cc4[2], cc4[3]);
        }
    };

    // ---- prologue loads ----
    {
        const size_t qrow0 = ((size_t)(b * Sq + q0)) * Dm + h * HDm;
        #pragma unroll
        for (int it = 0; it < 2; it++) {
            int i = tid + it * 256;
            int r = i >> 3, cc = i & 7;
            uint32_t doff = (uint32_t)(r * RSTR + cc * 8) * 2;
            CP16(smb + aQ + doff, g_Q16 + qrow0 + (size_t)r * Dm + cc * 8);
        }
        #pragma unroll
        for (int it = 0; it < 3; it++) {
            int i = tid + it * 256;
            if (i < 640) {
                int r = i >> 3, cc = i & 7;
                int rr = q0 + r; if (rr > Sq - 1) rr = Sq - 1;
                uint32_t doff = (uint32_t)(r * RSTR + cc * 8) * 2;
                CP16(smb + aQS + doff,
                     g_QS16 + ((size_t)(b * Sq + rr)) * Dm + h * HDm + cc * 8);
            }
        }
        load_er(-1); load_er(0); load_er(1);
        load_kv(0, 0);
        CP_COMMIT();                 // G0
        load_kv(1, 1);
        CP_COMMIT();                 // G1
    }

    CP_WAIT1();
    __syncthreads();                 // G0 visible

    // ---- hoist Q fragments (loop-invariant) ----
    uint32_t qa[4][4];
    {
        const uint32_t arow = (uint32_t)(wp * 16 + (lane & 15));
        #pragma unroll
        for (int ks = 0; ks < 4; ks++) {
            uint32_t addr = smb + aQ +
                (arow * RSTR + (uint32_t)(ks * 16 + (lane >> 4) * 8)) * 2;
            ldmx4(qa[ks], addr);
        }
    }

    float m_[2] = {-1e30f, -1e30f}, l_[2] = {0.f, 0.f};
    float co[8][4] = {};
    const int row16 = (lane >> 2);

    for (int kt = 0; kt < 16; kt++) {
        const int s = kt & 1;
        const int d0 = kt * 64 - q0;
        if (kt > 0) { CP_WAIT1(); __syncthreads(); }

        // ---- D strips (incremental, fp16 1-pass) ----
        if (kt == 0) { do_dstrip(-1); do_dstrip(0); }
        else do_dstrip(kt);

        // ---- QK^T: fp16 1-pass, 16 q rows x 32 k cols per warp ----
        float c[4][4] = {};
        {
            const uint32_t stK = smb + aKV + (uint32_t)s * 18432u;
            #pragma unroll
            for (int ks = 0; ks < 4; ks++) {
                uint32_t bh[4][2];
                #pragma unroll
                for (int pp = 0; pp < 2; pp++) {
                    uint32_t nrow = (uint32_t)(wh * 32 + pp * 16 +
                                    ((lane >> 3) & 1) * 8 + (lane & 7));
                    uint32_t addr = stK +
                        (nrow * RSTR + (uint32_t)(ks * 16 + (lane >> 4) * 8)) * 2;
                    uint32_t t4[4];
                    ldmx4(t4, addr);
                    bh[pp * 2][0] = t4[0]; bh[pp * 2][1] = t4[2];
                    bh[pp * 2 + 1][0] = t4[1]; bh[pp * 2 + 1][1] = t4[3];
                }
                #pragma unroll
                for (int nt = 0; nt < 4; nt++)
                    mma16816h(c[nt], qa[ks], bh[nt]);
            }
        }

        __syncthreads();   // Dw strip visible

        // ---- bias gather + own-half online softmax ----
        float mloc[2] = {-1e30f, -1e30f};
        #pragma unroll
        for (int nt = 0; nt < 4; nt++) {
            #pragma unroll
            for (int e2 = 0; e2 < 2; e2++) {
                const int col = wh * 32 + nt * 8 + (lane & 3) * 2 + e2;
                #pragma unroll
                for (int hf = 0; hf < 2; hf++) {
                    const int q_loc = wp * 16 + row16 + hf * 8;
                    const int e = d0 + col - q_loc;
                    float bias = (e == 1) ? 0.f
                        : __half2float(Dw[(q_loc + (e >= 2 ? 1 : 0)) * DSTR + (e & 127)]);
                    float sv = (c[nt][hf * 2 + e2] + bias) * SCALE_F;
                    c[nt][hf * 2 + e2] = sv;
                    mloc[hf] = fmaxf(mloc[hf], sv);
                }
            }
        }
        float corr[2], psum[2] = {0.f, 0.f};
        #pragma unroll
        for (int hf = 0; hf < 2; hf++) {
            mloc[hf] = fmaxf(mloc[hf], __shfl_xor_sync(0xffffffffu, mloc[hf], 1));
            mloc[hf] = fmaxf(mloc[hf], __shfl_xor_sync(0xffffffffu, mloc[hf], 2));
            float mn = fmaxf(m_[hf], mloc[hf]);
            corr[hf] = __expf(m_[hf] - mn);
            m_[hf] = mn;
        }
        #pragma unroll
        for (int nt = 0; nt < 4; nt++) {
            #pragma unroll
            for (int k4 = 0; k4 < 4; k4++) {
                const int hf = k4 >> 1;
                float p = __expf(c[nt][k4] - m_[hf]);
                c[nt][k4] = p;
                psum[hf] += p;
            }
        }
        #pragma unroll
        for (int hf = 0; hf < 2; hf++) {
            psum[hf] += __shfl_xor_sync(0xffffffffu, psum[hf], 1);
            psum[hf] += __shfl_xor_sync(0xffffffffu, psum[hf], 2);
            l_[hf] = l_[hf] * corr[hf] + psum[hf];
        }
        #pragma unroll
        for (int nt = 0; nt < 8; nt++) {
            co[nt][0] *= corr[0]; co[nt][1] *= corr[0];
            co[nt][2] *= corr[1]; co[nt][3] *= corr[1];
        }

        // ---- PV: Ph(fp16) x V(fp16), 1 pass ----
        {
            const uint32_t stV = smb + aKV + (uint32_t)s * 18432u + 9216u;
            #pragma unroll
            for (int ktk = 0; ktk < 2; ktk++) {
                uint32_t pha[4];
                #pragma unroll
                for (int sub = 0; sub < 2; sub++)
                    #pragma unroll
                    for (int h2 = 0; h2 < 2; h2++)
                        pha[h2 + sub * 2] = packh2(c[2 * ktk + sub][h2 * 2],
                                                   c[2 * ktk + sub][h2 * 2 + 1]);
                uint32_t vb[8][2];
                #pragma unroll
                for (int pp = 0; pp < 4; pp++) {
                    uint32_t krow = (uint32_t)(wh * 32 + ktk * 16 +
                                   (lane & 7) + ((lane >> 3) & 1) * 8);
                    uint32_t ncol = (uint32_t)(pp * 16 + (lane >> 4) * 8);
                    uint32_t addr = stV + (krow * RSTR + ncol) * 2;
                    uint32_t t4[4];
                    ldmx4t(t4, addr);
                    vb[pp * 2][0] = t4[0]; vb[pp * 2][1] = t4[1];
                    vb[pp * 2 + 1][0] = t4[2]; vb[pp * 2 + 1][1] = t4[3];
                }
                #pragma unroll
                for (int nt = 0; nt < 8; nt++)
                    mma16816h(co[nt], pha, vb[nt]);
            }
        }

        __syncthreads();   // all reads of KV stage s & Er slots done

        if (kt + 2 < 16) load_kv(kt + 2, s);
        if (kt + 2 <= 15) load_er(kt + 2);
        CP_COMMIT();
    }

    // ---- merge the two k-half softmax states, write out ----
    if ((lane & 3) == 0) {
        #pragma unroll
        for (int hf = 0; hf < 2; hf++) {
            sM[wh * 64 + wp * 16 + row16 + hf * 8] = m_[hf];
            sL[wh * 64 + wp * 16 + row16 + hf * 8] = l_[hf];
        }
    }
    __syncthreads();
    float myc[2], inv[2];
    #pragma unroll
    for (int hf = 0; hf < 2; hf++) {
        const int rowi = wp * 16 + row16 + hf * 8;
        float mo = sM[(wh ^ 1) * 64 + rowi];
        float lo2 = sL[(wh ^ 1) * 64 + rowi];
        float mstar = fmaxf(m_[hf], mo);
        myc[hf] = __expf(m_[hf] - mstar);
        float otc = __expf(mo - mstar);
        inv[hf] = 1.0f / (l_[hf] * myc[hf] + lo2 * otc);
    }
    __syncthreads();
    float* sOut = (float*)(sm + aKV);
    if (wh == 1) {
        #pragma unroll
        for (int hf = 0; hf < 2; hf++) {
            const int row = wp * 16 + row16 + hf * 8;
            #pragma unroll
            for (int nt = 0; nt < 8; nt++) {
                const int col = nt * 8 + (lane & 3) * 2;
                *(float2*)&sOut[row * OSTR + col] =
                    make_float2(co[nt][hf * 2] * myc[hf],
                                co[nt][hf * 2 + 1] * myc[hf]);
            }
        }
    }
    __syncthreads();
    if (wh == 0) {
        #pragma unroll
        for (int hf = 0; hf < 2; hf++) {
            const int row = wp * 16 + row16 + hf * 8;
            const size_t ob = ((size_t)(b * Sq + q0 + row)) * Dm + h * HDm;
            #pragma unroll
            for (int nt = 0; nt < 8; nt++) {
                const int col = nt * 8 + (lane & 3) * 2;
                float2 pr = *(float2*)&sOut[row * OSTR + col];
                *(float2*)&out[ob + col] =
                    make_float2((co[nt][hf * 2] * myc[hf] + pr.x) * inv[hf],
                                (co[nt][hf * 2 + 1] * myc[hf] + pr.y) * inv[hf]);
            }
        }
    }
}

// ---------------- launch ----------------------------------------------------
extern "C" void kernel_launch(void* const* d_in, const int* in_sizes, int n_in,
                              void* d_out, int out_size)
{
    (void)in_sizes; (void)n_in; (void)out_size;
    const float* patches  = (const float*)d_in[0];
    const float* time_emb = (const float*)d_in[1];
    const float* Wqs = (const float*)d_in[2];
    const float* bqs = (const float*)d_in[3];
    const float* Wks = (const float*)d_in[4];
    const float* bks = (const float*)d_in[5];
    const float* Wvs = (const float*)d_in[6];
    const float* bvs = (const float*)d_in[7];
    const float* Wqt = (const float*)d_in[8];
    const float* bqt = (const float*)d_in[9];
    const float* Wkt = (const float*)d_in[10];
    const float* bkt = (const float*)d_in[11];
    const float* Wvt = (const float*)d_in[12];
    const float* bvt = (const float*)d_in[13];
    const float* Er  = (const float*)d_in[14];
    float* out = (float*)d_out;

    time_proj<<<Bb, 256>>>(time_emb, Wqt, bqt, Wkt, bkt, Wvt, bvt);
    prep_patches<<<(Bb * Sq * Dm / 4) / 256, 256>>>(patches);
    prep_er<<<(Sq * HDm / 4) / 256, 256>>>(Er);
    prep_wt<<<dim3(Dm / 32, Dm / 32, 3), 256>>>(Wqs, Wks, Wvs);

    const int qkv_smem = 2 * STAGE_B;  // 110592 -> 2 CTAs/SM
    cudaFuncSetAttribute(qkv_mma, cudaFuncAttributeMaxDynamicSharedMemorySize, qkv_smem);
    qkv_mma<<<dim3(Dm / 128, (Bb * Sq) / 128, 3), 256, qkv_smem>>>(bqs, bks, bvs);

    cudaFuncSetAttribute(attn_mma, cudaFuncAttributeMaxDynamicSharedMemorySize, ATTN_SMEM);
    attn_mma<<<dim3(Sq / 64, Hh, Bb), 256, ATTN_SMEM>>>(out);
}

// round 10
// speedup vs baseline: 3.7258x; 1.1117x over previous
#include <cuda_runtime.h>
#include <cuda_bf16.h>
#include <cuda_fp16.h>
#include <cstdint>
#include <cstddef>

#define Sq 1024
#define Dm 768
#define Hh 12
#define HDm 64
#define Bb 8
#define Tt 384
#define SCALE_F 0.125f

// ---------------- scratch (device globals; no allocation allowed) ----------
__device__ float g_T[3][Bb][Dm];                    // time q/k/v vectors
__device__ __half g_P16[(size_t)Bb * Sq * Dm];      // patches fp16
__device__ __half g_WT16[3][Dm][Dm];                // W^T fp16 [z][n][k]
__device__ __half g_Q16[(size_t)Bb * Sq * Dm];      // qs+tq  (fp16)
__device__ __half g_K16[(size_t)Bb * Sq * Dm];      // ks+tk  (fp16)
__device__ __half g_QS16[(size_t)Bb * Sq * Dm];     // qs (no time, fp16)
__device__ __half g_V16[(size_t)Bb * Sq * Dm];      // vs+tv  (fp16)
__device__ __half g_Er16[Sq][HDm];

// ---------------- PTX helpers (baseline ISA: sm_80+) ------------------------
__device__ __forceinline__ uint32_t smem_u32(const void* p) {
    uint32_t a;
    asm("{ .reg .u64 t; cvta.to.shared.u64 t, %1; cvt.u32.u64 %0, t; }"
        : "=r"(a) : "l"(p));
    return a;
}
__device__ __forceinline__ void ldmx4(uint32_t* r, uint32_t addr) {
    asm volatile("ldmatrix.sync.aligned.m8n8.x4.shared.b16 {%0,%1,%2,%3}, [%4];"
                 : "=r"(r[0]), "=r"(r[1]), "=r"(r[2]), "=r"(r[3]) : "r"(addr));
}
__device__ __forceinline__ void ldmx4t(uint32_t* r, uint32_t addr) {
    asm volatile("ldmatrix.sync.aligned.m8n8.x4.trans.shared.b16 {%0,%1,%2,%3}, [%4];"
                 : "=r"(r[0]), "=r"(r[1]), "=r"(r[2]), "=r"(r[3]) : "r"(addr));
}
__device__ __forceinline__ void mma16816h(float* c, const uint32_t* a, const uint32_t* b) {
    asm volatile(
        "mma.sync.aligned.m16n8k16.row.col.f32.f16.f16.f32 "
        "{%0,%1,%2,%3}, {%4,%5,%6,%7}, {%8,%9}, {%0,%1,%2,%3};"
        : "+f"(c[0]), "+f"(c[1]), "+f"(c[2]), "+f"(c[3])
        : "r"(a[0]), "r"(a[1]), "r"(a[2]), "r"(a[3]), "r"(b[0]), "r"(b[1]));
}
#define CP16(dst, src) asm volatile("cp.async.cg.shared.global [%0], [%1], 16;" :: "r"(dst), "l"(src))
#define CP_COMMIT()    asm volatile("cp.async.commit_group;" ::: "memory")
#define CP_WAIT1()     asm volatile("cp.async.wait_group 1;" ::: "memory")
#define CP_WAIT0()     asm volatile("cp.async.wait_group 0;" ::: "memory")

#define KC 64
#define RSTR 72
#define TILE_B (128 * RSTR * 2)          // 18432 B per 128-row fp16 tile
#define STAGE2_B (2 * TILE_B)            // A, B = 36864 B (qkv single-pass)
#define DSTR 132

__device__ __forceinline__ uint32_t packh2(float x, float y) {
    __half2 hh = __floats2half2_rn(x, y);
    return *(uint32_t*)&hh;
}

// ---------------- kernel 1: time projections ------------------------------
__global__ void __launch_bounds__(256) time_proj(
    const float* __restrict__ time_emb,
    const float* __restrict__ Wqt, const float* __restrict__ bqt,
    const float* __restrict__ Wkt, const float* __restrict__ bkt,
    const float* __restrict__ Wvt, const float* __restrict__ bvt)
{
    const int b = blockIdx.x;
    __shared__ float te[Tt];
    for (int i = threadIdx.x; i < Tt; i += blockDim.x)
        te[i] = time_emb[b * Tt + i];
    __syncthreads();
    for (int n = threadIdx.x; n < Dm; n += blockDim.x) {
        float aq = 0.f, ak = 0.f, av = 0.f;
        for (int t = 0; t < Tt; t++) {
            float x = te[t];
            aq += x * Wqt[t * Dm + n];
            ak += x * Wkt[t * Dm + n];
            av += x * Wvt[t * Dm + n];
        }
        g_T[0][b][n] = aq + bqt[n];
        g_T[1][b][n] = ak + bkt[n];
        g_T[2][b][n] = av + bvt[n];
    }
}

// ---------------- preps --------------------------------------------------
__global__ void __launch_bounds__(256) prep_patches(const float* __restrict__ src)
{
    size_t i = (size_t)blockIdx.x * 256 + threadIdx.x;
    float4 v = ((const float4*)src)[i];
    uint32_t* H = (uint32_t*)g_P16;
    H[2 * i] = packh2(v.x, v.y);
    H[2 * i + 1] = packh2(v.z, v.w);
}

__global__ void __launch_bounds__(256) prep_er(const float* __restrict__ src)
{
    size_t i = (size_t)blockIdx.x * 256 + threadIdx.x;   // i < Sq*HDm/4
    float4 v = ((const float4*)src)[i];
    uint32_t* E = (uint32_t*)&g_Er16[0][0];
    E[2 * i] = packh2(v.x, v.y);
    E[2 * i + 1] = packh2(v.z, v.w);
}

__global__ void __launch_bounds__(256) prep_wt(
    const float* __restrict__ Wq, const float* __restrict__ Wk,
    const float* __restrict__ Wv)
{
    const int z = blockIdx.z;
    const float* __restrict__ W = (z == 0) ? Wq : (z == 1 ? Wk : Wv);
    __shared__ float s[32][33];
    const int n0 = blockIdx.x * 32, k0 = blockIdx.y * 32;
    const int tx = threadIdx.x & 31, ty = threadIdx.x >> 5;
    #pragma unroll
    for (int i = 0; i < 4; i++)
        s[ty + 8 * i][tx] = W[(size_t)(k0 + ty + 8 * i) * Dm + n0 + tx];
    __syncthreads();
    #pragma unroll
    for (int i = 0; i < 4; i++) {
        int n = n0 + ty + 8 * i, k = k0 + tx;
        g_WT16[z][n][k] = __float2half_rn(s[tx][ty + 8 * i]);
    }
}

// ---------------- microkernel: one Kc=64 chunk, single-pass fp16 -----------
__device__ __forceinline__ void mma_chunk1(uint32_t stage_base, int wm, int wn,
                                           int lane, float c[4][4][4])
{
    const uint32_t aRow = (uint32_t)(wm * 64 + (lane & 15));
    const uint32_t aColBase = (uint32_t)((lane >> 4) * 8);
    const uint32_t bRow = (uint32_t)(wn * 32 + ((lane >> 3) & 1) * 8 + (lane & 7));
    const uint32_t sA = stage_base;
    const uint32_t sB = stage_base + TILE_B;

    #pragma unroll
    for (int ks = 0; ks < 4; ks++) {
        const uint32_t kcol = (uint32_t)(ks * 16) + aColBase;
        uint32_t aa[4][4], bb[4][2];
        #pragma unroll
        for (int mt = 0; mt < 4; mt++) {
            uint32_t off = ((aRow + mt * 16) * RSTR + kcol) * 2;
            ldmx4(aa[mt], sA + off);
        }
        #pragma unroll
        for (int nt2 = 0; nt2 < 2; nt2++) {
            uint32_t off = ((bRow + nt2 * 16) * RSTR + kcol) * 2;
            uint32_t t[4];
            ldmx4(t, sB + off);
            bb[nt2 * 2][0] = t[0]; bb[nt2 * 2][1] = t[2];
            bb[nt2 * 2 + 1][0] = t[1]; bb[nt2 * 2 + 1][1] = t[3];
        }
        #pragma unroll
        for (int mt = 0; mt < 4; mt++)
            #pragma unroll
            for (int nt = 0; nt < 4; nt++)
                mma16816h(c[mt][nt], aa[mt], bb[nt]);
    }
}

// ---------------- kernel 2: QKV via mma.sync fp16 (3-stage, 2 CTA/SM) ------
__global__ void __launch_bounds__(256, 2) qkv_mma(
    const float* __restrict__ bq, const float* __restrict__ bk,
    const float* __restrict__ bv)
{
    extern __shared__ char sm[];
    const uint32_t smb = smem_u32(sm);
    const int z = blockIdx.z;
    const int n0 = blockIdx.x * 128, m0 = blockIdx.y * 128;
    const int tid = threadIdx.x;
    const int warp = tid >> 5, lane = tid & 31;
    const int wm = warp & 1, wn = warp >> 1;

    auto load_stage = [&](int chunk, int s) {
        const uint32_t st = smb + (uint32_t)s * STAGE2_B;
        const int k0 = chunk * KC;
        #pragma unroll
        for (int it = 0; it < 4; it++) {
            int i = tid + it * 256;
            int r = i >> 3, cc = i & 7;
            uint32_t doff = (uint32_t)(r * RSTR + cc * 8) * 2;
            CP16(st + doff, g_P16 + (size_t)(m0 + r) * Dm + k0 + cc * 8);
            CP16(st + TILE_B + doff, &g_WT16[z][n0 + r][k0 + cc * 8]);
        }
        CP_COMMIT();
    };

    float c[4][4][4] = {};

    load_stage(0, 0);
    load_stage(1, 1);
    for (int ch = 0; ch < 12; ch++) {
        if (ch < 10) CP_WAIT1(); else CP_WAIT0();
        __syncthreads();
        if (ch + 2 < 12) load_stage(ch + 2, (ch + 2) % 3);
        mma_chunk1(smb + (uint32_t)(ch % 3) * STAGE2_B, wm, wn, lane, c);
    }

    const float* bias = (z == 0) ? bq : (z == 1 ? bk : bv);
    const int lrow = lane >> 2, lcol = (lane & 3) * 2;
    #pragma unroll
    for (int mt = 0; mt < 4; mt++) {
        #pragma unroll
        for (int nt = 0; nt < 4; nt++) {
            const int col = n0 + wn * 32 + nt * 8 + lcol;
            const float bx = bias[col], by = bias[col + 1];
            #pragma unroll
            for (int hf = 0; hf < 2; hf++) {
                const int row = m0 + wm * 64 + mt * 16 + lrow + hf * 8;
                const int b = row >> 10;
                const float v0 = c[mt][nt][hf * 2 + 0] + bx;
                const float v1 = c[mt][nt][hf * 2 + 1] + by;
                const float t0 = g_T[z][b][col];
                const float t1 = g_T[z][b][col + 1];
                const size_t o = (size_t)row * Dm + col;
                if (z == 0) {
                    *(uint32_t*)&g_Q16[o] = packh2(v0 + t0, v1 + t1);
                    *(uint32_t*)&g_QS16[o] = packh2(v0, v1);
                } else if (z == 1) {
                    *(uint32_t*)&g_K16[o] = packh2(v0 + t0, v1 + t1);
                } else {
                    *(uint32_t*)&g_V16[o] = packh2(v0 + t0, v1 + t1);
                }
            }
        }
    }
}

// ---------------- kernel 3: fused flash attention + rel-bias (fp16) --------
// 256 threads (8 warps), 2 CTAs/SM. Warp = wp (16 q rows) x wh (32-col k-half).
// Er ring: 3 strips of 64 rows (slot = (s+3)%3). Dw stored fp16.
#define aQ    0u            /* 64x72 fp16 = 9216 */
#define aQS   9216u         /* 80x72 fp16 = 11520 */
#define aKV   20736u        /* stage: K16 | V16 each 9216 = 18432; x2 */
#define aEr   57600u        /* 192x72 fp16 = 27648 */
#define aD    85248u        /* 65x132 fp16 = 17160 */
#define aRed  102408u       /* sM 128 f32 + sL 128 f32 */
#define ATTN_SMEM 103432
#define OSTR 68

__global__ void __launch_bounds__(256, 2) attn_mma(float* __restrict__ out)
{
    extern __shared__ char sm[];
    const uint32_t smb = smem_u32(sm);
    const int q0 = blockIdx.x * 64;
    const int h = blockIdx.y, b = blockIdx.z;
    const int tid = threadIdx.x, warp = tid >> 5, lane = tid & 31;
    const int wp = warp & 3, wh = warp >> 2;
    __half* Dw = (__half*)(sm + aD);
    float* sM = (float*)(sm + aRed);
    float* sL = sM + 128;

    auto load_kv = [&](int kt, int s) {
        const uint32_t st = smb + aKV + (uint32_t)s * 18432u;
        const size_t krow0 = ((size_t)(b * Sq + kt * 64)) * Dm + h * HDm;
        #pragma unroll
        for (int it = 0; it < 2; it++) {
            int i = tid + it * 256;
            int r = i >> 3, cc = i & 7;
            uint32_t doff = (uint32_t)(r * RSTR + cc * 8) * 2;
            size_t src = krow0 + (size_t)r * Dm + cc * 8;
            CP16(st + doff, g_K16 + src);
            CP16(st + 9216u + doff, g_V16 + src);
        }
    };
    auto load_er = [&](int s) {
        const int estart = s * 64 - q0;
        const int slot = ((s + 3) % 3) * 64;
        #pragma unroll
        for (int it = 0; it < 2; it++) {
            int i = tid + it * 256;
            int r = i >> 3, cc = i & 7;
            int e = estart + r;
            int t = (e <= 0) ? (Sq - 1 + e) : (e - 2);
            if (t < 0) t = 0; if (t > Sq - 1) t = Sq - 1;
            uint32_t doff = (uint32_t)((slot + r) * RSTR + cc * 8) * 2;
            CP16(smb + aEr + doff, &g_Er16[t][cc * 8]);
        }
    };
    auto do_dstrip = [&](int s) {
        const int base = s * 64 - q0;
        const uint32_t erow0 = (uint32_t)(((s + 3) % 3) * 64);
        const int dcol0 = base & 127;
        const int par = warp & 1;
        uint32_t eb[4][2];
        const uint32_t nrow = erow0 +
            (uint32_t)((warp & 6) * 8 + ((lane >> 3) & 1) * 8 + (lane & 7));
        #pragma unroll
        for (int ks = 0; ks < 4; ks++) {
            uint32_t addr = smb + aEr +
                (nrow * RSTR + (uint32_t)(ks * 16 + (lane >> 4) * 8)) * 2;
            uint32_t t4[4];
            ldmx4(t4, addr);
            eb[ks][0] = t4[par]; eb[ks][1] = t4[2 + par];
        }
        #pragma unroll
        for (int mt = 0; mt < 5; mt++) {
            uint32_t sa[4][4];
            const uint32_t arow = (uint32_t)(mt * 16 + (lane & 15));
            #pragma unroll
            for (int ks = 0; ks < 4; ks++) {
                uint32_t addr = smb + aQS +
                    (arow * RSTR + (uint32_t)(ks * 16 + (lane >> 4) * 8)) * 2;
                ldmx4(sa[ks], addr);
            }
            float cc4[4] = {};
            #pragma unroll
            for (int ks = 0; ks < 4; ks++)
                mma16816h(cc4, sa[ks], eb[ks]);
            const int r0 = mt * 16 + (lane >> 2);
            const int colb = dcol0 + warp * 8 + (lane & 3) * 2;
            if (r0 <= 64)
                *(uint32_t*)&Dw[r0 * DSTR + colb] = packh2(cc4[0], cc4[1]);
            if (r0 + 8 <= 64)
                *(uint32_t*)&Dw[(r0 + 8) * DSTR + colb] = packh2(cc4[2], cc4[3]);
        }
    };

    // ---- prologue loads ----
    {
        const size_t qrow0 = ((size_t)(b * Sq + q0)) * Dm + h * HDm;
        #pragma unroll
        for (int it = 0; it < 2; it++) {
            int i = tid + it * 256;
            int r = i >> 3, cc = i & 7;
            uint32_t doff = (uint32_t)(r * RSTR + cc * 8) * 2;
            CP16(smb + aQ + doff, g_Q16 + qrow0 + (size_t)r * Dm + cc * 8);
        }
        #pragma unroll
        for (int it = 0; it < 3; it++) {
            int i = tid + it * 256;
            if (i < 640) {
                int r = i >> 3, cc = i & 7;
                int rr = q0 + r; if (rr > Sq - 1) rr = Sq - 1;
                uint32_t doff = (uint32_t)(r * RSTR + cc * 8) * 2;
                CP16(smb + aQS + doff,
                     g_QS16 + ((size_t)(b * Sq + rr)) * Dm + h * HDm + cc * 8);
            }
        }
        load_er(-1); load_er(0); load_er(1);
        load_kv(0, 0);
        CP_COMMIT();                 // G0
        load_kv(1, 1);
        CP_COMMIT();                 // G1
    }

    CP_WAIT1();
    __syncthreads();                 // G0 visible

    // ---- hoist Q fragments (loop-invariant) ----
    uint32_t qa[4][4];
    {
        const uint32_t arow = (uint32_t)(wp * 16 + (lane & 15));
        #pragma unroll
        for (int ks = 0; ks < 4; ks++) {
            uint32_t addr = smb + aQ +
                (arow * RSTR + (uint32_t)(ks * 16 + (lane >> 4) * 8)) * 2;
            ldmx4(qa[ks], addr);
        }
    }

    float m_[2] = {-1e30f, -1e30f}, l_[2] = {0.f, 0.f};
    float co[8][4] = {};
    const int row16 = (lane >> 2);

    for (int kt = 0; kt < 16; kt++) {
        const int s = kt & 1;
        const int d0 = kt * 64 - q0;
        if (kt > 0) { CP_WAIT1(); __syncthreads(); }

        // ---- D strips (incremental, fp16 1-pass) ----
        if (kt == 0) { do_dstrip(-1); do_dstrip(0); }
        else do_dstrip(kt);

        // ---- QK^T: fp16 1-pass, 16 q rows x 32 k cols per warp ----
        float c[4][4] = {};
        {
            const uint32_t stK = smb + aKV + (uint32_t)s * 18432u;
            #pragma unroll
            for (int ks = 0; ks < 4; ks++) {
                uint32_t bh[4][2];
                #pragma unroll
                for (int pp = 0; pp < 2; pp++) {
                    uint32_t nrow = (uint32_t)(wh * 32 + pp * 16 +
                                    ((lane >> 3) & 1) * 8 + (lane & 7));
                    uint32_t addr = stK +
                        (nrow * RSTR + (uint32_t)(ks * 16 + (lane >> 4) * 8)) * 2;
                    uint32_t t4[4];
                    ldmx4(t4, addr);
                    bh[pp * 2][0] = t4[0]; bh[pp * 2][1] = t4[2];
                    bh[pp * 2 + 1][0] = t4[1]; bh[pp * 2 + 1][1] = t4[3];
                }
                #pragma unroll
                for (int nt = 0; nt < 4; nt++)
                    mma16816h(c[nt], qa[ks], bh[nt]);
            }
        }

        __syncthreads();   // Dw strip visible

        // ---- bias gather + own-half online softmax ----
        float mloc[2] = {-1e30f, -1e30f};
        #pragma unroll
        for (int nt = 0; nt < 4; nt++) {
            #pragma unroll
            for (int e2 = 0; e2 < 2; e2++) {
                const int col = wh * 32 + nt * 8 + (lane & 3) * 2 + e2;
                #pragma unroll
                for (int hf = 0; hf < 2; hf++) {
                    const int q_loc = wp * 16 + row16 + hf * 8;
                    const int e = d0 + col - q_loc;
                    float bias = (e == 1) ? 0.f
                        : __half2float(Dw[(q_loc + (e >= 2 ? 1 : 0)) * DSTR + (e & 127)]);
                    float sv = (c[nt][hf * 2 + e2] + bias) * SCALE_F;
                    c[nt][hf * 2 + e2] = sv;
                    mloc[hf] = fmaxf(mloc[hf], sv);
                }
            }
        }
        float corr[2], psum[2] = {0.f, 0.f};
        #pragma unroll
        for (int hf = 0; hf < 2; hf++) {
            mloc[hf] = fmaxf(mloc[hf], __shfl_xor_sync(0xffffffffu, mloc[hf], 1));
            mloc[hf] = fmaxf(mloc[hf], __shfl_xor_sync(0xffffffffu, mloc[hf], 2));
            float mn = fmaxf(m_[hf], mloc[hf]);
            corr[hf] = __expf(m_[hf] - mn);
            m_[hf] = mn;
        }
        #pragma unroll
        for (int nt = 0; nt < 4; nt++) {
            #pragma unroll
            for (int k4 = 0; k4 < 4; k4++) {
                const int hf = k4 >> 1;
                float p = __expf(c[nt][k4] - m_[hf]);
                c[nt][k4] = p;
                psum[hf] += p;
            }
        }
        #pragma unroll
        for (int hf = 0; hf < 2; hf++) {
            psum[hf] += __shfl_xor_sync(0xffffffffu, psum[hf], 1);
            psum[hf] += __shfl_xor_sync(0xffffffffu, psum[hf], 2);
            l_[hf] = l_[hf] * corr[hf] + psum[hf];
        }
        #pragma unroll
        for (int nt = 0; nt < 8; nt++) {
            co[nt][0] *= corr[0]; co[nt][1] *= corr[0];
            co[nt][2] *= corr[1]; co[nt][3] *= corr[1];
        }

        // ---- PV: Ph(fp16) x V(fp16), 1 pass ----
        {
            const uint32_t stV = smb + aKV + (uint32_t)s * 18432u + 9216u;
            #pragma unroll
            for (int ktk = 0; ktk < 2; ktk++) {
                uint32_t pha[4];
                #pragma unroll
                for (int sub = 0; sub < 2; sub++)
                    #pragma unroll
                    for (int h2 = 0; h2 < 2; h2++)
                        pha[h2 + sub * 2] = packh2(c[2 * ktk + sub][h2 * 2],
                                                   c[2 * ktk + sub][h2 * 2 + 1]);
                uint32_t vb[8][2];
                #pragma unroll
                for (int pp = 0; pp < 4; pp++) {
                    uint32_t krow = (uint32_t)(wh * 32 + ktk * 16 +
                                   (lane & 7) + ((lane >> 3) & 1) * 8);
                    uint32_t ncol = (uint32_t)(pp * 16 + (lane >> 4) * 8);
                    uint32_t addr = stV + (krow * RSTR + ncol) * 2;
                    uint32_t t4[4];
                    ldmx4t(t4, addr);
                    vb[pp * 2][0] = t4[0]; vb[pp * 2][1] = t4[1];
                    vb[pp * 2 + 1][0] = t4[2]; vb[pp * 2 + 1][1] = t4[3];
                }
                #pragma unroll
                for (int nt = 0; nt < 8; nt++)
                    mma16816h(co[nt], pha, vb[nt]);
            }
        }

        __syncthreads();   // all reads of KV stage s & Er slots done

        if (kt + 2 < 16) load_kv(kt + 2, s);
        if (kt + 2 <= 15) load_er(kt + 2);
        CP_COMMIT();
    }

    // ---- merge the two k-half softmax states, write out ----
    if ((lane & 3) == 0) {
        #pragma unroll
        for (int hf = 0; hf < 2; hf++) {
            sM[wh * 64 + wp * 16 + row16 + hf * 8] = m_[hf];
            sL[wh * 64 + wp * 16 + row16 + hf * 8] = l_[hf];
        }
    }
    __syncthreads();
    float myc[2], inv[2];
    #pragma unroll
    for (int hf = 0; hf < 2; hf++) {
        const int rowi = wp * 16 + row16 + hf * 8;
        float mo = sM[(wh ^ 1) * 64 + rowi];
        float lo2 = sL[(wh ^ 1) * 64 + rowi];
        float mstar = fmaxf(m_[hf], mo);
        myc[hf] = __expf(m_[hf] - mstar);
        float otc = __expf(mo - mstar);
        inv[hf] = 1.0f / (l_[hf] * myc[hf] + lo2 * otc);
    }
    __syncthreads();
    float* sOut = (float*)(sm + aKV);
    if (wh == 1) {
        #pragma unroll
        for (int hf = 0; hf < 2; hf++) {
            const int row = wp * 16 + row16 + hf * 8;
            #pragma unroll
            for (int nt = 0; nt < 8; nt++) {
                const int col = nt * 8 + (lane & 3) * 2;
                *(float2*)&sOut[row * OSTR + col] =
                    make_float2(co[nt][hf * 2] * myc[hf],
                                co[nt][hf * 2 + 1] * myc[hf]);
            }
        }
    }
    __syncthreads();
    if (wh == 0) {
        #pragma unroll
        for (int hf = 0; hf < 2; hf++) {
            const int row = wp * 16 + row16 + hf * 8;
            const size_t ob = ((size_t)(b * Sq + q0 + row)) * Dm + h * HDm;
            #pragma unroll
            for (int nt = 0; nt < 8; nt++) {
                const int col = nt * 8 + (lane & 3) * 2;
                float2 pr = *(float2*)&sOut[row * OSTR + col];
                *(float2*)&out[ob + col] =
                    make_float2((co[nt][hf * 2] * myc[hf] + pr.x) * inv[hf],
                                (co[nt][hf * 2 + 1] * myc[hf] + pr.y) * inv[hf]);
            }
        }
    }
}

// ---------------- launch ----------------------------------------------------
extern "C" void kernel_launch(void* const* d_in, const int* in_sizes, int n_in,
                              void* d_out, int out_size)
{
    (void)in_sizes; (void)n_in; (void)out_size;
    const float* patches  = (const float*)d_in[0];
    const float* time_emb = (const float*)d_in[1];
    const float* Wqs = (const float*)d_in[2];
    const float* bqs = (const float*)d_in[3];
    const float* Wks = (const float*)d_in[4];
    const float* bks = (const float*)d_in[5];
    const float* Wvs = (const float*)d_in[6];
    const float* bvs = (const float*)d_in[7];
    const float* Wqt = (const float*)d_in[8];
    const float* bqt = (const float*)d_in[9];
    const float* Wkt = (const float*)d_in[10];
    const float* bkt = (const float*)d_in[11];
    const float* Wvt = (const float*)d_in[12];
    const float* bvt = (const float*)d_in[13];
    const float* Er  = (const float*)d_in[14];
    float* out = (float*)d_out;

    time_proj<<<Bb, 256>>>(time_emb, Wqt, bqt, Wkt, bkt, Wvt, bvt);
    prep_patches<<<(Bb * Sq * Dm / 4) / 256, 256>>>(patches);
    prep_er<<<(Sq * HDm / 4) / 256, 256>>>(Er);
    prep_wt<<<dim3(Dm / 32, Dm / 32, 3), 256>>>(Wqs, Wks, Wvs);

    const int qkv_smem = 3 * STAGE2_B;  // 110592 -> 2 CTAs/SM
    cudaFuncSetAttribute(qkv_mma, cudaFuncAttributeMaxDynamicSharedMemorySize, qkv_smem);
    qkv_mma<<<dim3(Dm / 128, (Bb * Sq) / 128, 3), 256, qkv_smem>>>(bqs, bks, bvs);

    cudaFuncSetAttribute(attn_mma, cudaFuncAttributeMaxDynamicSharedMemorySize, ATTN_SMEM);
    attn_mma<<<dim3(Sq / 64, Hh, Bb), 256, ATTN_SMEM>>>(out);
}

// round 11
// speedup vs baseline: 5.4586x; 1.4651x over previous
#include <cuda_runtime.h>
#include <cuda_bf16.h>
#include <cuda_fp16.h>
#include <cstdint>
#include <cstddef>

#define Sq 1024
#define Dm 768
#define Hh 12
#define HDm 64
#define Bb 8
#define Tt 384
#define SCALE_F 0.125f

// ---------------- scratch (device globals; no allocation allowed) ----------
__device__ float g_T[3][Bb][Dm];                    // time q/k/v vectors
__device__ __half g_P16[(size_t)Bb * Sq * Dm];      // patches fp16
__device__ __half g_WT16[3][Dm][Dm];                // W^T fp16 [z][n][k]
__device__ __half g_Q16[(size_t)Bb * Sq * Dm];      // (qs+tq)*0.125  (fp16)
__device__ __half g_K16[(size_t)Bb * Sq * Dm];      // ks+tk  (fp16)
__device__ __half g_QS16[(size_t)Bb * Sq * Dm];     // qs*0.125 (no time, fp16)
__device__ __half g_V16[(size_t)Bb * Sq * Dm];      // vs+tv  (fp16)
__device__ __half g_Er16[Sq][HDm];

// ---------------- PTX helpers (baseline ISA: sm_80+) ------------------------
__device__ __forceinline__ uint32_t smem_u32(const void* p) {
    uint32_t a;
    asm("{ .reg .u64 t; cvta.to.shared.u64 t, %1; cvt.u32.u64 %0, t; }"
        : "=r"(a) : "l"(p));
    return a;
}
__device__ __forceinline__ void ldmx4(uint32_t* r, uint32_t addr) {
    asm volatile("ldmatrix.sync.aligned.m8n8.x4.shared.b16 {%0,%1,%2,%3}, [%4];"
                 : "=r"(r[0]), "=r"(r[1]), "=r"(r[2]), "=r"(r[3]) : "r"(addr));
}
__device__ __forceinline__ void ldmx4t(uint32_t* r, uint32_t addr) {
    asm volatile("ldmatrix.sync.aligned.m8n8.x4.trans.shared.b16 {%0,%1,%2,%3}, [%4];"
                 : "=r"(r[0]), "=r"(r[1]), "=r"(r[2]), "=r"(r[3]) : "r"(addr));
}
__device__ __forceinline__ void mma16816h(float* c, const uint32_t* a, const uint32_t* b) {
    asm volatile(
        "mma.sync.aligned.m16n8k16.row.col.f32.f16.f16.f32 "
        "{%0,%1,%2,%3}, {%4,%5,%6,%7}, {%8,%9}, {%0,%1,%2,%3};"
        : "+f"(c[0]), "+f"(c[1]), "+f"(c[2]), "+f"(c[3])
        : "r"(a[0]), "r"(a[1]), "r"(a[2]), "r"(a[3]), "r"(b[0]), "r"(b[1]));
}
#define CP16(dst, src) asm volatile("cp.async.cg.shared.global [%0], [%1], 16;" :: "r"(dst), "l"(src))
#define CP_COMMIT()    asm volatile("cp.async.commit_group;" ::: "memory")
#define CP_WAIT1()     asm volatile("cp.async.wait_group 1;" ::: "memory")
#define CP_WAIT0()     asm volatile("cp.async.wait_group 0;" ::: "memory")

#define KC 64
#define RSTR 72
#define TILE_B (128 * RSTR * 2)          // 18432 B per 128-row fp16 tile
#define STAGE2_B (2 * TILE_B)            // A, B = 36864 B (qkv single-pass)
#define DSTR 132

__device__ __forceinline__ uint32_t packh2(float x, float y) {
    __half2 hh = __floats2half2_rn(x, y);
    return *(uint32_t*)&hh;
}

// ---------------- kernel 1: time projections (parallelized) ----------------
__global__ void __launch_bounds__(128) time_proj(
    const float* __restrict__ time_emb,
    const float* __restrict__ Wqt, const float* __restrict__ bqt,
    const float* __restrict__ Wkt, const float* __restrict__ bkt,
    const float* __restrict__ Wvt, const float* __restrict__ bvt)
{
    const int b = blockIdx.y;
    const int n = blockIdx.x * 128 + threadIdx.x;
    __shared__ float te[Tt];
    for (int i = threadIdx.x; i < Tt; i += 128)
        te[i] = time_emb[b * Tt + i];
    __syncthreads();
    float aq = 0.f, ak = 0.f, av = 0.f;
    for (int t = 0; t < Tt; t++) {
        float x = te[t];
        aq += x * Wqt[t * Dm + n];
        ak += x * Wkt[t * Dm + n];
        av += x * Wvt[t * Dm + n];
    }
    g_T[0][b][n] = aq + bqt[n];
    g_T[1][b][n] = ak + bkt[n];
    g_T[2][b][n] = av + bvt[n];
}

// ---------------- preps --------------------------------------------------
__global__ void __launch_bounds__(256) prep_patches(const float* __restrict__ src)
{
    size_t i = (size_t)blockIdx.x * 256 + threadIdx.x;
    float4 v = ((const float4*)src)[i];
    uint32_t* H = (uint32_t*)g_P16;
    H[2 * i] = packh2(v.x, v.y);
    H[2 * i + 1] = packh2(v.z, v.w);
}

__global__ void __launch_bounds__(256) prep_er(const float* __restrict__ src)
{
    size_t i = (size_t)blockIdx.x * 256 + threadIdx.x;   // i < Sq*HDm/4
    float4 v = ((const float4*)src)[i];
    uint32_t* E = (uint32_t*)&g_Er16[0][0];
    E[2 * i] = packh2(v.x, v.y);
    E[2 * i + 1] = packh2(v.z, v.w);
}

__global__ void __launch_bounds__(256) prep_wt(
    const float* __restrict__ Wq, const float* __restrict__ Wk,
    const float* __restrict__ Wv)
{
    const int z = blockIdx.z;
    const float* __restrict__ W = (z == 0) ? Wq : (z == 1 ? Wk : Wv);
    __shared__ float s[32][33];
    const int n0 = blockIdx.x * 32, k0 = blockIdx.y * 32;
    const int tx = threadIdx.x & 31, ty = threadIdx.x >> 5;
    #pragma unroll
    for (int i = 0; i < 4; i++)
        s[ty + 8 * i][tx] = W[(size_t)(k0 + ty + 8 * i) * Dm + n0 + tx];
    __syncthreads();
    #pragma unroll
    for (int i = 0; i < 4; i++) {
        int n = n0 + ty + 8 * i, k = k0 + tx;
        g_WT16[z][n][k] = __float2half_rn(s[tx][ty + 8 * i]);
    }
}

// ---------------- microkernel: one Kc=64 chunk, single-pass fp16 -----------
__device__ __forceinline__ void mma_chunk1(uint32_t stage_base, int wm, int wn,
                                           int lane, float c[4][4][4])
{
    const uint32_t aRow = (uint32_t)(wm * 64 + (lane & 15));
    const uint32_t aColBase = (uint32_t)((lane >> 4) * 8);
    const uint32_t bRow = (uint32_t)(wn * 32 + ((lane >> 3) & 1) * 8 + (lane & 7));
    const uint32_t sA = stage_base;
    const uint32_t sB = stage_base + TILE_B;

    #pragma unroll
    for (int ks = 0; ks < 4; ks++) {
        const uint32_t kcol = (uint32_t)(ks * 16) + aColBase;
        uint32_t aa[4][4], bb[4][2];
        #pragma unroll
        for (int mt = 0; mt < 4; mt++) {
            uint32_t off = ((aRow + mt * 16) * RSTR + kcol) * 2;
            ldmx4(aa[mt], sA + off);
        }
        #pragma unroll
        for (int nt2 = 0; nt2 < 2; nt2++) {
            uint32_t off = ((bRow + nt2 * 16) * RSTR + kcol) * 2;
            uint32_t t[4];
            ldmx4(t, sB + off);
            bb[nt2 * 2][0] = t[0]; bb[nt2 * 2][1] = t[2];
            bb[nt2 * 2 + 1][0] = t[1]; bb[nt2 * 2 + 1][1] = t[3];
        }
        #pragma unroll
        for (int mt = 0; mt < 4; mt++)
            #pragma unroll
            for (int nt = 0; nt < 4; nt++)
                mma16816h(c[mt][nt], aa[mt], bb[nt]);
    }
}

// ---------------- kernel 2: QKV via mma.sync fp16 (3-stage, 2 CTA/SM) ------
__global__ void __launch_bounds__(256, 2) qkv_mma(
    const float* __restrict__ bq, const float* __restrict__ bk,
    const float* __restrict__ bv)
{
    extern __shared__ char sm[];
    const uint32_t smb = smem_u32(sm);
    const int z = blockIdx.z;
    const int n0 = blockIdx.x * 128, m0 = blockIdx.y * 128;
    const int tid = threadIdx.x;
    const int warp = tid >> 5, lane = tid & 31;
    const int wm = warp & 1, wn = warp >> 1;

    auto load_stage = [&](int chunk, int s) {
        const uint32_t st = smb + (uint32_t)s * STAGE2_B;
        const int k0 = chunk * KC;
        #pragma unroll
        for (int it = 0; it < 4; it++) {
            int i = tid + it * 256;
            int r = i >> 3, cc = i & 7;
            uint32_t doff = (uint32_t)(r * RSTR + cc * 8) * 2;
            CP16(st + doff, g_P16 + (size_t)(m0 + r) * Dm + k0 + cc * 8);
            CP16(st + TILE_B + doff, &g_WT16[z][n0 + r][k0 + cc * 8]);
        }
        CP_COMMIT();
    };

    float c[4][4][4] = {};

    load_stage(0, 0);
    load_stage(1, 1);
    for (int ch = 0; ch < 12; ch++) {
        if (ch < 10) CP_WAIT1(); else CP_WAIT0();
        __syncthreads();
        if (ch + 2 < 12) load_stage(ch + 2, (ch + 2) % 3);
        mma_chunk1(smb + (uint32_t)(ch % 3) * STAGE2_B, wm, wn, lane, c);
    }

    const float* bias = (z == 0) ? bq : (z == 1 ? bk : bv);
    const int lrow = lane >> 2, lcol = (lane & 3) * 2;
    #pragma unroll
    for (int mt = 0; mt < 4; mt++) {
        #pragma unroll
        for (int nt = 0; nt < 4; nt++) {
            const int col = n0 + wn * 32 + nt * 8 + lcol;
            const float bx = bias[col], by = bias[col + 1];
            #pragma unroll
            for (int hf = 0; hf < 2; hf++) {
                const int row = m0 + wm * 64 + mt * 16 + lrow + hf * 8;
                const int b = row >> 10;
                const float v0 = c[mt][nt][hf * 2 + 0] + bx;
                const float v1 = c[mt][nt][hf * 2 + 1] + by;
                const float t0 = g_T[z][b][col];
                const float t1 = g_T[z][b][col + 1];
                const size_t o = (size_t)row * Dm + col;
                if (z == 0) {
                    // fold softmax scale (exact power of 2) into Q and QS
                    *(uint32_t*)&g_Q16[o] = packh2((v0 + t0) * SCALE_F,
                                                   (v1 + t1) * SCALE_F);
                    *(uint32_t*)&g_QS16[o] = packh2(v0 * SCALE_F, v1 * SCALE_F);
                } else if (z == 1) {
                    *(uint32_t*)&g_K16[o] = packh2(v0 + t0, v1 + t1);
                } else {
                    *(uint32_t*)&g_V16[o] = packh2(v0 + t0, v1 + t1);
                }
            }
        }
    }
}

// ---------------- kernel 3: fused flash attention + rel-bias (fp16) --------
// 256 threads (8 warps), 2 CTAs/SM. Warp = wp (16 q rows) x wh (32-col k-half).
// Er ring: 3 strips of 64 rows. Bias in DIAGONAL layout:
//   Dd[q][(e+q)&127] = bias(q, e)   (e==1 zeroed, (e>=2) row-shift at store)
// Read: bias(q, col) = Dd[q][(d0+col)&127]  -- predicate-free, aligned __half2.
#define aQ    0u            /* 64x72 fp16 = 9216 */
#define aQS   9216u         /* 80x72 fp16 = 11520 */
#define aKV   20736u        /* stage: K16 | V16 each 9216 = 18432; x2 */
#define aEr   57600u        /* 192x72 fp16 = 27648 */
#define aD    85248u        /* 64x132 fp16 = 16896 */
#define aRed  102408u       /* sM 128 f32 + sL 128 f32 */
#define ATTN_SMEM 103432
#define OSTR 68

__global__ void __launch_bounds__(256, 2) attn_mma(float* __restrict__ out)
{
    extern __shared__ char sm[];
    const uint32_t smb = smem_u32(sm);
    const int q0 = blockIdx.x * 64;
    const int h = blockIdx.y, b = blockIdx.z;
    const int tid = threadIdx.x, warp = tid >> 5, lane = tid & 31;
    const int wp = warp & 3, wh = warp >> 2;
    __half* Dd = (__half*)(sm + aD);
    float* sM = (float*)(sm + aRed);
    float* sL = sM + 128;

    auto load_kv = [&](int kt, int s) {
        const uint32_t st = smb + aKV + (uint32_t)s * 18432u;
        const size_t krow0 = ((size_t)(b * Sq + kt * 64)) * Dm + h * HDm;
        #pragma unroll
        for (int it = 0; it < 2; it++) {
            int i = tid + it * 256;
            int r = i >> 3, cc = i & 7;
            uint32_t doff = (uint32_t)(r * RSTR + cc * 8) * 2;
            size_t src = krow0 + (size_t)r * Dm + cc * 8;
            CP16(st + doff, g_K16 + src);
            CP16(st + 9216u + doff, g_V16 + src);
        }
    };
    auto load_er = [&](int s) {
        const int estart = s * 64 - q0;
        const int slot = ((s + 3) % 3) * 64;
        #pragma unroll
        for (int it = 0; it < 2; it++) {
            int i = tid + it * 256;
            int r = i >> 3, cc = i & 7;
            int e = estart + r;
            int t = (e <= 0) ? (Sq - 1 + e) : (e - 2);
            if (t < 0) t = 0; if (t > Sq - 1) t = Sq - 1;
            uint32_t doff = (uint32_t)((slot + r) * RSTR + cc * 8) * 2;
            CP16(smb + aEr + doff, &g_Er16[t][cc * 8]);
        }
    };
    auto do_dstrip = [&](int s) {
        const int base = s * 64 - q0;
        const uint32_t erow0 = (uint32_t)(((s + 3) % 3) * 64);
        const int par = warp & 1;
        uint32_t eb[4][2];
        const uint32_t nrow = erow0 +
            (uint32_t)((warp & 6) * 8 + ((lane >> 3) & 1) * 8 + (lane & 7));
        #pragma unroll
        for (int ks = 0; ks < 4; ks++) {
            uint32_t addr = smb + aEr +
                (nrow * RSTR + (uint32_t)(ks * 16 + (lane >> 4) * 8)) * 2;
            uint32_t t4[4];
            ldmx4(t4, addr);
            eb[ks][0] = t4[par]; eb[ks][1] = t4[2 + par];
        }
        const int e0 = base + warp * 8 + (lane & 3) * 2;  // even
        #pragma unroll
        for (int mt = 0; mt < 5; mt++) {
            uint32_t sa[4][4];
            const uint32_t arow = (uint32_t)(mt * 16 + (lane & 15));
            #pragma unroll
            for (int ks = 0; ks < 4; ks++) {
                uint32_t addr = smb + aQS +
                    (arow * RSTR + (uint32_t)(ks * 16 + (lane >> 4) * 8)) * 2;
                ldmx4(sa[ks], addr);
            }
            float cc4[4] = {};
            #pragma unroll
            for (int ks = 0; ks < 4; ks++)
                mma16816h(cc4, sa[ks], eb[ks]);
            // diagonal-layout store with row-shift + e==1 zeroing
            const int p = (e0 >= 2) ? 1 : 0;   // pair-uniform (e0 even)
            #pragma unroll
            for (int rr = 0; rr < 2; rr++) {
                const int r = mt * 16 + (lane >> 2) + rr * 8;
                const int q_dst = r - p;
                if (q_dst >= 0 && q_dst < 64) {
                    const int j0 = (e0 + q_dst) & 127;
                    const int j1 = (e0 + 1 + q_dst) & 127;
                    Dd[q_dst * DSTR + j0] = __float2half_rn(cc4[rr * 2]);
                    Dd[q_dst * DSTR + j1] =
                        (e0 + 1 == 1) ? __float2half_rn(0.f)
                                      : __float2half_rn(cc4[rr * 2 + 1]);
                }
            }
        }
    };

    // ---- prologue loads ----
    {
        const size_t qrow0 = ((size_t)(b * Sq + q0)) * Dm + h * HDm;
        #pragma unroll
        for (int it = 0; it < 2; it++) {
            int i = tid + it * 256;
            int r = i >> 3, cc = i & 7;
            uint32_t doff = (uint32_t)(r * RSTR + cc * 8) * 2;
            CP16(smb + aQ + doff, g_Q16 + qrow0 + (size_t)r * Dm + cc * 8);
        }
        #pragma unroll
        for (int it = 0; it < 3; it++) {
            int i = tid + it * 256;
            if (i < 640) {
                int r = i >> 3, cc = i & 7;
                int rr = q0 + r; if (rr > Sq - 1) rr = Sq - 1;
                uint32_t doff = (uint32_t)(r * RSTR + cc * 8) * 2;
                CP16(smb + aQS + doff,
                     g_QS16 + ((size_t)(b * Sq + rr)) * Dm + h * HDm + cc * 8);
            }
        }
        load_er(-1); load_er(0); load_er(1);
        load_kv(0, 0);
        CP_COMMIT();                 // G0
        load_kv(1, 1);
        CP_COMMIT();                 // G1
    }

    CP_WAIT1();
    __syncthreads();                 // G0 visible

    // ---- hoist Q fragments (loop-invariant) ----
    uint32_t qa[4][4];
    {
        const uint32_t arow = (uint32_t)(wp * 16 + (lane & 15));
        #pragma unroll
        for (int ks = 0; ks < 4; ks++) {
            uint32_t addr = smb + aQ +
                (arow * RSTR + (uint32_t)(ks * 16 + (lane >> 4) * 8)) * 2;
            ldmx4(qa[ks], addr);
        }
    }

    float m_[2] = {-1e30f, -1e30f}, l_[2] = {0.f, 0.f};
    float co[8][4] = {};
    const int row16 = (lane >> 2);

    for (int kt = 0; kt < 16; kt++) {
        const int s = kt & 1;
        const int d0 = kt * 64 - q0;
        if (kt > 0) { CP_WAIT1(); __syncthreads(); }

        // ---- D strips (incremental, fp16 1-pass) ----
        if (kt == 0) { do_dstrip(-1); do_dstrip(0); }
        else do_dstrip(kt);

        // ---- QK^T: fp16 1-pass, 16 q rows x 32 k cols per warp ----
        float c[4][4] = {};
        {
            const uint32_t stK = smb + aKV + (uint32_t)s * 18432u;
            #pragma unroll
            for (int ks = 0; ks < 4; ks++) {
                uint32_t bh[4][2];
                #pragma unroll
                for (int pp = 0; pp < 2; pp++) {
                    uint32_t nrow = (uint32_t)(wh * 32 + pp * 16 +
                                    ((lane >> 3) & 1) * 8 + (lane & 7));
                    uint32_t addr = stK +
                        (nrow * RSTR + (uint32_t)(ks * 16 + (lane >> 4) * 8)) * 2;
                    uint32_t t4[4];
                    ldmx4(t4, addr);
                    bh[pp * 2][0] = t4[0]; bh[pp * 2][1] = t4[2];
                    bh[pp * 2 + 1][0] = t4[1]; bh[pp * 2 + 1][1] = t4[3];
                }
                #pragma unroll
                for (int nt = 0; nt < 4; nt++)
                    mma16816h(c[nt], qa[ks], bh[nt]);
            }
        }

        __syncthreads();   // Dd strip visible

        // ---- bias add (diagonal layout, predicate-free) + online softmax --
        float mloc[2] = {-1e30f, -1e30f};
        #pragma unroll
        for (int hf = 0; hf < 2; hf++) {
            const int q_loc = wp * 16 + row16 + hf * 8;
            const uint32_t rbase = (uint32_t)(q_loc * DSTR);
            #pragma unroll
            for (int nt = 0; nt < 4; nt++) {
                const int col = wh * 32 + nt * 8 + (lane & 3) * 2;
                const int idx = (d0 + col) & 127;        // even -> aligned
                __half2 b2 = *(__half2*)&Dd[rbase + idx];
                float2 bf = __half22float2(b2);
                float sv0 = c[nt][hf * 2 + 0] + bf.x;
                float sv1 = c[nt][hf * 2 + 1] + bf.y;
                c[nt][hf * 2 + 0] = sv0;
                c[nt][hf * 2 + 1] = sv1;
                mloc[hf] = fmaxf(mloc[hf], fmaxf(sv0, sv1));
            }
        }
        float corr[2], psum[2] = {0.f, 0.f};
        #pragma unroll
        for (int hf = 0; hf < 2; hf++) {
            mloc[hf] = fmaxf(mloc[hf], __shfl_xor_sync(0xffffffffu, mloc[hf], 1));
            mloc[hf] = fmaxf(mloc[hf], __shfl_xor_sync(0xffffffffu, mloc[hf], 2));
            float mn = fmaxf(m_[hf], mloc[hf]);
            corr[hf] = __expf(m_[hf] - mn);
            m_[hf] = mn;
        }
        #pragma unroll
        for (int nt = 0; nt < 4; nt++) {
            #pragma unroll
            for (int k4 = 0; k4 < 4; k4++) {
                const int hf = k4 >> 1;
                float p = __expf(c[nt][k4] - m_[hf]);
                c[nt][k4] = p;
                psum[hf] += p;
            }
        }
        #pragma unroll
        for (int hf = 0; hf < 2; hf++) {
            psum[hf] += __shfl_xor_sync(0xffffffffu, psum[hf], 1);
            psum[hf] += __shfl_xor_sync(0xffffffffu, psum[hf], 2);
            l_[hf] = l_[hf] * corr[hf] + psum[hf];
        }
        #pragma unroll
        for (int nt = 0; nt < 8; nt++) {
            co[nt][0] *= corr[0]; co[nt][1] *= corr[0];
            co[nt][2] *= corr[1]; co[nt][3] *= corr[1];
        }

        // ---- PV: Ph(fp16) x V(fp16), 1 pass ----
        {
            const uint32_t stV = smb + aKV + (uint32_t)s * 18432u + 9216u;
            #pragma unroll
            for (int ktk = 0; ktk < 2; ktk++) {
                uint32_t pha[4];
                #pragma unroll
                for (int sub = 0; sub < 2; sub++)
                    #pragma unroll
                    for (int h2 = 0; h2 < 2; h2++)
                        pha[h2 + sub * 2] = packh2(c[2 * ktk + sub][h2 * 2],
                                                   c[2 * ktk + sub][h2 * 2 + 1]);
                uint32_t vb[8][2];
                #pragma unroll
                for (int pp = 0; pp < 4; pp++) {
                    uint32_t krow = (uint32_t)(wh * 32 + ktk * 16 +
                                   (lane & 7) + ((lane >> 3) & 1) * 8);
                    uint32_t ncol = (uint32_t)(pp * 16 + (lane >> 4) * 8);
                    uint32_t addr = stV + (krow * RSTR + ncol) * 2;
                    uint32_t t4[4];
                    ldmx4t(t4, addr);
                    vb[pp * 2][0] = t4[0]; vb[pp * 2][1] = t4[1];
                    vb[pp * 2 + 1][0] = t4[2]; vb[pp * 2 + 1][1] = t4[3];
                }
                #pragma unroll
                for (int nt = 0; nt < 8; nt++)
                    mma16816h(co[nt], pha, vb[nt]);
            }
        }

        __syncthreads();   // all reads of KV stage s & Er slots done

        if (kt + 2 < 16) load_kv(kt + 2, s);
        if (kt + 2 <= 15) load_er(kt + 2);
        CP_COMMIT();
    }

    // ---- merge the two k-half softmax states, write out ----
    if ((lane & 3) == 0) {
        #pragma unroll
        for (int hf = 0; hf < 2; hf++) {
            sM[wh * 64 + wp * 16 + row16 + hf * 8] = m_[hf];
            sL[wh * 64 + wp * 16 + row16 + hf * 8] = l_[hf];
        }
    }
    __syncthreads();
    float myc[2], inv[2];
    #pragma unroll
    for (int hf = 0; hf < 2; hf++) {
        const int rowi = wp * 16 + row16 + hf * 8;
        float mo = sM[(wh ^ 1) * 64 + rowi];
        float lo2 = sL[(wh ^ 1) * 64 + rowi];
        float mstar = fmaxf(m_[hf], mo);
        myc[hf] = __expf(m_[hf] - mstar);
        float otc = __expf(mo - mstar);
        inv[hf] = 1.0f / (l_[hf] * myc[hf] + lo2 * otc);
    }
    __syncthreads();
    float* sOut = (float*)(sm + aKV);
    if (wh == 1) {
        #pragma unroll
        for (int hf = 0; hf < 2; hf++) {
            const int row = wp * 16 + row16 + hf * 8;
            #pragma unroll
            for (int nt = 0; nt < 8; nt++) {
                const int col = nt * 8 + (lane & 3) * 2;
                *(float2*)&sOut[row * OSTR + col] =
                    make_float2(co[nt][hf * 2] * myc[hf],
                                co[nt][hf * 2 + 1] * myc[hf]);
            }
        }
    }
    __syncthreads();
    if (wh == 0) {
        #pragma unroll
        for (int hf = 0; hf < 2; hf++) {
            const int row = wp * 16 + row16 + hf * 8;
            const size_t ob = ((size_t)(b * Sq + q0 + row)) * Dm + h * HDm;
            #pragma unroll
            for (int nt = 0; nt < 8; nt++) {
                const int col = nt * 8 + (lane & 3) * 2;
                float2 pr = *(float2*)&sOut[row * OSTR + col];
                *(float2*)&out[ob + col] =
                    make_float2((co[nt][hf * 2] * myc[hf] + pr.x) * inv[hf],
                                (co[nt][hf * 2 + 1] * myc[hf] + pr.y) * inv[hf]);
            }
        }
    }
}

// ---------------- launch ----------------------------------------------------
extern "C" void kernel_launch(void* const* d_in, const int* in_sizes, int n_in,
                              void* d_out, int out_size)
{
    (void)in_sizes; (void)n_in; (void)out_size;
    const float* patches  = (const float*)d_in[0];
    const float* time_emb = (const float*)d_in[1];
    const float* Wqs = (const float*)d_in[2];
    const float* bqs = (const float*)d_in[3];
    const float* Wks = (const float*)d_in[4];
    const float* bks = (const float*)d_in[5];
    const float* Wvs = (const float*)d_in[6];
    const float* bvs = (const float*)d_in[7];
    const float* Wqt = (const float*)d_in[8];
    const float* bqt = (const float*)d_in[9];
    const float* Wkt = (const float*)d_in[10];
    const float* bkt = (const float*)d_in[11];
    const float* Wvt = (const float*)d_in[12];
    const float* bvt = (const float*)d_in[13];
    const float* Er  = (const float*)d_in[14];
    float* out = (float*)d_out;

    time_proj<<<dim3(Dm / 128, Bb), 128>>>(time_emb, Wqt, bqt, Wkt, bkt, Wvt, bvt);
    prep_patches<<<(Bb * Sq * Dm / 4) / 256, 256>>>(patches);
    prep_er<<<(Sq * HDm / 4) / 256, 256>>>(Er);
    prep_wt<<<dim3(Dm / 32, Dm / 32, 3), 256>>>(Wqs, Wks, Wvs);

    const int qkv_smem = 3 * STAGE2_B;  // 110592 -> 2 CTAs/SM
    cudaFuncSetAttribute(qkv_mma, cudaFuncAttributeMaxDynamicSharedMemorySize, qkv_smem);
    qkv_mma<<<dim3(Dm / 128, (Bb * Sq) / 128, 3), 256, qkv_smem>>>(bqs, bks, bvs);

    cudaFuncSetAttribute(attn_mma, cudaFuncAttributeMaxDynamicSharedMemorySize, ATTN_SMEM);
    attn_mma<<<dim3(Sq / 64, Hh, Bb), 256, ATTN_SMEM>>>(out);
}

// round 13
// speedup vs baseline: 5.6160x; 1.0288x over previous
#include <cuda_runtime.h>
#include <cuda_bf16.h>
#include <cuda_fp16.h>
#include <cstdint>
#include <cstddef>

#define Sq 1024
#define Dm 768
#define Hh 12
#define HDm 64
#define Bb 8
#define Tt 384
#define SCALE_F 0.125f

// ---------------- scratch (device globals; no allocation allowed) ----------
__device__ float g_T[3][Bb][Dm];                    // time q/k/v vectors
__device__ __half g_P16[(size_t)Bb * Sq * Dm];      // patches fp16
__device__ __half g_WT16[3][Dm][Dm];                // W^T fp16 [z][n][k]
__device__ __half g_Q16[(size_t)Bb * Sq * Dm];      // (qs+tq)*0.125  (fp16)
__device__ __half g_K16[(size_t)Bb * Sq * Dm];      // ks+tk  (fp16)
__device__ __half g_QS16[(size_t)Bb * Sq * Dm];     // qs*0.125 (no time, fp16)
__device__ __half g_V16[(size_t)Bb * Sq * Dm];      // vs+tv  (fp16)
__device__ __half g_Er16[Sq][HDm];

// ---------------- PTX helpers (baseline ISA: sm_80+) ------------------------
__device__ __forceinline__ uint32_t smem_u32(const void* p) {
    uint32_t a;
    asm("{ .reg .u64 t; cvta.to.shared.u64 t, %1; cvt.u32.u64 %0, t; }"
        : "=r"(a) : "l"(p));
    return a;
}
__device__ __forceinline__ void ldmx4(uint32_t* r, uint32_t addr) {
    asm volatile("ldmatrix.sync.aligned.m8n8.x4.shared.b16 {%0,%1,%2,%3}, [%4];"
                 : "=r"(r[0]), "=r"(r[1]), "=r"(r[2]), "=r"(r[3]) : "r"(addr));
}
__device__ __forceinline__ void ldmx4t(uint32_t* r, uint32_t addr) {
    asm volatile("ldmatrix.sync.aligned.m8n8.x4.trans.shared.b16 {%0,%1,%2,%3}, [%4];"
                 : "=r"(r[0]), "=r"(r[1]), "=r"(r[2]), "=r"(r[3]) : "r"(addr));
}
__device__ __forceinline__ void mma16816h(float* c, const uint32_t* a, const uint32_t* b) {
    asm volatile(
        "mma.sync.aligned.m16n8k16.row.col.f32.f16.f16.f32 "
        "{%0,%1,%2,%3}, {%4,%5,%6,%7}, {%8,%9}, {%0,%1,%2,%3};"
        : "+f"(c[0]), "+f"(c[1]), "+f"(c[2]), "+f"(c[3])
        : "r"(a[0]), "r"(a[1]), "r"(a[2]), "r"(a[3]), "r"(b[0]), "r"(b[1]));
}
#define CP16(dst, src) asm volatile("cp.async.cg.shared.global [%0], [%1], 16;" :: "r"(dst), "l"(src))
#define CP_COMMIT()    asm volatile("cp.async.commit_group;" ::: "memory")
#define CP_WAIT1()     asm volatile("cp.async.wait_group 1;" ::: "memory")
#define CP_WAIT0()     asm volatile("cp.async.wait_group 0;" ::: "memory")

#define KC 64
#define RSTR 72
#define TILE_B (128 * RSTR * 2)          // 18432 B per 128-row fp16 tile
#define STAGE2_B (2 * TILE_B)            // A, B = 36864 B (qkv single-pass)
#define DSTR 132

__device__ __forceinline__ uint32_t packh2(float x, float y) {
    __half2 hh = __floats2half2_rn(x, y);
    return *(uint32_t*)&hh;
}

// ---------------- kernel 1: time projections (parallelized) ----------------
__global__ void __launch_bounds__(128) time_proj(
    const float* __restrict__ time_emb,
    const float* __restrict__ Wqt, const float* __restrict__ bqt,
    const float* __restrict__ Wkt, const float* __restrict__ bkt,
    const float* __restrict__ Wvt, const float* __restrict__ bvt)
{
    const int b = blockIdx.y;
    const int n = blockIdx.x * 128 + threadIdx.x;
    __shared__ float te[Tt];
    for (int i = threadIdx.x; i < Tt; i += 128)
        te[i] = time_emb[b * Tt + i];
    __syncthreads();
    float aq = 0.f, ak = 0.f, av = 0.f;
    for (int t = 0; t < Tt; t++) {
        float x = te[t];
        aq += x * Wqt[t * Dm + n];
        ak += x * Wkt[t * Dm + n];
        av += x * Wvt[t * Dm + n];
    }
    g_T[0][b][n] = aq + bqt[n];
    g_T[1][b][n] = ak + bkt[n];
    g_T[2][b][n] = av + bvt[n];
}

// ---------------- preps --------------------------------------------------
__global__ void __launch_bounds__(256) prep_patches(const float* __restrict__ src)
{
    size_t i = (size_t)blockIdx.x * 256 + threadIdx.x;
    float4 v = ((const float4*)src)[i];
    uint32_t* H = (uint32_t*)g_P16;
    H[2 * i] = packh2(v.x, v.y);
    H[2 * i + 1] = packh2(v.z, v.w);
}

__global__ void __launch_bounds__(256) prep_er(const float* __restrict__ src)
{
    size_t i = (size_t)blockIdx.x * 256 + threadIdx.x;   // i < Sq*HDm/4
    float4 v = ((const float4*)src)[i];
    uint32_t* E = (uint32_t*)&g_Er16[0][0];
    E[2 * i] = packh2(v.x, v.y);
    E[2 * i + 1] = packh2(v.z, v.w);
}

__global__ void __launch_bounds__(256) prep_wt(
    const float* __restrict__ Wq, const float* __restrict__ Wk,
    const float* __restrict__ Wv)
{
    const int z = blockIdx.z;
    const float* __restrict__ W = (z == 0) ? Wq : (z == 1 ? Wk : Wv);
    __shared__ float s[32][33];
    const int n0 = blockIdx.x * 32, k0 = blockIdx.y * 32;
    const int tx = threadIdx.x & 31, ty = threadIdx.x >> 5;
    #pragma unroll
    for (int i = 0; i < 4; i++)
        s[ty + 8 * i][tx] = W[(size_t)(k0 + ty + 8 * i) * Dm + n0 + tx];
    __syncthreads();
    #pragma unroll
    for (int i = 0; i < 4; i++) {
        int n = n0 + ty + 8 * i, k = k0 + tx;
        g_WT16[z][n][k] = __float2half_rn(s[tx][ty + 8 * i]);
    }
}

// ---------------- microkernel: one Kc=64 chunk, single-pass fp16 -----------
__device__ __forceinline__ void mma_chunk1(uint32_t stage_base, int wm, int wn,
                                           int lane, float c[4][4][4])
{
    const uint32_t aRow = (uint32_t)(wm * 64 + (lane & 15));
    const uint32_t aColBase = (uint32_t)((lane >> 4) * 8);
    const uint32_t bRow = (uint32_t)(wn * 32 + ((lane >> 3) & 1) * 8 + (lane & 7));
    const uint32_t sA = stage_base;
    const uint32_t sB = stage_base + TILE_B;

    #pragma unroll
    for (int ks = 0; ks < 4; ks++) {
        const uint32_t kcol = (uint32_t)(ks * 16) + aColBase;
        uint32_t aa[4][4], bb[4][2];
        #pragma unroll
        for (int mt = 0; mt < 4; mt++) {
            uint32_t off = ((aRow + mt * 16) * RSTR + kcol) * 2;
            ldmx4(aa[mt], sA + off);
        }
        #pragma unroll
        for (int nt2 = 0; nt2 < 2; nt2++) {
            uint32_t off = ((bRow + nt2 * 16) * RSTR + kcol) * 2;
            uint32_t t[4];
            ldmx4(t, sB + off);
            bb[nt2 * 2][0] = t[0]; bb[nt2 * 2][1] = t[2];
            bb[nt2 * 2 + 1][0] = t[1]; bb[nt2 * 2 + 1][1] = t[3];
        }
        #pragma unroll
        for (int mt = 0; mt < 4; mt++)
            #pragma unroll
            for (int nt = 0; nt < 4; nt++)
                mma16816h(c[mt][nt], aa[mt], bb[nt]);
    }
}

// ---------------- kernel 2: QKV via mma.sync fp16 (3-stage, 2 CTA/SM) ------
__global__ void __launch_bounds__(256, 2) qkv_mma(
    const float* __restrict__ bq, const float* __restrict__ bk,
    const float* __restrict__ bv)
{
    extern __shared__ char sm[];
    const uint32_t smb = smem_u32(sm);
    const int z = blockIdx.z;
    const int n0 = blockIdx.x * 128, m0 = blockIdx.y * 128;
    const int tid = threadIdx.x;
    const int warp = tid >> 5, lane = tid & 31;
    const int wm = warp & 1, wn = warp >> 1;

    auto load_stage = [&](int chunk, int s) {
        const uint32_t st = smb + (uint32_t)s * STAGE2_B;
        const int k0 = chunk * KC;
        #pragma unroll
        for (int it = 0; it < 4; it++) {
            int i = tid + it * 256;
            int r = i >> 3, cc = i & 7;
            uint32_t doff = (uint32_t)(r * RSTR + cc * 8) * 2;
            CP16(st + doff, g_P16 + (size_t)(m0 + r) * Dm + k0 + cc * 8);
            CP16(st + TILE_B + doff, &g_WT16[z][n0 + r][k0 + cc * 8]);
        }
        CP_COMMIT();
    };

    float c[4][4][4] = {};

    load_stage(0, 0);
    load_stage(1, 1);
    for (int ch = 0; ch < 12; ch++) {
        if (ch < 10) CP_WAIT1(); else CP_WAIT0();
        __syncthreads();
        if (ch + 2 < 12) load_stage(ch + 2, (ch + 2) % 3);
        mma_chunk1(smb + (uint32_t)(ch % 3) * STAGE2_B, wm, wn, lane, c);
    }

    const float* bias = (z == 0) ? bq : (z == 1 ? bk : bv);
    const int lrow = lane >> 2, lcol = (lane & 3) * 2;
    #pragma unroll
    for (int mt = 0; mt < 4; mt++) {
        #pragma unroll
        for (int nt = 0; nt < 4; nt++) {
            const int col = n0 + wn * 32 + nt * 8 + lcol;
            const float bx = bias[col], by = bias[col + 1];
            #pragma unroll
            for (int hf = 0; hf < 2; hf++) {
                const int row = m0 + wm * 64 + mt * 16 + lrow + hf * 8;
                const int b = row >> 10;
                const float v0 = c[mt][nt][hf * 2 + 0] + bx;
                const float v1 = c[mt][nt][hf * 2 + 1] + by;
                const float t0 = g_T[z][b][col];
                const float t1 = g_T[z][b][col + 1];
                const size_t o = (size_t)row * Dm + col;
                if (z == 0) {
                    *(uint32_t*)&g_Q16[o] = packh2((v0 + t0) * SCALE_F,
                                                   (v1 + t1) * SCALE_F);
                    *(uint32_t*)&g_QS16[o] = packh2(v0 * SCALE_F, v1 * SCALE_F);
                } else if (z == 1) {
                    *(uint32_t*)&g_K16[o] = packh2(v0 + t0, v1 + t1);
                } else {
                    *(uint32_t*)&g_V16[o] = packh2(v0 + t0, v1 + t1);
                }
            }
        }
    }
}

// ---------------- kernel 3: fused flash attention + rel-bias (fp16) --------
// 256 threads (8 warps), 2 CTAs/SM. Warp = wp (16 q rows) x wh (32-col k-half).
// Diagonal bias layout. Schedule per iter (2 block syncs):
//   [top: CP_WAIT1+sync (kt>0)] QK -> bias -> softmax -> PV
//   [post-PV sync] dstrip(kt+1) -> loads(kv kt+2, er kt+3) -> commit
// dstrip(kt+1) is AFTER the post-PV sync so it cannot clobber Dd entries that
// slower warps are still reading in bias(kt). Prologue uses CP_WAIT0 so er(2)
// (slot 2) has landed before dstrip(-1) reads slot 2's er(-1)... (er(-1) is
// read first; both are waited, and er(-1) is in the EARLIER group; with both
// groups drained, slot 2 holds the LAST write = er(2)? No: er(-1)->slot 2 and
// er(2)->slot 2 would still collide. So er(2) is NOT preloaded; instead
// dstrip(-1)+dstrip(0) run on slots 2,0; er(2)->slot 2 is loaded at iter-0
// bottom (after prologue dstrips are done and sync'd).
#define aQ    0u            /* 64x72 fp16 = 9216 */
#define aQS   9216u         /* 80x72 fp16 = 11520 */
#define aKV   20736u        /* stage: K16 | V16 each 9216 = 18432; x2 */
#define aEr   57600u        /* 192x72 fp16 = 27648 */
#define aD    85248u        /* 64x132 fp16 = 16896 */
#define aRed  102408u       /* sM 128 f32 + sL 128 f32 */
#define ATTN_SMEM 103432
#define OSTR 68

__global__ void __launch_bounds__(256, 2) attn_mma(float* __restrict__ out)
{
    extern __shared__ char sm[];
    const uint32_t smb = smem_u32(sm);
    const int q0 = blockIdx.x * 64;
    const int h = blockIdx.y, b = blockIdx.z;
    const int tid = threadIdx.x, warp = tid >> 5, lane = tid & 31;
    const int wp = warp & 3, wh = warp >> 2;
    __half* Dd = (__half*)(sm + aD);
    float* sM = (float*)(sm + aRed);
    float* sL = sM + 128;

    auto load_kv = [&](int kt, int s) {
        const uint32_t st = smb + aKV + (uint32_t)s * 18432u;
        const size_t krow0 = ((size_t)(b * Sq + kt * 64)) * Dm + h * HDm;
        #pragma unroll
        for (int it = 0; it < 2; it++) {
            int i = tid + it * 256;
            int r = i >> 3, cc = i & 7;
            uint32_t doff = (uint32_t)(r * RSTR + cc * 8) * 2;
            size_t src = krow0 + (size_t)r * Dm + cc * 8;
            CP16(st + doff, g_K16 + src);
            CP16(st + 9216u + doff, g_V16 + src);
        }
    };
    auto load_er = [&](int s) {
        const int estart = s * 64 - q0;
        const int slot = ((s + 3) % 3) * 64;
        #pragma unroll
        for (int it = 0; it < 2; it++) {
            int i = tid + it * 256;
            int r = i >> 3, cc = i & 7;
            int e = estart + r;
            int t = (e <= 0) ? (Sq - 1 + e) : (e - 2);
            if (t < 0) t = 0; if (t > Sq - 1) t = Sq - 1;
            uint32_t doff = (uint32_t)((slot + r) * RSTR + cc * 8) * 2;
            CP16(smb + aEr + doff, &g_Er16[t][cc * 8]);
        }
    };
    auto do_dstrip = [&](int s) {
        const int base = s * 64 - q0;
        const uint32_t erow0 = (uint32_t)(((s + 3) % 3) * 64);
        const int par = warp & 1;
        uint32_t eb[4][2];
        const uint32_t nrow = erow0 +
            (uint32_t)((warp & 6) * 8 + ((lane >> 3) & 1) * 8 + (lane & 7));
        #pragma unroll
        for (int ks = 0; ks < 4; ks++) {
            uint32_t addr = smb + aEr +
                (nrow * RSTR + (uint32_t)(ks * 16 + (lane >> 4) * 8)) * 2;
            uint32_t t4[4];
            ldmx4(t4, addr);
            eb[ks][0] = t4[par]; eb[ks][1] = t4[2 + par];
        }
        const int e0 = base + warp * 8 + (lane & 3) * 2;  // even
        #pragma unroll
        for (int mt = 0; mt < 5; mt++) {
            uint32_t sa[4][4];
            const uint32_t arow = (uint32_t)(mt * 16 + (lane & 15));
            #pragma unroll
            for (int ks = 0; ks < 4; ks++) {
                uint32_t addr = smb + aQS +
                    (arow * RSTR + (uint32_t)(ks * 16 + (lane >> 4) * 8)) * 2;
                ldmx4(sa[ks], addr);
            }
            float cc4[4] = {};
            #pragma unroll
            for (int ks = 0; ks < 4; ks++)
                mma16816h(cc4, sa[ks], eb[ks]);
            const int p = (e0 >= 2) ? 1 : 0;
            #pragma unroll
            for (int rr = 0; rr < 2; rr++) {
                const int r = mt * 16 + (lane >> 2) + rr * 8;
                const int q_dst = r - p;
                if (q_dst >= 0 && q_dst < 64) {
                    const int j0 = (e0 + q_dst) & 127;
                    const int j1 = (e0 + 1 + q_dst) & 127;
                    Dd[q_dst * DSTR + j0] = __float2half_rn(cc4[rr * 2]);
                    Dd[q_dst * DSTR + j1] =
                        (e0 + 1 == 1) ? __float2half_rn(0.f)
                                      : __float2half_rn(cc4[rr * 2 + 1]);
                }
            }
        }
    };

    // ---- prologue loads: G0 = {Q, QS, er(-1,0,1), kv0}, G1 = {kv1} --------
    {
        const size_t qrow0 = ((size_t)(b * Sq + q0)) * Dm + h * HDm;
        #pragma unroll
        for (int it = 0; it < 2; it++) {
            int i = tid + it * 256;
            int r = i >> 3, cc = i & 7;
            uint32_t doff = (uint32_t)(r * RSTR + cc * 8) * 2;
            CP16(smb + aQ + doff, g_Q16 + qrow0 + (size_t)r * Dm + cc * 8);
        }
        #pragma unroll
        for (int it = 0; it < 3; it++) {
            int i = tid + it * 256;
            if (i < 640) {
                int r = i >> 3, cc = i & 7;
                int rr = q0 + r; if (rr > Sq - 1) rr = Sq - 1;
                uint32_t doff = (uint32_t)(r * RSTR + cc * 8) * 2;
                CP16(smb + aQS + doff,
                     g_QS16 + ((size_t)(b * Sq + rr)) * Dm + h * HDm + cc * 8);
            }
        }
        load_er(-1); load_er(0); load_er(1);
        load_kv(0, 0);
        CP_COMMIT();                 // G0
        load_kv(1, 1);
        CP_COMMIT();                 // G1
    }

    CP_WAIT1();
    __syncthreads();                 // G0 visible (Q, QS, er(-1,0,1), kv0)

    // ---- hoist Q fragments (loop-invariant) ----
    uint32_t qa[4][4];
    {
        const uint32_t arow = (uint32_t)(wp * 16 + (lane & 15));
        #pragma unroll
        for (int ks = 0; ks < 4; ks++) {
            uint32_t addr = smb + aQ +
                (arow * RSTR + (uint32_t)(ks * 16 + (lane >> 4) * 8)) * 2;
            ldmx4(qa[ks], addr);
        }
    }

    // ---- prologue D strips {-1, 0} (slots 2, 0; er(2) not yet loaded) -----
    do_dstrip(-1);
    do_dstrip(0);
    __syncthreads();                 // Dd + all prologue dstrip reads done

    float m_[2] = {-1e30f, -1e30f}, l_[2] = {0.f, 0.f};
    float co[8][4] = {};
    const int row16 = (lane >> 2);

    for (int kt = 0; kt < 16; kt++) {
        const int s = kt & 1;
        const int d0 = kt * 64 - q0;
        if (kt > 0) { CP_WAIT1(); __syncthreads(); }  // KV(kt), Er(kt+1), Dd(kt)

        // ---- QK^T: fp16 1-pass, 16 q rows x 32 k cols per warp ----
        float c[4][4] = {};
        {
            const uint32_t stK = smb + aKV + (uint32_t)s * 18432u;
            #pragma unroll
            for (int ks = 0; ks < 4; ks++) {
                uint32_t bh[4][2];
                #pragma unroll
                for (int pp = 0; pp < 2; pp++) {
                    uint32_t nrow = (uint32_t)(wh * 32 + pp * 16 +
                                    ((lane >> 3) & 1) * 8 + (lane & 7));
                    uint32_t addr = stK +
                        (nrow * RSTR + (uint32_t)(ks * 16 + (lane >> 4) * 8)) * 2;
                    uint32_t t4[4];
                    ldmx4(t4, addr);
                    bh[pp * 2][0] = t4[0]; bh[pp * 2][1] = t4[2];
                    bh[pp * 2 + 1][0] = t4[1]; bh[pp * 2 + 1][1] = t4[3];
                }
                #pragma unroll
                for (int nt = 0; nt < 4; nt++)
                    mma16816h(c[nt], qa[ks], bh[nt]);
            }
        }

        // ---- bias add (diagonal; Dd strips kt-1,kt ready via top sync) ----
        float mloc[2] = {-1e30f, -1e30f};
        #pragma unroll
        for (int hf = 0; hf < 2; hf++) {
            const int q_loc = wp * 16 + row16 + hf * 8;
            const uint32_t rbase = (uint32_t)(q_loc * DSTR);
            #pragma unroll
            for (int nt = 0; nt < 4; nt++) {
                const int col = wh * 32 + nt * 8 + (lane & 3) * 2;
                const int idx = (d0 + col) & 127;        // even -> aligned
                __half2 b2 = *(__half2*)&Dd[rbase + idx];
                float2 bf = __half22float2(b2);
                float sv0 = c[nt][hf * 2 + 0] + bf.x;
                float sv1 = c[nt][hf * 2 + 1] + bf.y;
                c[nt][hf * 2 + 0] = sv0;
                c[nt][hf * 2 + 1] = sv1;
                mloc[hf] = fmaxf(mloc[hf], fmaxf(sv0, sv1));
            }
        }
        float corr[2], psum[2] = {0.f, 0.f};
        #pragma unroll
        for (int hf = 0; hf < 2; hf++) {
            mloc[hf] = fmaxf(mloc[hf], __shfl_xor_sync(0xffffffffu, mloc[hf], 1));
            mloc[hf] = fmaxf(mloc[hf], __shfl_xor_sync(0xffffffffu, mloc[hf], 2));
            float mn = fmaxf(m_[hf], mloc[hf]);
            corr[hf] = __expf(m_[hf] - mn);
            m_[hf] = mn;
        }
        #pragma unroll
        for (int nt = 0; nt < 4; nt++) {
            #pragma unroll
            for (int k4 = 0; k4 < 4; k4++) {
                const int hf = k4 >> 1;
                float p = __expf(c[nt][k4] - m_[hf]);
                c[nt][k4] = p;
                psum[hf] += p;
            }
        }
        #pragma unroll
        for (int hf = 0; hf < 2; hf++) {
            psum[hf] += __shfl_xor_sync(0xffffffffu, psum[hf], 1);
            psum[hf] += __shfl_xor_sync(0xffffffffu, psum[hf], 2);
            l_[hf] = l_[hf] * corr[hf] + psum[hf];
        }
        #pragma unroll
        for (int nt = 0; nt < 8; nt++) {
            co[nt][0] *= corr[0]; co[nt][1] *= corr[0];
            co[nt][2] *= corr[1]; co[nt][3] *= corr[1];
        }

        // ---- PV: Ph(fp16) x V(fp16), 1 pass ----
        {
            const uint32_t stV = smb + aKV + (uint32_t)s * 18432u + 9216u;
            #pragma unroll
            for (int ktk = 0; ktk < 2; ktk++) {
                uint32_t pha[4];
                #pragma unroll
                for (int sub = 0; sub < 2; sub++)
                    #pragma unroll
                    for (int h2 = 0; h2 < 2; h2++)
                        pha[h2 + sub * 2] = packh2(c[2 * ktk + sub][h2 * 2],
                                                   c[2 * ktk + sub][h2 * 2 + 1]);
                uint32_t vb[8][2];
                #pragma unroll
                for (int pp = 0; pp < 4; pp++) {
                    uint32_t krow = (uint32_t)(wh * 32 + ktk * 16 +
                                   (lane & 7) + ((lane >> 3) & 1) * 8);
                    uint32_t ncol = (uint32_t)(pp * 16 + (lane >> 4) * 8);
                    uint32_t addr = stV + (krow * RSTR + ncol) * 2;
                    uint32_t t4[4];
                    ldmx4t(t4, addr);
                    vb[pp * 2][0] = t4[0]; vb[pp * 2][1] = t4[1];
                    vb[pp * 2 + 1][0] = t4[2]; vb[pp * 2 + 1][1] = t4[3];
                }
                #pragma unroll
                for (int nt = 0; nt < 8; nt++)
                    mma16816h(co[nt], pha, vb[nt]);
            }
        }

        __syncthreads();   // ALL bias(kt)+PV(kt) reads done before dstrip/loads

        // ---- D strip kt+1: safe now (writes only touch data no longer read)
        if (kt + 1 <= 15) do_dstrip(kt + 1);

        if (kt + 2 < 16) load_kv(kt + 2, s);
        if (kt + 2 == 2) load_er(2);            // er(2): slot 2 free after prologue dstrips
        if (kt + 3 <= 15) load_er(kt + 3);
        CP_COMMIT();
    }

    // ---- merge the two k-half softmax states, write out ----
    if ((lane & 3) == 0) {
        #pragma unroll
        for (int hf = 0; hf < 2; hf++) {
            sM[wh * 64 + wp * 16 + row16 + hf * 8] = m_[hf];
            sL[wh * 64 + wp * 16 + row16 + hf * 8] = l_[hf];
        }
    }
    __syncthreads();
    float myc[2], inv[2];
    #pragma unroll
    for (int hf = 0; hf < 2; hf++) {
        const int rowi = wp * 16 + row16 + hf * 8;
        float mo = sM[(wh ^ 1) * 64 + rowi];
        float lo2 = sL[(wh ^ 1) * 64 + rowi];
        float mstar = fmaxf(m_[hf], mo);
        myc[hf] = __expf(m_[hf] - mstar);
        float otc = __expf(mo - mstar);
        inv[hf] = 1.0f / (l_[hf] * myc[hf] + lo2 * otc);
    }
    __syncthreads();
    float* sOut = (float*)(sm + aKV);
    if (wh == 1) {
        #pragma unroll
        for (int hf = 0; hf < 2; hf++) {
            const int row = wp * 16 + row16 + hf * 8;
            #pragma unroll
            for (int nt = 0; nt < 8; nt++) {
                const int col = nt * 8 + (lane & 3) * 2;
                *(float2*)&sOut[row * OSTR + col] =
                    make_float2(co[nt][hf * 2] * myc[hf],
                                co[nt][hf * 2 + 1] * myc[hf]);
            }
        }
    }
    __syncthreads();
    if (wh == 0) {
        #pragma unroll
        for (int hf = 0; hf < 2; hf++) {
            const int row = wp * 16 + row16 + hf * 8;
            const size_t ob = ((size_t)(b * Sq + q0 + row)) * Dm + h * HDm;
            #pragma unroll
            for (int nt = 0; nt < 8; nt++) {
                const int col = nt * 8 + (lane & 3) * 2;
                float2 pr = *(float2*)&sOut[row * OSTR + col];
                *(float2*)&out[ob + col] =
                    make_float2((co[nt][hf * 2] * myc[hf] + pr.x) * inv[hf],
                                (co[nt][hf * 2 + 1] * myc[hf] + pr.y) * inv[hf]);
            }
        }
    }
}

// ---------------- launch ----------------------------------------------------
extern "C" void kernel_launch(void* const* d_in, const int* in_sizes, int n_in,
                              void* d_out, int out_size)
{
    (void)in_sizes; (void)n_in; (void)out_size;
    const float* patches  = (const float*)d_in[0];
    const float* time_emb = (const float*)d_in[1];
    const float* Wqs = (const float*)d_in[2];
    const float* bqs = (const float*)d_in[3];
    const float* Wks = (const float*)d_in[4];
    const float* bks = (const float*)d_in[5];
    const float* Wvs = (const float*)d_in[6];
    const float* bvs = (const float*)d_in[7];
    const float* Wqt = (const float*)d_in[8];
    const float* bqt = (const float*)d_in[9];
    const float* Wkt = (const float*)d_in[10];
    const float* bkt = (const float*)d_in[11];
    const float* Wvt = (const float*)d_in[12];
    const float* bvt = (const float*)d_in[13];
    const float* Er  = (const float*)d_in[14];
    float* out = (float*)d_out;

    time_proj<<<dim3(Dm / 128, Bb), 128>>>(time_emb, Wqt, bqt, Wkt, bkt, Wvt, bvt);
    prep_patches<<<(Bb * Sq * Dm / 4) / 256, 256>>>(patches);
    prep_er<<<(Sq * HDm / 4) / 256, 256>>>(Er);
    prep_wt<<<dim3(Dm / 32, Dm / 32, 3), 256>>>(Wqs, Wks, Wvs);

    const int qkv_smem = 3 * STAGE2_B;  // 110592 -> 2 CTAs/SM
    cudaFuncSetAttribute(qkv_mma, cudaFuncAttributeMaxDynamicSharedMemorySize, qkv_smem);
    qkv_mma<<<dim3(Dm / 128, (Bb * Sq) / 128, 3), 256, qkv_smem>>>(bqs, bks, bvs);

    cudaFuncSetAttribute(attn_mma, cudaFuncAttributeMaxDynamicSharedMemorySize, ATTN_SMEM);
    attn_mma<<<dim3(Sq / 64, Hh, Bb), 256, ATTN_SMEM>>>(out);
}

// round 14
// speedup vs baseline: 6.6194x; 1.1787x over previous
#include <cuda_runtime.h>
#include <cuda_bf16.h>
#include <cuda_fp16.h>
#include <cstdint>
#include <cstddef>

#define Sq 1024
#define Dm 768
#define Hh 12
#define HDm 64
#define Bb 8
#define Tt 384
#define SCALE_L2E 0.18033688011112042f   /* 0.125 * log2(e) */

// ---------------- scratch (device globals; no allocation allowed) ----------
__device__ float g_T[3][Bb][Dm];                    // time q/k/v vectors
__device__ __half g_P16[(size_t)Bb * Sq * Dm];      // patches fp16
__device__ __half g_WT16[3][Dm][Dm];                // W^T fp16 [z][n][k]
__device__ __half g_Q16[(size_t)Bb * Sq * Dm];      // (qs+tq)*0.125*log2e (fp16)
__device__ __half g_K16[(size_t)Bb * Sq * Dm];      // ks+tk  (fp16)
__device__ __half g_QS16[(size_t)Bb * Sq * Dm];     // qs*0.125*log2e (fp16)
__device__ __half g_V16[(size_t)Bb * Sq * Dm];      // vs+tv  (fp16)
__device__ __half g_Er16[Sq][HDm];

// ---------------- PTX helpers (baseline ISA: sm_80+) ------------------------
__device__ __forceinline__ uint32_t smem_u32(const void* p) {
    uint32_t a;
    asm("{ .reg .u64 t; cvta.to.shared.u64 t, %1; cvt.u32.u64 %0, t; }"
        : "=r"(a) : "l"(p));
    return a;
}
__device__ __forceinline__ void ldmx4(uint32_t* r, uint32_t addr) {
    asm volatile("ldmatrix.sync.aligned.m8n8.x4.shared.b16 {%0,%1,%2,%3}, [%4];"
                 : "=r"(r[0]), "=r"(r[1]), "=r"(r[2]), "=r"(r[3]) : "r"(addr));
}
__device__ __forceinline__ void ldmx4t(uint32_t* r, uint32_t addr) {
    asm volatile("ldmatrix.sync.aligned.m8n8.x4.trans.shared.b16 {%0,%1,%2,%3}, [%4];"
                 : "=r"(r[0]), "=r"(r[1]), "=r"(r[2]), "=r"(r[3]) : "r"(addr));
}
__device__ __forceinline__ void mma16816h(float* c, const uint32_t* a, const uint32_t* b) {
    asm volatile(
        "mma.sync.aligned.m16n8k16.row.col.f32.f16.f16.f32 "
        "{%0,%1,%2,%3}, {%4,%5,%6,%7}, {%8,%9}, {%0,%1,%2,%3};"
        : "+f"(c[0]), "+f"(c[1]), "+f"(c[2]), "+f"(c[3])
        : "r"(a[0]), "r"(a[1]), "r"(a[2]), "r"(a[3]), "r"(b[0]), "r"(b[1]));
}
__device__ __forceinline__ float ex2f(float x) {
    float y; asm("ex2.approx.f32 %0, %1;" : "=f"(y) : "f"(x)); return y;
}
#define CP16(dst, src) asm volatile("cp.async.cg.shared.global [%0], [%1], 16;" :: "r"(dst), "l"(src))
#define CP_COMMIT()    asm volatile("cp.async.commit_group;" ::: "memory")
#define CP_WAIT1()     asm volatile("cp.async.wait_group 1;" ::: "memory")
#define CP_WAIT0()     asm volatile("cp.async.wait_group 0;" ::: "memory")

#define KC 64
#define RSTR 72
#define TILE_B (128 * RSTR * 2)          // 18432 B per 128-row fp16 tile
#define STAGE2_B (2 * TILE_B)            // A, B = 36864 B (qkv single-pass)
#define DSTR 132

__device__ __forceinline__ uint32_t packh2(float x, float y) {
    __half2 hh = __floats2half2_rn(x, y);
    return *(uint32_t*)&hh;
}

// ---------------- kernel 1: time projections (parallelized) ----------------
__global__ void __launch_bounds__(128) time_proj(
    const float* __restrict__ time_emb,
    const float* __restrict__ Wqt, const float* __restrict__ bqt,
    const float* __restrict__ Wkt, const float* __restrict__ bkt,
    const float* __restrict__ Wvt, const float* __restrict__ bvt)
{
    const int b = blockIdx.y;
    const int n = blockIdx.x * 128 + threadIdx.x;
    __shared__ float te[Tt];
    for (int i = threadIdx.x; i < Tt; i += 128)
        te[i] = time_emb[b * Tt + i];
    __syncthreads();
    float aq = 0.f, ak = 0.f, av = 0.f;
    for (int t = 0; t < Tt; t++) {
        float x = te[t];
        aq += x * Wqt[t * Dm + n];
        ak += x * Wkt[t * Dm + n];
        av += x * Wvt[t * Dm + n];
    }
    g_T[0][b][n] = aq + bqt[n];
    g_T[1][b][n] = ak + bkt[n];
    g_T[2][b][n] = av + bvt[n];
}

// ---------------- preps --------------------------------------------------
__global__ void __launch_bounds__(256) prep_patches(const float* __restrict__ src)
{
    size_t i = (size_t)blockIdx.x * 256 + threadIdx.x;
    float4 v = ((const float4*)src)[i];
    uint32_t* H = (uint32_t*)g_P16;
    H[2 * i] = packh2(v.x, v.y);
    H[2 * i + 1] = packh2(v.z, v.w);
}

__global__ void __launch_bounds__(256) prep_er(const float* __restrict__ src)
{
    size_t i = (size_t)blockIdx.x * 256 + threadIdx.x;   // i < Sq*HDm/4
    float4 v = ((const float4*)src)[i];
    uint32_t* E = (uint32_t*)&g_Er16[0][0];
    E[2 * i] = packh2(v.x, v.y);
    E[2 * i + 1] = packh2(v.z, v.w);
}

__global__ void __launch_bounds__(256) prep_wt(
    const float* __restrict__ Wq, const float* __restrict__ Wk,
    const float* __restrict__ Wv)
{
    const int z = blockIdx.z;
    const float* __restrict__ W = (z == 0) ? Wq : (z == 1 ? Wk : Wv);
    __shared__ float s[32][33];
    const int n0 = blockIdx.x * 32, k0 = blockIdx.y * 32;
    const int tx = threadIdx.x & 31, ty = threadIdx.x >> 5;
    #pragma unroll
    for (int i = 0; i < 4; i++)
        s[ty + 8 * i][tx] = W[(size_t)(k0 + ty + 8 * i) * Dm + n0 + tx];
    __syncthreads();
    #pragma unroll
    for (int i = 0; i < 4; i++) {
        int n = n0 + ty + 8 * i, k = k0 + tx;
        g_WT16[z][n][k] = __float2half_rn(s[tx][ty + 8 * i]);
    }
}

// ---------------- microkernel: one Kc=64 chunk, single-pass fp16 -----------
__device__ __forceinline__ void mma_chunk1(uint32_t stage_base, int wm, int wn,
                                           int lane, float c[4][4][4])
{
    const uint32_t aRow = (uint32_t)(wm * 64 + (lane & 15));
    const uint32_t aColBase = (uint32_t)((lane >> 4) * 8);
    const uint32_t bRow = (uint32_t)(wn * 32 + ((lane >> 3) & 1) * 8 + (lane & 7));
    const uint32_t sA = stage_base;
    const uint32_t sB = stage_base + TILE_B;

    #pragma unroll
    for (int ks = 0; ks < 4; ks++) {
        const uint32_t kcol = (uint32_t)(ks * 16) + aColBase;
        uint32_t aa[4][4], bb[4][2];
        #pragma unroll
        for (int mt = 0; mt < 4; mt++) {
            uint32_t off = ((aRow + mt * 16) * RSTR + kcol) * 2;
            ldmx4(aa[mt], sA + off);
        }
        #pragma unroll
        for (int nt2 = 0; nt2 < 2; nt2++) {
            uint32_t off = ((bRow + nt2 * 16) * RSTR + kcol) * 2;
            uint32_t t[4];
            ldmx4(t, sB + off);
            bb[nt2 * 2][0] = t[0]; bb[nt2 * 2][1] = t[2];
            bb[nt2 * 2 + 1][0] = t[1]; bb[nt2 * 2 + 1][1] = t[3];
        }
        #pragma unroll
        for (int mt = 0; mt < 4; mt++)
            #pragma unroll
            for (int nt = 0; nt < 4; nt++)
                mma16816h(c[mt][nt], aa[mt], bb[nt]);
    }
}

// ---------------- kernel 2: QKV via mma.sync fp16 (3-stage, 2 CTA/SM) ------
__global__ void __launch_bounds__(256, 2) qkv_mma(
    const float* __restrict__ bq, const float* __restrict__ bk,
    const float* __restrict__ bv)
{
    extern __shared__ char sm[];
    const uint32_t smb = smem_u32(sm);
    const int z = blockIdx.z;
    const int n0 = blockIdx.x * 128, m0 = blockIdx.y * 128;
    const int tid = threadIdx.x;
    const int warp = tid >> 5, lane = tid & 31;
    const int wm = warp & 1, wn = warp >> 1;

    auto load_stage = [&](int chunk, int s) {
        const uint32_t st = smb + (uint32_t)s * STAGE2_B;
        const int k0 = chunk * KC;
        #pragma unroll
        for (int it = 0; it < 4; it++) {
            int i = tid + it * 256;
            int r = i >> 3, cc = i & 7;
            uint32_t doff = (uint32_t)(r * RSTR + cc * 8) * 2;
            CP16(st + doff, g_P16 + (size_t)(m0 + r) * Dm + k0 + cc * 8);
            CP16(st + TILE_B + doff, &g_WT16[z][n0 + r][k0 + cc * 8]);
        }
        CP_COMMIT();
    };

    float c[4][4][4] = {};

    load_stage(0, 0);
    load_stage(1, 1);
    for (int ch = 0; ch < 12; ch++) {
        if (ch < 10) CP_WAIT1(); else CP_WAIT0();
        __syncthreads();
        if (ch + 2 < 12) load_stage(ch + 2, (ch + 2) % 3);
        mma_chunk1(smb + (uint32_t)(ch % 3) * STAGE2_B, wm, wn, lane, c);
    }

    const float* bias = (z == 0) ? bq : (z == 1 ? bk : bv);
    const int lrow = lane >> 2, lcol = (lane & 3) * 2;
    #pragma unroll
    for (int mt = 0; mt < 4; mt++) {
        #pragma unroll
        for (int nt = 0; nt < 4; nt++) {
            const int col = n0 + wn * 32 + nt * 8 + lcol;
            const float bx = bias[col], by = bias[col + 1];
            #pragma unroll
            for (int hf = 0; hf < 2; hf++) {
                const int row = m0 + wm * 64 + mt * 16 + lrow + hf * 8;
                const int b = row >> 10;
                const float v0 = c[mt][nt][hf * 2 + 0] + bx;
                const float v1 = c[mt][nt][hf * 2 + 1] + by;
                const float t0 = g_T[z][b][col];
                const float t1 = g_T[z][b][col + 1];
                const size_t o = (size_t)row * Dm + col;
                if (z == 0) {
                    *(uint32_t*)&g_Q16[o] = packh2((v0 + t0) * SCALE_L2E,
                                                   (v1 + t1) * SCALE_L2E);
                    *(uint32_t*)&g_QS16[o] = packh2(v0 * SCALE_L2E, v1 * SCALE_L2E);
                } else if (z == 1) {
                    *(uint32_t*)&g_K16[o] = packh2(v0 + t0, v1 + t1);
                } else {
                    *(uint32_t*)&g_V16[o] = packh2(v0 + t0, v1 + t1);
                }
            }
        }
    }
}

// ---------------- kernel 3: fused flash attention + rel-bias (fp16) --------
// 256 threads (8 warps), 2 CTAs/SM. Warp = wp (16 q rows) x wh (32-col k-half).
// Diagonal bias layout, log2-domain softmax (scale folded into Q/QS).
// D strips: strip s == blockIdx.x contains e=1 -> mixed path (per-row shift,
// e==1 zeroing). All other strips have uniform shift p = (s > bx) and use the
// transposed formulation O[e][q] = Er_strip x QS(rows q+p): 16 MMAs, 12 ldsm.
#define aQ    0u            /* 64x72 fp16 = 9216 */
#define aQS   9216u         /* 80x72 fp16 = 11520 */
#define aKV   20736u        /* stage: K16 | V16 each 9216 = 18432; x2 */
#define aEr   57600u        /* 192x72 fp16 = 27648 */
#define aD    85248u        /* 64x132 fp16 = 16896 */
#define aRed  102408u       /* sM 128 f32 + sL 128 f32 */
#define ATTN_SMEM 103432
#define OSTR 68

__global__ void __launch_bounds__(256, 2) attn_mma(float* __restrict__ out)
{
    extern __shared__ char sm[];
    const uint32_t smb = smem_u32(sm);
    const int bx = blockIdx.x;
    const int q0 = bx * 64;
    const int h = blockIdx.y, b = blockIdx.z;
    const int tid = threadIdx.x, warp = tid >> 5, lane = tid & 31;
    const int wp = warp & 3, wh = warp >> 2;
    __half* Dd = (__half*)(sm + aD);
    float* sM = (float*)(sm + aRed);
    float* sL = sM + 128;

    auto load_kv = [&](int kt, int s) {
        const uint32_t st = smb + aKV + (uint32_t)s * 18432u;
        const size_t krow0 = ((size_t)(b * Sq + kt * 64)) * Dm + h * HDm;
        #pragma unroll
        for (int it = 0; it < 2; it++) {
            int i = tid + it * 256;
            int r = i >> 3, cc = i & 7;
            uint32_t doff = (uint32_t)(r * RSTR + cc * 8) * 2;
            size_t src = krow0 + (size_t)r * Dm + cc * 8;
            CP16(st + doff, g_K16 + src);
            CP16(st + 9216u + doff, g_V16 + src);
        }
    };
    auto load_er = [&](int s) {
        const int estart = s * 64 - q0;
        const int slot = ((s + 3) % 3) * 64;
        #pragma unroll
        for (int it = 0; it < 2; it++) {
            int i = tid + it * 256;
            int r = i >> 3, cc = i & 7;
            int e = estart + r;
            int t = (e <= 0) ? (Sq - 1 + e) : (e - 2);
            if (t < 0) t = 0; if (t > Sq - 1) t = Sq - 1;
            uint32_t doff = (uint32_t)((slot + r) * RSTR + cc * 8) * 2;
            CP16(smb + aEr + doff, &g_Er16[t][cc * 8]);
        }
    };
    // mixed strip (contains e=1): old formulation, per-row shift + zeroing
    auto do_dstrip_m = [&](int s) {
        const int base = s * 64 - q0;
        const uint32_t erow0 = (uint32_t)(((s + 3) % 3) * 64);
        const int par = warp & 1;
        uint32_t eb[4][2];
        const uint32_t nrow = erow0 +
            (uint32_t)((warp & 6) * 8 + ((lane >> 3) & 1) * 8 + (lane & 7));
        #pragma unroll
        for (int ks = 0; ks < 4; ks++) {
            uint32_t addr = smb + aEr +
                (nrow * RSTR + (uint32_t)(ks * 16 + (lane >> 4) * 8)) * 2;
            uint32_t t4[4];
            ldmx4(t4, addr);
            eb[ks][0] = t4[par]; eb[ks][1] = t4[2 + par];
        }
        const int e0 = base + warp * 8 + (lane & 3) * 2;  // even
        #pragma unroll
        for (int mt = 0; mt < 5; mt++) {
            uint32_t sa[4][4];
            const uint32_t arow = (uint32_t)(mt * 16 + (lane & 15));
            #pragma unroll
            for (int ks = 0; ks < 4; ks++) {
                uint32_t addr = smb + aQS +
                    (arow * RSTR + (uint32_t)(ks * 16 + (lane >> 4) * 8)) * 2;
                ldmx4(sa[ks], addr);
            }
            float cc4[4] = {};
            #pragma unroll
            for (int ks = 0; ks < 4; ks++)
                mma16816h(cc4, sa[ks], eb[ks]);
            const int p = (e0 >= 2) ? 1 : 0;
            #pragma unroll
            for (int rr = 0; rr < 2; rr++) {
                const int r = mt * 16 + (lane >> 2) + rr * 8;
                const int q_dst = r - p;
                if (q_dst >= 0 && q_dst < 64) {
                    const int j0 = (e0 + q_dst) & 127;
                    const int j1 = (e0 + 1 + q_dst) & 127;
                    Dd[q_dst * DSTR + j0] = __float2half_rn(cc4[rr * 2]);
                    Dd[q_dst * DSTR + j1] =
                        (e0 + 1 == 1) ? __float2half_rn(0.f)
                                      : __float2half_rn(cc4[rr * 2 + 1]);
                }
            }
        }
    };
    // uniform strip: O[e][q] = Er_strip(64 rows) x QS(rows q+p); store direct
    auto do_dstrip_u = [&](int s, int p) {
        const int estart = s * 64 - q0;
        const uint32_t erow0 = (uint32_t)(((s + 3) % 3) * 64);
        uint32_t ea[4][4];
        {
            const uint32_t arow = erow0 + (uint32_t)(wp * 16 + (lane & 15));
            #pragma unroll
            for (int ks = 0; ks < 4; ks++) {
                uint32_t addr = smb + aEr +
                    (arow * RSTR + (uint32_t)(ks * 16 + (lane >> 4) * 8)) * 2;
                ldmx4(ea[ks], addr);
            }
        }
        float c4[4][4] = {};
        #pragma unroll
        for (int ks = 0; ks < 4; ks++) {
            uint32_t bb[4][2];
            #pragma unroll
            for (int pp = 0; pp < 2; pp++) {
                uint32_t nrow = (uint32_t)(p + wh * 32 + pp * 16 +
                                ((lane >> 3) & 1) * 8 + (lane & 7));
                uint32_t addr = smb + aQS +
                    (nrow * RSTR + (uint32_t)(ks * 16 + (lane >> 4) * 8)) * 2;
                uint32_t t4[4];
                ldmx4(t4, addr);
                bb[pp * 2][0] = t4[0]; bb[pp * 2][1] = t4[2];
                bb[pp * 2 + 1][0] = t4[1]; bb[pp * 2 + 1][1] = t4[3];
            }
            #pragma unroll
            for (int nt = 0; nt < 4; nt++)
                mma16816h(c4[nt], ea[ks], bb[nt]);
        }
        #pragma unroll
        for (int nt = 0; nt < 4; nt++) {
            #pragma unroll
            for (int hf = 0; hf < 2; hf++) {
                const int e_abs = estart + wp * 16 + (lane >> 2) + hf * 8;
                const int qb = wh * 32 + nt * 8 + (lane & 3) * 2;
                Dd[qb * DSTR + ((e_abs + qb) & 127)] =
                    __float2half_rn(c4[nt][hf * 2]);
                Dd[(qb + 1) * DSTR + ((e_abs + qb + 1) & 127)] =
                    __float2half_rn(c4[nt][hf * 2 + 1]);
            }
        }
    };
    auto dstrip = [&](int s) {
        if (s == bx) do_dstrip_m(s);
        else do_dstrip_u(s, (s > bx) ? 1 : 0);
    };

    // ---- prologue loads: G0 = {Q, QS, er(-1,0,1), kv0}, G1 = {kv1} --------
    {
        const size_t qrow0 = ((size_t)(b * Sq + q0)) * Dm + h * HDm;
        #pragma unroll
        for (int it = 0; it < 2; it++) {
            int i = tid + it * 256;
            int r = i >> 3, cc = i & 7;
            uint32_t doff = (uint32_t)(r * RSTR + cc * 8) * 2;
            CP16(smb + aQ + doff, g_Q16 + qrow0 + (size_t)r * Dm + cc * 8);
        }
        #pragma unroll
        for (int it = 0; it < 3; it++) {
            int i = tid + it * 256;
            if (i < 640) {
                int r = i >> 3, cc = i & 7;
                int rr = q0 + r; if (rr > Sq - 1) rr = Sq - 1;
                uint32_t doff = (uint32_t)(r * RSTR + cc * 8) * 2;
                CP16(smb + aQS + doff,
                     g_QS16 + ((size_t)(b * Sq + rr)) * Dm + h * HDm + cc * 8);
            }
        }
        load_er(-1); load_er(0); load_er(1);
        load_kv(0, 0);
        CP_COMMIT();                 // G0
        load_kv(1, 1);
        CP_COMMIT();                 // G1
    }

    CP_WAIT1();
    __syncthreads();                 // G0 visible (Q, QS, er(-1,0,1), kv0)

    // ---- hoist Q fragments (loop-invariant) ----
    uint32_t qa[4][4];
    {
        const uint32_t arow = (uint32_t)(wp * 16 + (lane & 15));
        #pragma unroll
        for (int ks = 0; ks < 4; ks++) {
            uint32_t addr = smb + aQ +
                (arow * RSTR + (uint32_t)(ks * 16 + (lane >> 4) * 8)) * 2;
            ldmx4(qa[ks], addr);
        }
    }

    // ---- prologue D strips {-1, 0} ----
    dstrip(-1);
    dstrip(0);
    __syncthreads();                 // Dd + all prologue dstrip reads done

    float m_[2] = {-1e30f, -1e30f}, l_[2] = {0.f, 0.f};
    float co[8][4] = {};
    const int row16 = (lane >> 2);

    for (int kt = 0; kt < 16; kt++) {
        const int s = kt & 1;
        const int d0 = kt * 64 - q0;
        if (kt > 0) { CP_WAIT1(); __syncthreads(); }  // KV(kt), Er(kt+1), Dd(kt)

        // ---- QK^T: fp16 1-pass, 16 q rows x 32 k cols per warp ----
        float c[4][4] = {};
        {
            const uint32_t stK = smb + aKV + (uint32_t)s * 18432u;
            #pragma unroll
            for (int ks = 0; ks < 4; ks++) {
                uint32_t bh[4][2];
                #pragma unroll
                for (int pp = 0; pp < 2; pp++) {
                    uint32_t nrow = (uint32_t)(wh * 32 + pp * 16 +
                                    ((lane >> 3) & 1) * 8 + (lane & 7));
                    uint32_t addr = stK +
                        (nrow * RSTR + (uint32_t)(ks * 16 + (lane >> 4) * 8)) * 2;
                    uint32_t t4[4];
                    ldmx4(t4, addr);
                    bh[pp * 2][0] = t4[0]; bh[pp * 2][1] = t4[2];
                    bh[pp * 2 + 1][0] = t4[1]; bh[pp * 2 + 1][1] = t4[3];
                }
                #pragma unroll
                for (int nt = 0; nt < 4; nt++)
                    mma16816h(c[nt], qa[ks], bh[nt]);
            }
        }

        // ---- bias add (diagonal; ready via top sync) + log2 softmax ----
        float mloc[2] = {-1e30f, -1e30f};
        #pragma unroll
        for (int hf = 0; hf < 2; hf++) {
            const int q_loc = wp * 16 + row16 + hf * 8;
            const uint32_t rbase = (uint32_t)(q_loc * DSTR);
            #pragma unroll
            for (int nt = 0; nt < 4; nt++) {
                const int col = wh * 32 + nt * 8 + (lane & 3) * 2;
                const int idx = (d0 + col) & 127;        // even -> aligned
                __half2 b2 = *(__half2*)&Dd[rbase + idx];
                float2 bf = __half22float2(b2);
                float sv0 = c[nt][hf * 2 + 0] + bf.x;
                float sv1 = c[nt][hf * 2 + 1] + bf.y;
                c[nt][hf * 2 + 0] = sv0;
                c[nt][hf * 2 + 1] = sv1;
                mloc[hf] = fmaxf(mloc[hf], fmaxf(sv0, sv1));
            }
        }
        float corr[2], psum[2] = {0.f, 0.f};
        #pragma unroll
        for (int hf = 0; hf < 2; hf++) {
            mloc[hf] = fmaxf(mloc[hf], __shfl_xor_sync(0xffffffffu, mloc[hf], 1));
            mloc[hf] = fmaxf(mloc[hf], __shfl_xor_sync(0xffffffffu, mloc[hf], 2));
            float mn = fmaxf(m_[hf], mloc[hf]);
            corr[hf] = ex2f(m_[hf] - mn);
            m_[hf] = mn;
        }
        #pragma unroll
        for (int nt = 0; nt < 4; nt++) {
            #pragma unroll
            for (int k4 = 0; k4 < 4; k4++) {
                const int hf = k4 >> 1;
                float p = ex2f(c[nt][k4] - m_[hf]);
                c[nt][k4] = p;
                psum[hf] += p;
            }
        }
        #pragma unroll
        for (int hf = 0; hf < 2; hf++) {
            psum[hf] += __shfl_xor_sync(0xffffffffu, psum[hf], 1);
            psum[hf] += __shfl_xor_sync(0xffffffffu, psum[hf], 2);
            l_[hf] = l_[hf] * corr[hf] + psum[hf];
        }
        #pragma unroll
        for (int nt = 0; nt < 8; nt++) {
            co[nt][0] *= corr[0]; co[nt][1] *= corr[0];
            co[nt][2] *= corr[1]; co[nt][3] *= corr[1];
        }

        // ---- PV: Ph(fp16) x V(fp16), 1 pass ----
        {
            const uint32_t stV = smb + aKV + (uint32_t)s * 18432u + 9216u;
            #pragma unroll
            for (int ktk = 0; ktk < 2; ktk++) {
                uint32_t pha[4];
                #pragma unroll
                for (int sub = 0; sub < 2; sub++)
                    #pragma unroll
                    for (int h2 = 0; h2 < 2; h2++)
                        pha[h2 + sub * 2] = packh2(c[2 * ktk + sub][h2 * 2],
                                                   c[2 * ktk + sub][h2 * 2 + 1]);
                uint32_t vb[8][2];
                #pragma unroll
                for (int pp = 0; pp < 4; pp++) {
                    uint32_t krow = (uint32_t)(wh * 32 + ktk * 16 +
                                   (lane & 7) + ((lane >> 3) & 1) * 8);
                    uint32_t ncol = (uint32_t)(pp * 16 + (lane >> 4) * 8);
                    uint32_t addr = stV + (krow * RSTR + ncol) * 2;
                    uint32_t t4[4];
                    ldmx4t(t4, addr);
                    vb[pp * 2][0] = t4[0]; vb[pp * 2][1] = t4[1];
                    vb[pp * 2 + 1][0] = t4[2]; vb[pp * 2 + 1][1] = t4[3];
                }
                #pragma unroll
                for (int nt = 0; nt < 8; nt++)
                    mma16816h(co[nt], pha, vb[nt]);
            }
        }

        __syncthreads();   // ALL bias(kt)+PV(kt) reads done before dstrip/loads

        // ---- D strip kt+1 (after sync: cannot clobber in-flight reads) ----
        if (kt + 1 <= 15) dstrip(kt + 1);

        if (kt + 2 < 16) load_kv(kt + 2, s);
        if (kt + 2 == 2) load_er(2);    // slot 2 free after prologue dstrips
        if (kt + 3 <= 15) load_er(kt + 3);
        CP_COMMIT();
    }

    // ---- merge the two k-half softmax states, write out ----
    if ((lane & 3) == 0) {
        #pragma unroll
        for (int hf = 0; hf < 2; hf++) {
            sM[wh * 64 + wp * 16 + row16 + hf * 8] = m_[hf];
            sL[wh * 64 + wp * 16 + row16 + hf * 8] = l_[hf];
        }
    }
    __syncthreads();
    float myc[2], inv[2];
    #pragma unroll
    for (int hf = 0; hf < 2; hf++) {
        const int rowi = wp * 16 + row16 + hf * 8;
        float mo = sM[(wh ^ 1) * 64 + rowi];
        float lo2 = sL[(wh ^ 1) * 64 + rowi];
        float mstar = fmaxf(m_[hf], mo);
        myc[hf] = ex2f(m_[hf] - mstar);
        float otc = ex2f(mo - mstar);
        inv[hf] = 1.0f / (l_[hf] * myc[hf] + lo2 * otc);
    }
    __syncthreads();
    float* sOut = (float*)(sm + aKV);
    if (wh == 1) {
        #pragma unroll
        for (int hf = 0; hf < 2; hf++) {
            const int row = wp * 16 + row16 + hf * 8;
            #pragma unroll
            for (int nt = 0; nt < 8; nt++) {
                const int col = nt * 8 + (lane & 3) * 2;
                *(float2*)&sOut[row * OSTR + col] =
                    make_float2(co[nt][hf * 2] * myc[hf],
                                co[nt][hf * 2 + 1] * myc[hf]);
            }
        }
    }
    __syncthreads();
    if (wh == 0) {
        #pragma unroll
        for (int hf = 0; hf < 2; hf++) {
            const int row = wp * 16 + row16 + hf * 8;
            const size_t ob = ((size_t)(b * Sq + q0 + row)) * Dm + h * HDm;
            #pragma unroll
            for (int nt = 0; nt < 8; nt++) {
                const int col = nt * 8 + (lane & 3) * 2;
                float2 pr = *(float2*)&sOut[row * OSTR + col];
                *(float2*)&out[ob + col] =
                    make_float2((co[nt][hf * 2] * myc[hf] + pr.x) * inv[hf],
                                (co[nt][hf * 2 + 1] * myc[hf] + pr.y) * inv[hf]);
            }
        }
    }
}

// ---------------- launch ----------------------------------------------------
extern "C" void kernel_launch(void* const* d_in, const int* in_sizes, int n_in,
                              void* d_out, int out_size)
{
    (void)in_sizes; (void)n_in; (void)out_size;
    const float* patches  = (const float*)d_in[0];
    const float* time_emb = (const float*)d_in[1];
    const float* Wqs = (const float*)d_in[2];
    const float* bqs = (const float*)d_in[3];
    const float* Wks = (const float*)d_in[4];
    const float* bks = (const float*)d_in[5];
    const float* Wvs = (const float*)d_in[6];
    const float* bvs = (const float*)d_in[7];
    const float* Wqt = (const float*)d_in[8];
    const float* bqt = (const float*)d_in[9];
    const float* Wkt = (const float*)d_in[10];
    const float* bkt = (const float*)d_in[11];
    const float* Wvt = (const float*)d_in[12];
    const float* bvt = (const float*)d_in[13];
    const float* Er  = (const float*)d_in[14];
    float* out = (float*)d_out;

    time_proj<<<dim3(Dm / 128, Bb), 128>>>(time_emb, Wqt, bqt, Wkt, bkt, Wvt, bvt);
    prep_patches<<<(Bb * Sq * Dm / 4) / 256, 256>>>(patches);
    prep_er<<<(Sq * HDm / 4) / 256, 256>>>(Er);
    prep_wt<<<dim3(Dm / 32, Dm / 32, 3), 256>>>(Wqs, Wks, Wvs);

    const int qkv_smem = 3 * STAGE2_B;  // 110592 -> 2 CTAs/SM
    cudaFuncSetAttribute(qkv_mma, cudaFuncAttributeMaxDynamicSharedMemorySize, qkv_smem);
    qkv_mma<<<dim3(Dm / 128, (Bb * Sq) / 128, 3), 256, qkv_smem>>>(bqs, bks, bvs);

    cudaFuncSetAttribute(attn_mma, cudaFuncAttributeMaxDynamicSharedMemorySize, ATTN_SMEM);
    attn_mma<<<dim3(Sq / 64, Hh, Bb), 256, ATTN_SMEM>>>(out);
}